// round 1
// baseline (speedup 1.0000x reference)
#include <cuda_runtime.h>
#include <math.h>
#include <limits.h>

#define Lc   2
#define Bc   32
#define Sc   512
#define Dc   512
#define Hc   8
#define DFFc 2048
#define DHc  64
#define KIDX 5
#define BSc  (Bc*Sc)   // 16384

// ---------------- scratch (static device globals; no allocation) ----------------
__device__ float g_x[(size_t)BSc*Dc];
__device__ float g_y[(size_t)BSc*Dc];
__device__ float g_q[(size_t)BSc*Dc];      // q == k (kq_same)
__device__ float g_v[(size_t)BSc*Dc];
__device__ float g_attn[(size_t)BSc*Dc];
__device__ float g_h1[(size_t)BSc*DFFc];
__device__ float g_t2[(size_t)BSc*Dc];

// ---------------- elementwise: x = qemb + pos, y = iemb + pos ----------------
__global__ void addpos_kernel(const float* __restrict__ qe, const float* __restrict__ ie,
                              const float* __restrict__ pe,
                              float* __restrict__ x, float* __restrict__ y)
{
    size_t idx = (size_t)blockIdx.x * blockDim.x + threadIdx.x;
    if (idx >= (size_t)BSc * Dc) return;
    size_t p = idx % ((size_t)Sc * Dc);
    float pv = pe[p];
    x[idx] = qe[idx] + pv;
    y[idx] = ie[idx] + pv;
}

// ---------------- SGEMM: C[M,N] = A[M,K] @ B[K,N] + bias (opt ReLU) ----------------
// 128x128 block tile, 8x8 thread tile, BK=8, 256 threads. M,N,K all multiples of 128/8.
__global__ __launch_bounds__(256)
void sgemm_kernel(const float* __restrict__ A, const float* __restrict__ Bm,
                  const float* __restrict__ bias, float* __restrict__ C,
                  int N, int K, int relu)
{
    __shared__ float As[8][128];
    __shared__ float Bs[8][128];

    int tid = threadIdx.x;
    int bx = blockIdx.x, by = blockIdx.y;
    int tx = tid & 15;        // 0..15 (col group)
    int ty = tid >> 4;        // 0..15 (row group)

    const float* Ab = A + (size_t)by * 128 * K;
    const float* Bb = Bm + (size_t)bx * 128;

    int ar = tid >> 1;            // 0..127   A tile row
    int ac = (tid & 1) * 4;       // 0 or 4   A tile col (float4)
    int bk = tid >> 5;            // 0..7     B tile row
    int bc = (tid & 31) * 4;      // 0..124   B tile col (float4)

    float acc[8][8];
    #pragma unroll
    for (int i = 0; i < 8; i++)
        #pragma unroll
        for (int j = 0; j < 8; j++) acc[i][j] = 0.f;

    for (int k0 = 0; k0 < K; k0 += 8) {
        float4 av = *(const float4*)(Ab + (size_t)ar * K + k0 + ac);
        float4 bv = *(const float4*)(Bb + (size_t)(k0 + bk) * N + bc);
        As[ac + 0][ar] = av.x; As[ac + 1][ar] = av.y;
        As[ac + 2][ar] = av.z; As[ac + 3][ar] = av.w;
        *(float4*)&Bs[bk][bc] = bv;
        __syncthreads();

        #pragma unroll
        for (int kk = 0; kk < 8; kk++) {
            float a[8], b[8];
            *(float4*)(a)     = *(const float4*)&As[kk][ty * 8];
            *(float4*)(a + 4) = *(const float4*)&As[kk][ty * 8 + 4];
            *(float4*)(b)     = *(const float4*)&Bs[kk][tx * 8];
            *(float4*)(b + 4) = *(const float4*)&Bs[kk][tx * 8 + 4];
            #pragma unroll
            for (int i = 0; i < 8; i++)
                #pragma unroll
                for (int j = 0; j < 8; j++)
                    acc[i][j] += a[i] * b[j];
        }
        __syncthreads();
    }

    #pragma unroll
    for (int i = 0; i < 8; i++) {
        size_t row = (size_t)by * 128 + ty * 8 + i;
        #pragma unroll
        for (int j = 0; j < 8; j += 4) {
            int col = bx * 128 + tx * 8 + j;
            float4 o;
            o.x = acc[i][j]     + bias[col];
            o.y = acc[i][j + 1] + bias[col + 1];
            o.z = acc[i][j + 2] + bias[col + 2];
            o.w = acc[i][j + 3] + bias[col + 3];
            if (relu) {
                o.x = fmaxf(o.x, 0.f); o.y = fmaxf(o.y, 0.f);
                o.z = fmaxf(o.z, 0.f); o.w = fmaxf(o.w, 0.f);
            }
            *(float4*)(C + row * N + col) = o;
        }
    }
}

// ---------------- attention with exact SparseKT top-k semantics ----------------
// One 128-thread block per (query i, head h, batch b).
// Layout of Q/V/O: [B, S, H*DH] row-major (head-interleaved), so a (b,h) head row
// is 64 contiguous floats at offset ((b*S + s)*D + h*DH).
__global__ void attn_kernel(const float* __restrict__ Q, const float* __restrict__ V,
                            float* __restrict__ O)
{
    const int i = blockIdx.x;
    const int h = blockIdx.y;
    const int b = blockIdx.z;
    const int tid = threadIdx.x;   // 128

    __shared__ float s_q[DHc];
    __shared__ float s_p[Sc];      // softmax probs (preserved)
    __shared__ float s_w[Sc];      // scratch for top-k passes, then final weights
    __shared__ float s_red[128];
    __shared__ int   s_claim;

    const size_t base = ((size_t)b * Sc) * Dc + (size_t)h * DHc;
    float* out = O + base + (size_t)i * Dc;

    if (i == 0) {                  // zero_pad: first query row output is 0
        if (tid < DHc) out[tid] = 0.f;
        return;
    }

    if (tid < DHc) s_q[tid] = Q[base + (size_t)i * Dc + tid];
    __syncthreads();

    // scores for keys j < i (strict-causal tril(k=-1)); scale 1/sqrt(64)
    for (int j = tid; j < i; j += 128) {
        const float4* kp = (const float4*)(Q + base + (size_t)j * Dc);
        const float4* qp = (const float4*)s_q;
        float acc = 0.f;
        #pragma unroll
        for (int d4 = 0; d4 < DHc / 4; d4++) {
            float4 kv = kp[d4], qv = qp[d4];
            acc += qv.x * kv.x + qv.y * kv.y + qv.z * kv.z + qv.w * kv.w;
        }
        s_p[j] = acc * 0.125f;
    }
    __syncthreads();

    // softmax over j < i (masked entries contribute exactly 0, as in reference)
    float lm = -1e30f;
    for (int j = tid; j < i; j += 128) lm = fmaxf(lm, s_p[j]);
    s_red[tid] = lm; __syncthreads();
    for (int s = 64; s > 0; s >>= 1) { if (tid < s) s_red[tid] = fmaxf(s_red[tid], s_red[tid + s]); __syncthreads(); }
    float m = s_red[0]; __syncthreads();

    float ls = 0.f;
    for (int j = tid; j < i; j += 128) { float e = expf(s_p[j] - m); s_p[j] = e; ls += e; }
    s_red[tid] = ls; __syncthreads();
    for (int s = 64; s > 0; s >>= 1) { if (tid < s) s_red[tid] += s_red[tid + s]; __syncthreads(); }
    float invZ = 1.f / s_red[0]; __syncthreads();

    for (int j = tid; j < i; j += 128) { float p = s_p[j] * invZ; s_p[j] = p; s_w[j] = p; }
    __syncthreads();

    float scale = 1.f;
    if (i > KIDX) {
        // thresh = 5th-largest prob (incl. duplicates): 5 max passes, excluding one
        // occurrence per pass — matches jax.lax.top_k order-statistic semantics.
        float pmax = 0.f, thresh = 0.f;
        #pragma unroll 1
        for (int t = 0; t < 5; t++) {
            float lmx = -1.f;
            for (int j = tid; j < i; j += 128) lmx = fmaxf(lmx, s_w[j]);
            s_red[tid] = lmx; __syncthreads();
            for (int s = 64; s > 0; s >>= 1) { if (tid < s) s_red[tid] = fmaxf(s_red[tid], s_red[tid + s]); __syncthreads(); }
            float mt = s_red[0];
            if (t == 0) pmax = mt;
            thresh = mt;
            __syncthreads();
            if (t < 4) {
                if (tid == 0) s_claim = INT_MAX;
                __syncthreads();
                for (int j = tid; j < i; j += 128)
                    if (s_w[j] == mt) atomicMin(&s_claim, j);
                __syncthreads();
                if (tid == 0 && s_claim != INT_MAX) s_w[s_claim] = -1.f;
                __syncthreads();
            }
        }
        // re-softmax over kept probs: exp(p - pmax) for p >= thresh, else 0
        for (int j = tid; j < i; j += 128) {
            float p = s_p[j];
            s_w[j] = (p >= thresh) ? expf(p - pmax) : 0.f;
        }
        __syncthreads();
        float lsum = 0.f;
        for (int j = tid; j < i; j += 128) lsum += s_w[j];
        s_red[tid] = lsum; __syncthreads();
        for (int s = 64; s > 0; s >>= 1) { if (tid < s) s_red[tid] += s_red[tid + s]; __syncthreads(); }
        scale = 1.f / s_red[0];
        __syncthreads();
    }

    // out[d] = scale * sum_j w_j * V[j][d]; two 64-thread teams split j.
    const int half = tid >> 6;   // 0/1
    const int d    = tid & 63;
    float acc = 0.f;
    for (int j = half; j < i; j += 2)
        acc += s_w[j] * V[base + (size_t)j * Dc + d];
    s_red[tid] = acc; __syncthreads();
    if (tid < 64) out[d] = (s_red[tid] + s_red[tid + 64]) * scale;
}

// ---------------- fused residual + LayerNorm: O = LN(X + R) * g + b ----------------
__global__ void ln_kernel(const float* __restrict__ X, const float* __restrict__ R,
                          const float* __restrict__ g, const float* __restrict__ bt,
                          float* __restrict__ O)
{
    const int row = blockIdx.x;
    const int tid = threadIdx.x;   // 128
    __shared__ float s_red[128];

    const float* xr = X + (size_t)row * Dc;
    const float* rr = R + (size_t)row * Dc;

    float v[4];
    float sum = 0.f, sq = 0.f;
    #pragma unroll
    for (int k = 0; k < 4; k++) {
        float t = xr[tid + k * 128] + rr[tid + k * 128];
        v[k] = t; sum += t; sq += t * t;
    }
    s_red[tid] = sum; __syncthreads();
    for (int s = 64; s > 0; s >>= 1) { if (tid < s) s_red[tid] += s_red[tid + s]; __syncthreads(); }
    float mean = s_red[0] * (1.f / Dc); __syncthreads();
    s_red[tid] = sq; __syncthreads();
    for (int s = 64; s > 0; s >>= 1) { if (tid < s) s_red[tid] += s_red[tid + s]; __syncthreads(); }
    float var = s_red[0] * (1.f / Dc) - mean * mean;
    float rs = rsqrtf(var + 1e-5f);

    #pragma unroll
    for (int k = 0; k < 4; k++) {
        int c = tid + k * 128;
        O[(size_t)row * Dc + c] = (v[k] - mean) * rs * g[c] + bt[c];
    }
}

// ---------------- launch ----------------
extern "C" void kernel_launch(void* const* d_in, const int* in_sizes, int n_in,
                              void* d_out, int out_size)
{
    const float* qe   = (const float*)d_in[0];
    const float* ie   = (const float*)d_in[1];
    const float* pe   = (const float*)d_in[2];
    const float* Wk   = (const float*)d_in[3];
    const float* bk   = (const float*)d_in[4];
    const float* Wv   = (const float*)d_in[5];
    const float* bv   = (const float*)d_in[6];
    const float* Wo   = (const float*)d_in[7];
    const float* bo   = (const float*)d_in[8];
    const float* ln1g = (const float*)d_in[9];
    const float* ln1b = (const float*)d_in[10];
    const float* W1   = (const float*)d_in[11];
    const float* b1   = (const float*)d_in[12];
    const float* W2   = (const float*)d_in[13];
    const float* b2   = (const float*)d_in[14];
    const float* ln2g = (const float*)d_in[15];
    const float* ln2b = (const float*)d_in[16];
    float* out = (float*)d_out;

    float *x, *y, *q, *v, *attn, *h1, *t2;
    cudaGetSymbolAddress((void**)&x,    g_x);
    cudaGetSymbolAddress((void**)&y,    g_y);
    cudaGetSymbolAddress((void**)&q,    g_q);
    cudaGetSymbolAddress((void**)&v,    g_v);
    cudaGetSymbolAddress((void**)&attn, g_attn);
    cudaGetSymbolAddress((void**)&h1,   g_h1);
    cudaGetSymbolAddress((void**)&t2,   g_t2);

    addpos_kernel<<<((size_t)BSc * Dc + 255) / 256, 256>>>(qe, ie, pe, x, y);

    for (int l = 0; l < Lc; l++) {
        const float* Wkl = Wk + (size_t)l * Dc * Dc;
        const float* Wvl = Wv + (size_t)l * Dc * Dc;
        const float* Wol = Wo + (size_t)l * Dc * Dc;
        const float* W1l = W1 + (size_t)l * Dc * DFFc;
        const float* W2l = W2 + (size_t)l * DFFc * Dc;

        // q = x@Wk + bk  (kq_same: k is identical, computed once)
        sgemm_kernel<<<dim3(Dc / 128, BSc / 128), 256>>>(x, Wkl, bk + l * Dc, q, Dc, Dc, 0);
        // v = y@Wv + bv  (y never changes across layers)
        sgemm_kernel<<<dim3(Dc / 128, BSc / 128), 256>>>(y, Wvl, bv + l * Dc, v, Dc, Dc, 0);
        // sparse attention
        attn_kernel<<<dim3(Sc, Hc, Bc), 128>>>(q, v, attn);
        // o-proj
        sgemm_kernel<<<dim3(Dc / 128, BSc / 128), 256>>>(attn, Wol, bo + l * Dc, t2, Dc, Dc, 0);
        // x = LN(x + proj)
        ln_kernel<<<BSc, 128>>>(x, t2, ln1g + l * Dc, ln1b + l * Dc, x);
        // h1 = relu(x@W1 + b1)
        sgemm_kernel<<<dim3(DFFc / 128, BSc / 128), 256>>>(x, W1l, b1 + l * DFFc, h1, DFFc, Dc, 1);
        // t2 = h1@W2 + b2
        sgemm_kernel<<<dim3(Dc / 128, BSc / 128), 256>>>(h1, W2l, b2 + l * Dc, t2, Dc, DFFc, 0);
        // x = LN(x + t2); last layer writes straight to output
        float* dst = (l == Lc - 1) ? out : x;
        ln_kernel<<<BSc, 128>>>(x, t2, ln2g + l * Dc, ln2b + l * Dc, dst);
    }
}

// round 3
// speedup vs baseline: 1.0042x; 1.0042x over previous
#include <cuda_runtime.h>
#include <math.h>
#include <limits.h>
#include <stdint.h>

#define Lc   2
#define Bc   32
#define Sc   512
#define Dc   512
#define Hc   8
#define DFFc 2048
#define DHc  64
#define KIDX 5
#define BSc  (Bc*Sc)   // 16384

// ---------------- scratch (static device globals; no allocation) ----------------
__device__ float g_x[(size_t)BSc*Dc];
__device__ float g_y[(size_t)BSc*Dc];
__device__ float g_q[(size_t)BSc*Dc];      // q == k (kq_same)
__device__ float g_v[(size_t)BSc*Dc];
__device__ float g_attn[(size_t)BSc*Dc];
__device__ float g_h1[(size_t)BSc*DFFc];
__device__ float g_t2[(size_t)BSc*Dc];

// ---------------- elementwise: x = qemb + pos, y = iemb + pos ----------------
__global__ void addpos_kernel(const float* __restrict__ qe, const float* __restrict__ ie,
                              const float* __restrict__ pe,
                              float* __restrict__ x, float* __restrict__ y)
{
    size_t idx = (size_t)blockIdx.x * blockDim.x + threadIdx.x;
    if (idx >= (size_t)BSc * Dc) return;
    size_t p = idx % ((size_t)Sc * Dc);
    float pv = pe[p];
    x[idx] = qe[idx] + pv;
    y[idx] = ie[idx] + pv;
}

// ---------------- tf32x3 tensor-core GEMM (fp32-accurate) ----------------
// C[M,N] = A[M,K] @ B[K,N] + bias (opt ReLU).
// Each operand split once: big = tf32(x), small = tf32(x - big).
// C += A_s*B_b + A_b*B_s + A_b*B_b  (A_s*B_s term ~2^-22, dropped).
// Block tile 128x128, BK=16, 256 threads (8 warps 2x4), warp tile 64x32.

__device__ __forceinline__ float f2tf32f(float x) {
    uint32_t r;
    asm("cvt.rna.tf32.f32 %0, %1;" : "=r"(r) : "f"(x));
    return __uint_as_float(r);
}

__device__ __forceinline__ void mma_tf32(float c[4], const uint32_t a[4], const uint32_t b[2]) {
    asm volatile(
        "mma.sync.aligned.m16n8k8.row.col.f32.tf32.tf32.f32 "
        "{%0,%1,%2,%3}, {%4,%5,%6,%7}, {%8,%9}, {%0,%1,%2,%3};"
        : "+f"(c[0]), "+f"(c[1]), "+f"(c[2]), "+f"(c[3])
        : "r"(a[0]), "r"(a[1]), "r"(a[2]), "r"(a[3]), "r"(b[0]), "r"(b[1]));
}

#define BM 128
#define BN 128
#define BKt 16

__global__ __launch_bounds__(256)
void tgemm_kernel(const float* __restrict__ A, const float* __restrict__ Bm,
                  const float* __restrict__ bias, float* __restrict__ C,
                  int N, int K, int relu)
{
    __shared__ float As_b[BM][20];    // big  A [m][k], pad->conflict-free
    __shared__ float As_s[BM][20];    // small A
    __shared__ float Bs_b[BKt][136];  // big  B [k][n]
    __shared__ float Bs_s[BKt][136];  // small B

    const int tid  = threadIdx.x;
    const int warp = tid >> 5;
    const int lane = tid & 31;
    const int wm   = warp >> 2;   // 0..1
    const int wn   = warp & 3;    // 0..3
    const int bx = blockIdx.x, by = blockIdx.y;

    const int ar0 = tid >> 2;            // A rows: ar0, ar0+64
    const int ac  = (tid & 3) * 4;       // A col within BK
    const int br0 = tid >> 5;            // B rows: br0, br0+8
    const int bc  = (tid & 31) * 4;      // B col within BN

    const float* Ag = A  + ((size_t)by * BM) * K;
    const float* Bg = Bm + (size_t)bx * BN;

    float c[4][4][4];
    #pragma unroll
    for (int mt = 0; mt < 4; mt++)
        #pragma unroll
        for (int nt = 0; nt < 4; nt++)
            #pragma unroll
            for (int e = 0; e < 4; e++) c[mt][nt][e] = 0.f;

    const int NT = K / BKt;
    float4 a_st[2], b_st[2];

    // prefetch tile 0
    a_st[0] = *(const float4*)(Ag + (size_t)ar0 * K + ac);
    a_st[1] = *(const float4*)(Ag + (size_t)(ar0 + 64) * K + ac);
    b_st[0] = *(const float4*)(Bg + (size_t)br0 * N + bc);
    b_st[1] = *(const float4*)(Bg + (size_t)(br0 + 8) * N + bc);

    for (int kt = 0; kt < NT; kt++) {
        // deposit staged tile into smem with big/small split
        #pragma unroll
        for (int e = 0; e < 4; e++) {
            float v0 = ((const float*)&a_st[0])[e];
            float v1 = ((const float*)&a_st[1])[e];
            float b0 = f2tf32f(v0), b1 = f2tf32f(v1);
            As_b[ar0][ac + e]      = b0;
            As_s[ar0][ac + e]      = f2tf32f(v0 - b0);
            As_b[ar0 + 64][ac + e] = b1;
            As_s[ar0 + 64][ac + e] = f2tf32f(v1 - b1);

            float w0 = ((const float*)&b_st[0])[e];
            float w1 = ((const float*)&b_st[1])[e];
            float c0 = f2tf32f(w0), c1 = f2tf32f(w1);
            Bs_b[br0][bc + e]     = c0;
            Bs_s[br0][bc + e]     = f2tf32f(w0 - c0);
            Bs_b[br0 + 8][bc + e] = c1;
            Bs_s[br0 + 8][bc + e] = f2tf32f(w1 - c1);
        }
        __syncthreads();

        // prefetch next tile while computing
        if (kt + 1 < NT) {
            const int k0 = (kt + 1) * BKt;
            a_st[0] = *(const float4*)(Ag + (size_t)ar0 * K + k0 + ac);
            a_st[1] = *(const float4*)(Ag + (size_t)(ar0 + 64) * K + k0 + ac);
            b_st[0] = *(const float4*)(Bg + (size_t)(k0 + br0) * N + bc);
            b_st[1] = *(const float4*)(Bg + (size_t)(k0 + br0 + 8) * N + bc);
        }

        #pragma unroll
        for (int ks = 0; ks < 2; ks++) {
            const int kk = ks * 8;
            const int kq = kk + (lane & 3);
            uint32_t ab[4][4], as[4][4], bb[4][2], bs[4][2];
            #pragma unroll
            for (int mt = 0; mt < 4; mt++) {
                const int r = wm * 64 + mt * 16 + (lane >> 2);
                ab[mt][0] = __float_as_uint(As_b[r    ][kq    ]);
                ab[mt][1] = __float_as_uint(As_b[r + 8][kq    ]);
                ab[mt][2] = __float_as_uint(As_b[r    ][kq + 4]);
                ab[mt][3] = __float_as_uint(As_b[r + 8][kq + 4]);
                as[mt][0] = __float_as_uint(As_s[r    ][kq    ]);
                as[mt][1] = __float_as_uint(As_s[r + 8][kq    ]);
                as[mt][2] = __float_as_uint(As_s[r    ][kq + 4]);
                as[mt][3] = __float_as_uint(As_s[r + 8][kq + 4]);
            }
            #pragma unroll
            for (int nt = 0; nt < 4; nt++) {
                const int cc = wn * 32 + nt * 8 + (lane >> 2);
                bb[nt][0] = __float_as_uint(Bs_b[kq    ][cc]);
                bb[nt][1] = __float_as_uint(Bs_b[kq + 4][cc]);
                bs[nt][0] = __float_as_uint(Bs_s[kq    ][cc]);
                bs[nt][1] = __float_as_uint(Bs_s[kq + 4][cc]);
            }
            #pragma unroll
            for (int mt = 0; mt < 4; mt++)
                #pragma unroll
                for (int nt = 0; nt < 4; nt++) {
                    mma_tf32(c[mt][nt], as[mt], bb[nt]);   // small*big
                    mma_tf32(c[mt][nt], ab[mt], bs[nt]);   // big*small
                    mma_tf32(c[mt][nt], ab[mt], bb[nt]);   // big*big
                }
        }
        __syncthreads();
    }

    // epilogue: bias (+ optional relu), float2 stores
    #pragma unroll
    for (int mt = 0; mt < 4; mt++) {
        const int r0 = by * BM + wm * 64 + mt * 16 + (lane >> 2);
        #pragma unroll
        for (int nt = 0; nt < 4; nt++) {
            const int col = bx * BN + wn * 32 + nt * 8 + 2 * (lane & 3);
            const float b0 = bias[col], b1 = bias[col + 1];
            float2 o0, o1;
            o0.x = c[mt][nt][0] + b0; o0.y = c[mt][nt][1] + b1;
            o1.x = c[mt][nt][2] + b0; o1.y = c[mt][nt][3] + b1;
            if (relu) {
                o0.x = fmaxf(o0.x, 0.f); o0.y = fmaxf(o0.y, 0.f);
                o1.x = fmaxf(o1.x, 0.f); o1.y = fmaxf(o1.y, 0.f);
            }
            *(float2*)(C + (size_t)r0 * N + col)       = o0;
            *(float2*)(C + (size_t)(r0 + 8) * N + col) = o1;
        }
    }
}

// ---------------- attention with exact SparseKT top-k semantics ----------------
__global__ void attn_kernel(const float* __restrict__ Q, const float* __restrict__ V,
                            float* __restrict__ O)
{
    const int i = blockIdx.x;
    const int h = blockIdx.y;
    const int b = blockIdx.z;
    const int tid = threadIdx.x;   // 128

    __shared__ float s_q[DHc];
    __shared__ float s_p[Sc];
    __shared__ float s_w[Sc];
    __shared__ float s_red[128];
    __shared__ int   s_claim;

    const size_t base = ((size_t)b * Sc) * Dc + (size_t)h * DHc;
    float* out = O + base + (size_t)i * Dc;

    if (i == 0) {
        if (tid < DHc) out[tid] = 0.f;
        return;
    }

    if (tid < DHc) s_q[tid] = Q[base + (size_t)i * Dc + tid];
    __syncthreads();

    for (int j = tid; j < i; j += 128) {
        const float4* kp = (const float4*)(Q + base + (size_t)j * Dc);
        const float4* qp = (const float4*)s_q;
        float acc = 0.f;
        #pragma unroll
        for (int d4 = 0; d4 < DHc / 4; d4++) {
            float4 kv = kp[d4], qv = qp[d4];
            acc += qv.x * kv.x + qv.y * kv.y + qv.z * kv.z + qv.w * kv.w;
        }
        s_p[j] = acc * 0.125f;
    }
    __syncthreads();

    float lm = -1e30f;
    for (int j = tid; j < i; j += 128) lm = fmaxf(lm, s_p[j]);
    s_red[tid] = lm; __syncthreads();
    for (int s = 64; s > 0; s >>= 1) { if (tid < s) s_red[tid] = fmaxf(s_red[tid], s_red[tid + s]); __syncthreads(); }
    float m = s_red[0]; __syncthreads();

    float ls = 0.f;
    for (int j = tid; j < i; j += 128) { float e = expf(s_p[j] - m); s_p[j] = e; ls += e; }
    s_red[tid] = ls; __syncthreads();
    for (int s = 64; s > 0; s >>= 1) { if (tid < s) s_red[tid] += s_red[tid + s]; __syncthreads(); }
    float invZ = 1.f / s_red[0]; __syncthreads();

    for (int j = tid; j < i; j += 128) { float p = s_p[j] * invZ; s_p[j] = p; s_w[j] = p; }
    __syncthreads();

    float scale = 1.f;
    if (i > KIDX) {
        float pmax = 0.f, thresh = 0.f;
        #pragma unroll 1
        for (int t = 0; t < 5; t++) {
            float lmx = -1.f;
            for (int j = tid; j < i; j += 128) lmx = fmaxf(lmx, s_w[j]);
            s_red[tid] = lmx; __syncthreads();
            for (int s = 64; s > 0; s >>= 1) { if (tid < s) s_red[tid] = fmaxf(s_red[tid], s_red[tid + s]); __syncthreads(); }
            float mt = s_red[0];
            if (t == 0) pmax = mt;
            thresh = mt;
            __syncthreads();
            if (t < 4) {
                if (tid == 0) s_claim = INT_MAX;
                __syncthreads();
                for (int j = tid; j < i; j += 128)
                    if (s_w[j] == mt) atomicMin(&s_claim, j);
                __syncthreads();
                if (tid == 0 && s_claim != INT_MAX) s_w[s_claim] = -1.f;
                __syncthreads();
            }
        }
        for (int j = tid; j < i; j += 128) {
            float p = s_p[j];
            s_w[j] = (p >= thresh) ? expf(p - pmax) : 0.f;
        }
        __syncthreads();
        float lsum = 0.f;
        for (int j = tid; j < i; j += 128) lsum += s_w[j];
        s_red[tid] = lsum; __syncthreads();
        for (int s = 64; s > 0; s >>= 1) { if (tid < s) s_red[tid] += s_red[tid + s]; __syncthreads(); }
        scale = 1.f / s_red[0];
        __syncthreads();
    }

    const int half = tid >> 6;
    const int d    = tid & 63;
    float acc = 0.f;
    for (int j = half; j < i; j += 2)
        acc += s_w[j] * V[base + (size_t)j * Dc + d];
    s_red[tid] = acc; __syncthreads();
    if (tid < 64) out[d] = (s_red[tid] + s_red[tid + 64]) * scale;
}

// ---------------- fused residual + LayerNorm: O = LN(X + R) * g + b ----------------
__global__ void ln_kernel(const float* __restrict__ X, const float* __restrict__ R,
                          const float* __restrict__ g, const float* __restrict__ bt,
                          float* __restrict__ O)
{
    const int row = blockIdx.x;
    const int tid = threadIdx.x;   // 128
    __shared__ float s_red[128];

    const float* xr = X + (size_t)row * Dc;
    const float* rr = R + (size_t)row * Dc;

    float v[4];
    float sum = 0.f, sq = 0.f;
    #pragma unroll
    for (int k = 0; k < 4; k++) {
        float t = xr[tid + k * 128] + rr[tid + k * 128];
        v[k] = t; sum += t; sq += t * t;
    }
    s_red[tid] = sum; __syncthreads();
    for (int s = 64; s > 0; s >>= 1) { if (tid < s) s_red[tid] += s_red[tid + s]; __syncthreads(); }
    float mean = s_red[0] * (1.f / Dc); __syncthreads();
    s_red[tid] = sq; __syncthreads();
    for (int s = 64; s > 0; s >>= 1) { if (tid < s) s_red[tid] += s_red[tid + s]; __syncthreads(); }
    float var = s_red[0] * (1.f / Dc) - mean * mean;
    float rs = rsqrtf(var + 1e-5f);

    #pragma unroll
    for (int k = 0; k < 4; k++) {
        int c = tid + k * 128;
        O[(size_t)row * Dc + c] = (v[k] - mean) * rs * g[c] + bt[c];
    }
}

// ---------------- launch ----------------
extern "C" void kernel_launch(void* const* d_in, const int* in_sizes, int n_in,
                              void* d_out, int out_size)
{
    const float* qe   = (const float*)d_in[0];
    const float* ie   = (const float*)d_in[1];
    const float* pe   = (const float*)d_in[2];
    const float* Wk   = (const float*)d_in[3];
    const float* bk   = (const float*)d_in[4];
    const float* Wv   = (const float*)d_in[5];
    const float* bv   = (const float*)d_in[6];
    const float* Wo   = (const float*)d_in[7];
    const float* bo   = (const float*)d_in[8];
    const float* ln1g = (const float*)d_in[9];
    const float* ln1b = (const float*)d_in[10];
    const float* W1   = (const float*)d_in[11];
    const float* b1   = (const float*)d_in[12];
    const float* W2   = (const float*)d_in[13];
    const float* b2   = (const float*)d_in[14];
    const float* ln2g = (const float*)d_in[15];
    const float* ln2b = (const float*)d_in[16];
    float* out = (float*)d_out;

    float *x, *y, *q, *v, *attn, *h1, *t2;
    cudaGetSymbolAddress((void**)&x,    g_x);
    cudaGetSymbolAddress((void**)&y,    g_y);
    cudaGetSymbolAddress((void**)&q,    g_q);
    cudaGetSymbolAddress((void**)&v,    g_v);
    cudaGetSymbolAddress((void**)&attn, g_attn);
    cudaGetSymbolAddress((void**)&h1,   g_h1);
    cudaGetSymbolAddress((void**)&t2,   g_t2);

    addpos_kernel<<<((size_t)BSc * Dc + 255) / 256, 256>>>(qe, ie, pe, x, y);

    for (int l = 0; l < Lc; l++) {
        const float* Wkl = Wk + (size_t)l * Dc * Dc;
        const float* Wvl = Wv + (size_t)l * Dc * Dc;
        const float* Wol = Wo + (size_t)l * Dc * Dc;
        const float* W1l = W1 + (size_t)l * Dc * DFFc;
        const float* W2l = W2 + (size_t)l * DFFc * Dc;

        tgemm_kernel<<<dim3(Dc / BN, BSc / BM), 256>>>(x, Wkl, bk + l * Dc, q, Dc, Dc, 0);
        tgemm_kernel<<<dim3(Dc / BN, BSc / BM), 256>>>(y, Wvl, bv + l * Dc, v, Dc, Dc, 0);
        attn_kernel<<<dim3(Sc, Hc, Bc), 128>>>(q, v, attn);
        tgemm_kernel<<<dim3(Dc / BN, BSc / BM), 256>>>(attn, Wol, bo + l * Dc, t2, Dc, Dc, 0);
        ln_kernel<<<BSc, 128>>>(x, t2, ln1g + l * Dc, ln1b + l * Dc, x);
        tgemm_kernel<<<dim3(DFFc / BN, BSc / BM), 256>>>(x, W1l, b1 + l * DFFc, h1, DFFc, Dc, 1);
        tgemm_kernel<<<dim3(Dc / BN, BSc / BM), 256>>>(h1, W2l, b2 + l * Dc, t2, Dc, DFFc, 0);
        float* dst = (l == Lc - 1) ? out : x;
        ln_kernel<<<BSc, 128>>>(x, t2, ln2g + l * Dc, ln2b + l * Dc, dst);
    }
}

// round 5
// speedup vs baseline: 1.9281x; 1.9200x over previous
#include <cuda_runtime.h>
#include <math.h>
#include <float.h>
#include <limits.h>
#include <stdint.h>

#define Lc   2
#define Bc   32
#define Sc   512
#define Dc   512
#define Hc   8
#define DFFc 2048
#define DHc  64
#define KIDX 5
#define BSc  (Bc*Sc)   // 16384

// ---------------- scratch (static device globals; no allocation) ----------------
__device__ float g_x[(size_t)BSc*Dc];
__device__ float g_y[(size_t)BSc*Dc];
__device__ float g_q[(size_t)BSc*Dc];      // q == k (kq_same)
__device__ float g_v[(size_t)BSc*Dc];
__device__ float g_attn[(size_t)BSc*Dc];
__device__ float g_h1[(size_t)BSc*DFFc];
__device__ float g_t2[(size_t)BSc*Dc];

// ---------------- elementwise: x = qemb + pos, y = iemb + pos ----------------
__global__ void addpos_kernel(const float* __restrict__ qe, const float* __restrict__ ie,
                              const float* __restrict__ pe,
                              float* __restrict__ x, float* __restrict__ y)
{
    size_t idx = (size_t)blockIdx.x * blockDim.x + threadIdx.x;
    if (idx >= (size_t)BSc * Dc) return;
    size_t p = idx % ((size_t)Sc * Dc);
    float pv = pe[p];
    x[idx] = qe[idx] + pv;
    y[idx] = ie[idx] + pv;
}

// ---------------- tf32x3 tensor-core GEMM (fp32-accurate) ----------------
__device__ __forceinline__ float f2tf32f(float x) {
    uint32_t r;
    asm("cvt.rna.tf32.f32 %0, %1;" : "=r"(r) : "f"(x));
    return __uint_as_float(r);
}

__device__ __forceinline__ void mma_tf32(float c[4], const uint32_t a[4], const uint32_t b[2]) {
    asm volatile(
        "mma.sync.aligned.m16n8k8.row.col.f32.tf32.tf32.f32 "
        "{%0,%1,%2,%3}, {%4,%5,%6,%7}, {%8,%9}, {%0,%1,%2,%3};"
        : "+f"(c[0]), "+f"(c[1]), "+f"(c[2]), "+f"(c[3])
        : "r"(a[0]), "r"(a[1]), "r"(a[2]), "r"(a[3]), "r"(b[0]), "r"(b[1]));
}

#define BM 128
#define BN 128
#define BKt 16

__global__ __launch_bounds__(256)
void tgemm_kernel(const float* __restrict__ A, const float* __restrict__ Bm,
                  const float* __restrict__ bias, float* __restrict__ C,
                  int N, int K, int relu)
{
    __shared__ float As_b[BM][20];
    __shared__ float As_s[BM][20];
    __shared__ float Bs_b[BKt][136];
    __shared__ float Bs_s[BKt][136];

    const int tid  = threadIdx.x;
    const int warp = tid >> 5;
    const int lane = tid & 31;
    const int wm   = warp >> 2;
    const int wn   = warp & 3;
    const int bx = blockIdx.x, by = blockIdx.y;

    const int ar0 = tid >> 2;
    const int ac  = (tid & 3) * 4;
    const int br0 = tid >> 5;
    const int bc  = (tid & 31) * 4;

    const float* Ag = A  + ((size_t)by * BM) * K;
    const float* Bg = Bm + (size_t)bx * BN;

    float c[4][4][4];
    #pragma unroll
    for (int mt = 0; mt < 4; mt++)
        #pragma unroll
        for (int nt = 0; nt < 4; nt++)
            #pragma unroll
            for (int e = 0; e < 4; e++) c[mt][nt][e] = 0.f;

    const int NT = K / BKt;
    float4 a_st[2], b_st[2];

    a_st[0] = *(const float4*)(Ag + (size_t)ar0 * K + ac);
    a_st[1] = *(const float4*)(Ag + (size_t)(ar0 + 64) * K + ac);
    b_st[0] = *(const float4*)(Bg + (size_t)br0 * N + bc);
    b_st[1] = *(const float4*)(Bg + (size_t)(br0 + 8) * N + bc);

    for (int kt = 0; kt < NT; kt++) {
        #pragma unroll
        for (int e = 0; e < 4; e++) {
            float v0 = ((const float*)&a_st[0])[e];
            float v1 = ((const float*)&a_st[1])[e];
            float b0 = f2tf32f(v0), b1 = f2tf32f(v1);
            As_b[ar0][ac + e]      = b0;
            As_s[ar0][ac + e]      = f2tf32f(v0 - b0);
            As_b[ar0 + 64][ac + e] = b1;
            As_s[ar0 + 64][ac + e] = f2tf32f(v1 - b1);

            float w0 = ((const float*)&b_st[0])[e];
            float w1 = ((const float*)&b_st[1])[e];
            float c0 = f2tf32f(w0), c1 = f2tf32f(w1);
            Bs_b[br0][bc + e]     = c0;
            Bs_s[br0][bc + e]     = f2tf32f(w0 - c0);
            Bs_b[br0 + 8][bc + e] = c1;
            Bs_s[br0 + 8][bc + e] = f2tf32f(w1 - c1);
        }
        __syncthreads();

        if (kt + 1 < NT) {
            const int k0 = (kt + 1) * BKt;
            a_st[0] = *(const float4*)(Ag + (size_t)ar0 * K + k0 + ac);
            a_st[1] = *(const float4*)(Ag + (size_t)(ar0 + 64) * K + k0 + ac);
            b_st[0] = *(const float4*)(Bg + (size_t)(k0 + br0) * N + bc);
            b_st[1] = *(const float4*)(Bg + (size_t)(k0 + br0 + 8) * N + bc);
        }

        #pragma unroll
        for (int ks = 0; ks < 2; ks++) {
            const int kk = ks * 8;
            const int kq = kk + (lane & 3);
            uint32_t ab[4][4], as[4][4], bb[4][2], bs[4][2];
            #pragma unroll
            for (int mt = 0; mt < 4; mt++) {
                const int r = wm * 64 + mt * 16 + (lane >> 2);
                ab[mt][0] = __float_as_uint(As_b[r    ][kq    ]);
                ab[mt][1] = __float_as_uint(As_b[r + 8][kq    ]);
                ab[mt][2] = __float_as_uint(As_b[r    ][kq + 4]);
                ab[mt][3] = __float_as_uint(As_b[r + 8][kq + 4]);
                as[mt][0] = __float_as_uint(As_s[r    ][kq    ]);
                as[mt][1] = __float_as_uint(As_s[r + 8][kq    ]);
                as[mt][2] = __float_as_uint(As_s[r    ][kq + 4]);
                as[mt][3] = __float_as_uint(As_s[r + 8][kq + 4]);
            }
            #pragma unroll
            for (int nt = 0; nt < 4; nt++) {
                const int cc = wn * 32 + nt * 8 + (lane >> 2);
                bb[nt][0] = __float_as_uint(Bs_b[kq    ][cc]);
                bb[nt][1] = __float_as_uint(Bs_b[kq + 4][cc]);
                bs[nt][0] = __float_as_uint(Bs_s[kq    ][cc]);
                bs[nt][1] = __float_as_uint(Bs_s[kq + 4][cc]);
            }
            #pragma unroll
            for (int mt = 0; mt < 4; mt++)
                #pragma unroll
                for (int nt = 0; nt < 4; nt++) {
                    mma_tf32(c[mt][nt], as[mt], bb[nt]);
                    mma_tf32(c[mt][nt], ab[mt], bs[nt]);
                    mma_tf32(c[mt][nt], ab[mt], bb[nt]);
                }
        }
        __syncthreads();
    }

    #pragma unroll
    for (int mt = 0; mt < 4; mt++) {
        const int r0 = by * BM + wm * 64 + mt * 16 + (lane >> 2);
        #pragma unroll
        for (int nt = 0; nt < 4; nt++) {
            const int col = bx * BN + wn * 32 + nt * 8 + 2 * (lane & 3);
            const float b0 = bias[col], b1 = bias[col + 1];
            float2 o0, o1;
            o0.x = c[mt][nt][0] + b0; o0.y = c[mt][nt][1] + b1;
            o1.x = c[mt][nt][2] + b0; o1.y = c[mt][nt][3] + b1;
            if (relu) {
                o0.x = fmaxf(o0.x, 0.f); o0.y = fmaxf(o0.y, 0.f);
                o1.x = fmaxf(o1.x, 0.f); o1.y = fmaxf(o1.y, 0.f);
            }
            *(float2*)(C + (size_t)r0 * N + col)       = o0;
            *(float2*)(C + (size_t)(r0 + 8) * N + col) = o1;
        }
    }
}

// ---------------- warp-level attention, SparseKT top-k semantics ----------------
// One warp per query; 8 warps/block share one (b,h) and 8 consecutive queries.
// K staged in smem (transposed); scores/probs in registers; top-k via shuffles;
// PV is a sparse gather over the ~5 surviving keys, read directly from global.

#define FULLM 0xFFFFFFFFu
#define QPB 8

__device__ __forceinline__ float warp_max(float v) {
    #pragma unroll
    for (int o = 16; o > 0; o >>= 1) v = fmaxf(v, __shfl_xor_sync(FULLM, v, o));
    return v;
}
__device__ __forceinline__ float warp_sum(float v) {
    #pragma unroll
    for (int o = 16; o > 0; o >>= 1) v += __shfl_xor_sync(FULLM, v, o);
    return v;
}
__device__ __forceinline__ int warp_min_i(int v) {
    #pragma unroll
    for (int o = 16; o > 0; o >>= 1) v = min(v, __shfl_xor_sync(FULLM, v, o));
    return v;
}

__global__ __launch_bounds__(256)
void attn_kernel(const float* __restrict__ Q, const float* __restrict__ V,
                 float* __restrict__ O)
{
    const int qt   = blockIdx.x;               // query tile (8 queries)
    const int h    = blockIdx.y;
    const int b    = blockIdx.z;
    const int tid  = threadIdx.x;
    const int warp = tid >> 5;
    const int lane = tid & 31;
    const int i    = qt * QPB + warp;          // this warp's query row

    __shared__ float KT[64][65];               // transposed K tile [d][key]
    __shared__ float qs[QPB][64];              // per-warp query vector

    const size_t base = ((size_t)b * Sc) * Dc + (size_t)h * DHc;

    // load q for this warp
    qs[warp][lane]      = Q[base + (size_t)i * Dc + lane];
    qs[warp][lane + 32] = Q[base + (size_t)i * Dc + lane + 32];

    // scores in registers: slot t holds j = 32*t + lane
    float p[16];
    #pragma unroll
    for (int t = 0; t < 16; t++) p[t] = -FLT_MAX;

    const int nk = qt * QPB + QPB - 1;         // keys needed: j < i_max (= qt*8+7)

    const int key = tid >> 2;                  // 0..63
    const int d0  = (tid & 3) * 16;

    #pragma unroll
    for (int tt = 0; tt < 8; tt++) {
        if (tt * 64 < nk) {
            const int j0 = tt * 64;
            __syncthreads();                   // protect KT from previous iter readers (and qs on iter 0)
            {
                const float* src = Q + base + (size_t)(j0 + key) * Dc + d0;
                float4 f0 = *(const float4*)(src);
                float4 f1 = *(const float4*)(src + 4);
                float4 f2 = *(const float4*)(src + 8);
                float4 f3 = *(const float4*)(src + 12);
                KT[d0 + 0][key] = f0.x; KT[d0 + 1][key] = f0.y;
                KT[d0 + 2][key] = f0.z; KT[d0 + 3][key] = f0.w;
                KT[d0 + 4][key] = f1.x; KT[d0 + 5][key] = f1.y;
                KT[d0 + 6][key] = f1.z; KT[d0 + 7][key] = f1.w;
                KT[d0 + 8][key] = f2.x; KT[d0 + 9][key] = f2.y;
                KT[d0 +10][key] = f2.z; KT[d0 +11][key] = f2.w;
                KT[d0 +12][key] = f3.x; KT[d0 +13][key] = f3.y;
                KT[d0 +14][key] = f3.z; KT[d0 +15][key] = f3.w;
            }
            __syncthreads();

            float acc0 = 0.f, acc1 = 0.f;
            #pragma unroll
            for (int d = 0; d < 64; d++) {
                const float qd = qs[warp][d];
                acc0 = fmaf(qd, KT[d][lane],      acc0);
                acc1 = fmaf(qd, KT[d][lane + 32], acc1);
            }
            const int j1 = j0 + lane, j2 = j0 + lane + 32;
            if (j1 < i) p[2 * tt]     = acc0 * 0.125f;
            if (j2 < i) p[2 * tt + 1] = acc1 * 0.125f;
        }
    }

    // ---- softmax over j < i (invalid slots: -FLT_MAX -> exp underflows to 0) ----
    float lm = -FLT_MAX;
    #pragma unroll
    for (int t = 0; t < 16; t++) lm = fmaxf(lm, p[t]);
    const float m = warp_max(lm);

    float ls = 0.f;
    #pragma unroll
    for (int t = 0; t < 16; t++) { p[t] = expf(p[t] - m); ls += p[t]; }
    const float invZ = 1.f / warp_sum(ls);
    #pragma unroll
    for (int t = 0; t < 16; t++) p[t] *= invZ;

    // ---- final weights w[] + scale ----
    float w[16];
    float scale = 1.f;
    if (i > KIDX) {
        #pragma unroll
        for (int t = 0; t < 16; t++) w[t] = p[t];
        float pmax = 0.f, thresh = 0.f;
        #pragma unroll 1
        for (int pass = 0; pass < 5; pass++) {
            float lmx = -1.f;
            #pragma unroll
            for (int t = 0; t < 16; t++) lmx = fmaxf(lmx, w[t]);
            const float mt = warp_max(lmx);
            if (pass == 0) pmax = mt;
            thresh = mt;
            if (pass < 4) {
                int cand = INT_MAX;
                #pragma unroll
                for (int t = 0; t < 16; t++)
                    if (w[t] == mt) cand = min(cand, t * 32 + lane);
                const int jmin = warp_min_i(cand);
                #pragma unroll
                for (int t = 0; t < 16; t++)
                    if (jmin != INT_MAX && t == (jmin >> 5) && lane == (jmin & 31))
                        w[t] = -1.f;
            }
        }
        float lsum = 0.f;
        #pragma unroll
        for (int t = 0; t < 16; t++) {
            w[t] = (p[t] >= thresh) ? expf(p[t] - pmax) : 0.f;
            lsum += w[t];
        }
        scale = 1.f / warp_sum(lsum);
    } else {
        #pragma unroll
        for (int t = 0; t < 16; t++) w[t] = p[t];
    }

    // ---- sparse PV: only keys with w > 0 (~5 per row) ----
    float* out = O + base + (size_t)i * Dc;
    if (i == 0) {
        out[lane] = 0.f; out[lane + 32] = 0.f;   // zero_pad row
        return;
    }

    float o0 = 0.f, o1 = 0.f;
    #pragma unroll
    for (int t = 0; t < 16; t++) {
        unsigned mask = __ballot_sync(FULLM, w[t] > 0.f);
        while (mask) {
            const int bit = __ffs(mask) - 1;
            mask &= mask - 1;
            const float wj = __shfl_sync(FULLM, w[t], bit);
            const float* vr = V + base + (size_t)(t * 32 + bit) * Dc;
            o0 = fmaf(wj, vr[lane],      o0);
            o1 = fmaf(wj, vr[lane + 32], o1);
        }
    }
    out[lane]      = o0 * scale;
    out[lane + 32] = o1 * scale;
}

// ---------------- fused residual + LayerNorm: O = LN(X + R) * g + b ----------------
__global__ void ln_kernel(const float* __restrict__ X, const float* __restrict__ R,
                          const float* __restrict__ g, const float* __restrict__ bt,
                          float* __restrict__ O)
{
    const int row = blockIdx.x;
    const int tid = threadIdx.x;   // 128
    __shared__ float s_red[128];

    const float* xr = X + (size_t)row * Dc;
    const float* rr = R + (size_t)row * Dc;

    float v[4];
    float sum = 0.f, sq = 0.f;
    #pragma unroll
    for (int k = 0; k < 4; k++) {
        float t = xr[tid + k * 128] + rr[tid + k * 128];
        v[k] = t; sum += t; sq += t * t;
    }
    s_red[tid] = sum; __syncthreads();
    for (int s = 64; s > 0; s >>= 1) { if (tid < s) s_red[tid] += s_red[tid + s]; __syncthreads(); }
    float mean = s_red[0] * (1.f / Dc); __syncthreads();
    s_red[tid] = sq; __syncthreads();
    for (int s = 64; s > 0; s >>= 1) { if (tid < s) s_red[tid] += s_red[tid + s]; __syncthreads(); }
    float var = s_red[0] * (1.f / Dc) - mean * mean;
    float rs = rsqrtf(var + 1e-5f);

    #pragma unroll
    for (int k = 0; k < 4; k++) {
        int c = tid + k * 128;
        O[(size_t)row * Dc + c] = (v[k] - mean) * rs * g[c] + bt[c];
    }
}

// ---------------- launch ----------------
extern "C" void kernel_launch(void* const* d_in, const int* in_sizes, int n_in,
                              void* d_out, int out_size)
{
    const float* qe   = (const float*)d_in[0];
    const float* ie   = (const float*)d_in[1];
    const float* pe   = (const float*)d_in[2];
    const float* Wk   = (const float*)d_in[3];
    const float* bk   = (const float*)d_in[4];
    const float* Wv   = (const float*)d_in[5];
    const float* bv   = (const float*)d_in[6];
    const float* Wo   = (const float*)d_in[7];
    const float* bo   = (const float*)d_in[8];
    const float* ln1g = (const float*)d_in[9];
    const float* ln1b = (const float*)d_in[10];
    const float* W1   = (const float*)d_in[11];
    const float* b1   = (const float*)d_in[12];
    const float* W2   = (const float*)d_in[13];
    const float* b2   = (const float*)d_in[14];
    const float* ln2g = (const float*)d_in[15];
    const float* ln2b = (const float*)d_in[16];
    float* out = (float*)d_out;

    float *x, *y, *q, *v, *attn, *h1, *t2;
    cudaGetSymbolAddress((void**)&x,    g_x);
    cudaGetSymbolAddress((void**)&y,    g_y);
    cudaGetSymbolAddress((void**)&q,    g_q);
    cudaGetSymbolAddress((void**)&v,    g_v);
    cudaGetSymbolAddress((void**)&attn, g_attn);
    cudaGetSymbolAddress((void**)&h1,   g_h1);
    cudaGetSymbolAddress((void**)&t2,   g_t2);

    addpos_kernel<<<((size_t)BSc * Dc + 255) / 256, 256>>>(qe, ie, pe, x, y);

    for (int l = 0; l < Lc; l++) {
        const float* Wkl = Wk + (size_t)l * Dc * Dc;
        const float* Wvl = Wv + (size_t)l * Dc * Dc;
        const float* Wol = Wo + (size_t)l * Dc * Dc;
        const float* W1l = W1 + (size_t)l * Dc * DFFc;
        const float* W2l = W2 + (size_t)l * DFFc * Dc;

        tgemm_kernel<<<dim3(Dc / BN, BSc / BM), 256>>>(x, Wkl, bk + l * Dc, q, Dc, Dc, 0);
        tgemm_kernel<<<dim3(Dc / BN, BSc / BM), 256>>>(y, Wvl, bv + l * Dc, v, Dc, Dc, 0);
        attn_kernel<<<dim3(Sc / QPB, Hc, Bc), 256>>>(q, v, attn);
        tgemm_kernel<<<dim3(Dc / BN, BSc / BM), 256>>>(attn, Wol, bo + l * Dc, t2, Dc, Dc, 0);
        ln_kernel<<<BSc, 128>>>(x, t2, ln1g + l * Dc, ln1b + l * Dc, x);
        tgemm_kernel<<<dim3(DFFc / BN, BSc / BM), 256>>>(x, W1l, b1 + l * DFFc, h1, DFFc, Dc, 1);
        tgemm_kernel<<<dim3(Dc / BN, BSc / BM), 256>>>(h1, W2l, b2 + l * Dc, t2, Dc, DFFc, 0);
        float* dst = (l == Lc - 1) ? out : x;
        ln_kernel<<<BSc, 128>>>(x, t2, ln2g + l * Dc, ln2b + l * Dc, dst);
    }
}

// round 7
// speedup vs baseline: 2.3309x; 1.2089x over previous
#include <cuda_runtime.h>
#include <math.h>
#include <float.h>
#include <limits.h>
#include <stdint.h>

#define Lc   2
#define Bc   32
#define Sc   512
#define Dc   512
#define Hc   8
#define DFFc 2048
#define DHc  64
#define KIDX 5
#define BSc  (Bc*Sc)   // 16384

// ---------------- scratch (static device globals; no allocation) ----------------
__device__ float g_x[(size_t)BSc*Dc];
__device__ float g_y[(size_t)BSc*Dc];
__device__ float g_q[(size_t)BSc*Dc];      // q == k (kq_same)
__device__ float g_v[(size_t)BSc*Dc];
__device__ float g_attn[(size_t)BSc*Dc];
__device__ float g_h1[(size_t)BSc*DFFc];
__device__ float g_t2[(size_t)BSc*Dc];

// ---------------- elementwise: x = qemb + pos, y = iemb + pos ----------------
__global__ void addpos_kernel(const float* __restrict__ qe, const float* __restrict__ ie,
                              const float* __restrict__ pe,
                              float* __restrict__ x, float* __restrict__ y)
{
    size_t idx = (size_t)blockIdx.x * blockDim.x + threadIdx.x;
    if (idx >= (size_t)BSc * Dc) return;
    size_t p = idx % ((size_t)Sc * Dc);
    float pv = pe[p];
    x[idx] = qe[idx] + pv;
    y[idx] = ie[idx] + pv;
}

// ---------------- tf32x3 tensor-core GEMM (fp32-accurate) ----------------
__device__ __forceinline__ float f2tf32f(float x) {
    uint32_t r;
    asm("cvt.rna.tf32.f32 %0, %1;" : "=r"(r) : "f"(x));
    return __uint_as_float(r);
}

__device__ __forceinline__ void mma_tf32(float c[4], const uint32_t a[4], const uint32_t b[2]) {
    asm volatile(
        "mma.sync.aligned.m16n8k8.row.col.f32.tf32.tf32.f32 "
        "{%0,%1,%2,%3}, {%4,%5,%6,%7}, {%8,%9}, {%0,%1,%2,%3};"
        : "+f"(c[0]), "+f"(c[1]), "+f"(c[2]), "+f"(c[3])
        : "r"(a[0]), "r"(a[1]), "r"(a[2]), "r"(a[3]), "r"(b[0]), "r"(b[1]));
}

#define BM 128
#define BN 128
#define BKt 16

__global__ __launch_bounds__(256)
void tgemm_kernel(const float* __restrict__ A, const float* __restrict__ Bm,
                  const float* __restrict__ bias, float* __restrict__ C,
                  int N, int K, int relu)
{
    __shared__ float As_b[BM][20];
    __shared__ float As_s[BM][20];
    __shared__ float Bs_b[BKt][136];
    __shared__ float Bs_s[BKt][136];

    const int tid  = threadIdx.x;
    const int warp = tid >> 5;
    const int lane = tid & 31;
    const int wm   = warp >> 2;
    const int wn   = warp & 3;
    const int bx = blockIdx.x, by = blockIdx.y;

    const int ar0 = tid >> 2;
    const int ac  = (tid & 3) * 4;
    const int br0 = tid >> 5;
    const int bc  = (tid & 31) * 4;

    const float* Ag = A  + ((size_t)by * BM) * K;
    const float* Bg = Bm + (size_t)bx * BN;

    float c[4][4][4];
    #pragma unroll
    for (int mt = 0; mt < 4; mt++)
        #pragma unroll
        for (int nt = 0; nt < 4; nt++)
            #pragma unroll
            for (int e = 0; e < 4; e++) c[mt][nt][e] = 0.f;

    const int NT = K / BKt;
    float4 a_st[2], b_st[2];

    a_st[0] = *(const float4*)(Ag + (size_t)ar0 * K + ac);
    a_st[1] = *(const float4*)(Ag + (size_t)(ar0 + 64) * K + ac);
    b_st[0] = *(const float4*)(Bg + (size_t)br0 * N + bc);
    b_st[1] = *(const float4*)(Bg + (size_t)(br0 + 8) * N + bc);

    for (int kt = 0; kt < NT; kt++) {
        #pragma unroll
        for (int e = 0; e < 4; e++) {
            float v0 = ((const float*)&a_st[0])[e];
            float v1 = ((const float*)&a_st[1])[e];
            float b0 = f2tf32f(v0), b1 = f2tf32f(v1);
            As_b[ar0][ac + e]      = b0;
            As_s[ar0][ac + e]      = f2tf32f(v0 - b0);
            As_b[ar0 + 64][ac + e] = b1;
            As_s[ar0 + 64][ac + e] = f2tf32f(v1 - b1);

            float w0 = ((const float*)&b_st[0])[e];
            float w1 = ((const float*)&b_st[1])[e];
            float c0 = f2tf32f(w0), c1 = f2tf32f(w1);
            Bs_b[br0][bc + e]     = c0;
            Bs_s[br0][bc + e]     = f2tf32f(w0 - c0);
            Bs_b[br0 + 8][bc + e] = c1;
            Bs_s[br0 + 8][bc + e] = f2tf32f(w1 - c1);
        }
        __syncthreads();

        if (kt + 1 < NT) {
            const int k0 = (kt + 1) * BKt;
            a_st[0] = *(const float4*)(Ag + (size_t)ar0 * K + k0 + ac);
            a_st[1] = *(const float4*)(Ag + (size_t)(ar0 + 64) * K + k0 + ac);
            b_st[0] = *(const float4*)(Bg + (size_t)(k0 + br0) * N + bc);
            b_st[1] = *(const float4*)(Bg + (size_t)(k0 + br0 + 8) * N + bc);
        }

        #pragma unroll
        for (int ks = 0; ks < 2; ks++) {
            const int kk = ks * 8;
            const int kq = kk + (lane & 3);
            uint32_t ab[4][4], as[4][4], bb[4][2], bs[4][2];
            #pragma unroll
            for (int mt = 0; mt < 4; mt++) {
                const int r = wm * 64 + mt * 16 + (lane >> 2);
                ab[mt][0] = __float_as_uint(As_b[r    ][kq    ]);
                ab[mt][1] = __float_as_uint(As_b[r + 8][kq    ]);
                ab[mt][2] = __float_as_uint(As_b[r    ][kq + 4]);
                ab[mt][3] = __float_as_uint(As_b[r + 8][kq + 4]);
                as[mt][0] = __float_as_uint(As_s[r    ][kq    ]);
                as[mt][1] = __float_as_uint(As_s[r + 8][kq    ]);
                as[mt][2] = __float_as_uint(As_s[r    ][kq + 4]);
                as[mt][3] = __float_as_uint(As_s[r + 8][kq + 4]);
            }
            #pragma unroll
            for (int nt = 0; nt < 4; nt++) {
                const int cc = wn * 32 + nt * 8 + (lane >> 2);
                bb[nt][0] = __float_as_uint(Bs_b[kq    ][cc]);
                bb[nt][1] = __float_as_uint(Bs_b[kq + 4][cc]);
                bs[nt][0] = __float_as_uint(Bs_s[kq    ][cc]);
                bs[nt][1] = __float_as_uint(Bs_s[kq + 4][cc]);
            }
            #pragma unroll
            for (int mt = 0; mt < 4; mt++)
                #pragma unroll
                for (int nt = 0; nt < 4; nt++) {
                    mma_tf32(c[mt][nt], as[mt], bb[nt]);
                    mma_tf32(c[mt][nt], ab[mt], bs[nt]);
                    mma_tf32(c[mt][nt], ab[mt], bb[nt]);
                }
        }
        __syncthreads();
    }

    #pragma unroll
    for (int mt = 0; mt < 4; mt++) {
        const int r0 = by * BM + wm * 64 + mt * 16 + (lane >> 2);
        #pragma unroll
        for (int nt = 0; nt < 4; nt++) {
            const int col = bx * BN + wn * 32 + nt * 8 + 2 * (lane & 3);
            const float b0 = bias[col], b1 = bias[col + 1];
            float2 o0, o1;
            o0.x = c[mt][nt][0] + b0; o0.y = c[mt][nt][1] + b1;
            o1.x = c[mt][nt][2] + b0; o1.y = c[mt][nt][3] + b1;
            if (relu) {
                o0.x = fmaxf(o0.x, 0.f); o0.y = fmaxf(o0.y, 0.f);
                o1.x = fmaxf(o1.x, 0.f); o1.y = fmaxf(o1.y, 0.f);
            }
            *(float2*)(C + (size_t)r0 * N + col)       = o0;
            *(float2*)(C + (size_t)(r0 + 8) * N + col) = o1;
        }
    }
}

// ---------------- bf16x3 tensor-core GEMM (m16n8k16, ~2x tf32x3 rate) ----------------
// big = bf16(x); small = bf16(x - big); C += As*Bb + Ab*Bs + Ab*Bb.
// Pairs of consecutive-k bf16 packed in uint32 smem words. BK=16.

__device__ __forceinline__ uint32_t pack_bf16(float lo, float hi) {
    uint32_t r;
    asm("cvt.rn.bf16x2.f32 %0, %1, %2;" : "=r"(r) : "f"(hi), "f"(lo));
    return r;
}

__device__ __forceinline__ void mma_bf16(float c[4], const uint32_t a[4], const uint32_t b[2]) {
    asm volatile(
        "mma.sync.aligned.m16n8k16.row.col.f32.bf16.bf16.f32 "
        "{%0,%1,%2,%3}, {%4,%5,%6,%7}, {%8,%9}, {%0,%1,%2,%3};"
        : "+f"(c[0]), "+f"(c[1]), "+f"(c[2]), "+f"(c[3])
        : "r"(a[0]), "r"(a[1]), "r"(a[2]), "r"(a[3]), "r"(b[0]), "r"(b[1]));
}

// split a pair (x,y): big word + small word via truncation trick
__device__ __forceinline__ void split_pair(float x, float y, uint32_t& wb, uint32_t& ws) {
    wb = pack_bf16(x, y);
    float bx = __uint_as_float(wb << 16);
    float by = __uint_as_float(wb & 0xFFFF0000u);
    ws = pack_bf16(x - bx, y - by);
}

#define BKb 16

__global__ __launch_bounds__(256)
void bgemm_kernel(const float* __restrict__ A, const float* __restrict__ Bm,
                  const float* __restrict__ bias, float* __restrict__ C,
                  int N, int K, int relu)
{
    // word index = k/2; 8 words used per row, stride 12 -> conflict-free frag loads
    __shared__ uint32_t Ab_[BM][12];
    __shared__ uint32_t As_[BM][12];
    __shared__ uint32_t Bb_[BN][12];   // [n][k/2]
    __shared__ uint32_t Bs_[BN][12];

    const int tid  = threadIdx.x;
    const int warp = tid >> 5;
    const int lane = tid & 31;
    const int wm   = warp >> 2;
    const int wn   = warp & 3;
    const int bx = blockIdx.x, by = blockIdx.y;

    // deposit mappings
    const int arow = tid >> 1;            // 0..127
    const int acb  = (tid & 1) * 8;       // float col base: 0 or 8
    const int kp   = tid & 7;             // k-pair index 0..7
    const int bn0  = (tid >> 3) * 4;      // 0..124

    const float* Ag = A  + ((size_t)by * BM) * K;
    const float* Bg = Bm + (size_t)bx * BN;

    float c[4][4][4];
    #pragma unroll
    for (int mt = 0; mt < 4; mt++)
        #pragma unroll
        for (int nt = 0; nt < 4; nt++)
            #pragma unroll
            for (int e = 0; e < 4; e++) c[mt][nt][e] = 0.f;

    const int NT = K / BKb;
    float4 a_st[2], b_st[2];

    a_st[0] = *(const float4*)(Ag + (size_t)arow * K + acb);
    a_st[1] = *(const float4*)(Ag + (size_t)arow * K + acb + 4);
    b_st[0] = *(const float4*)(Bg + (size_t)(2 * kp)     * N + bn0);
    b_st[1] = *(const float4*)(Bg + (size_t)(2 * kp + 1) * N + bn0);

    for (int kt = 0; kt < NT; kt++) {
        // deposit A: rows of 16 floats -> 8 packed words (big/small)
        {
            const int wc = (tid & 1) * 4;   // word col base
            uint32_t wb, ws;
            split_pair(a_st[0].x, a_st[0].y, wb, ws);
            Ab_[arow][wc + 0] = wb; As_[arow][wc + 0] = ws;
            split_pair(a_st[0].z, a_st[0].w, wb, ws);
            Ab_[arow][wc + 1] = wb; As_[arow][wc + 1] = ws;
            split_pair(a_st[1].x, a_st[1].y, wb, ws);
            Ab_[arow][wc + 2] = wb; As_[arow][wc + 2] = ws;
            split_pair(a_st[1].z, a_st[1].w, wb, ws);
            Ab_[arow][wc + 3] = wb; As_[arow][wc + 3] = ws;
        }
        // deposit B: pair rows (2kp, 2kp+1) x 4 cols -> Bpair[n][kp]
        {
            const float* r0 = (const float*)&b_st[0];
            const float* r1 = (const float*)&b_st[1];
            #pragma unroll
            for (int j = 0; j < 4; j++) {
                uint32_t wb, ws;
                split_pair(r0[j], r1[j], wb, ws);
                Bb_[bn0 + j][kp] = wb;
                Bs_[bn0 + j][kp] = ws;
            }
        }
        __syncthreads();

        if (kt + 1 < NT) {
            const int k0 = (kt + 1) * BKb;
            a_st[0] = *(const float4*)(Ag + (size_t)arow * K + k0 + acb);
            a_st[1] = *(const float4*)(Ag + (size_t)arow * K + k0 + acb + 4);
            b_st[0] = *(const float4*)(Bg + (size_t)(k0 + 2 * kp)     * N + bn0);
            b_st[1] = *(const float4*)(Bg + (size_t)(k0 + 2 * kp + 1) * N + bn0);
        }

        // one k16 mma step per tile
        {
            const int kq = lane & 3;
            uint32_t ab[4][4], as[4][4], bb[4][2], bs[4][2];
            #pragma unroll
            for (int mt = 0; mt < 4; mt++) {
                const int r = wm * 64 + mt * 16 + (lane >> 2);
                ab[mt][0] = Ab_[r    ][kq    ];
                ab[mt][1] = Ab_[r + 8][kq    ];
                ab[mt][2] = Ab_[r    ][kq + 4];
                ab[mt][3] = Ab_[r + 8][kq + 4];
                as[mt][0] = As_[r    ][kq    ];
                as[mt][1] = As_[r + 8][kq    ];
                as[mt][2] = As_[r    ][kq + 4];
                as[mt][3] = As_[r + 8][kq + 4];
            }
            #pragma unroll
            for (int nt = 0; nt < 4; nt++) {
                const int n = wn * 32 + nt * 8 + (lane >> 2);
                bb[nt][0] = Bb_[n][kq    ];
                bb[nt][1] = Bb_[n][kq + 4];
                bs[nt][0] = Bs_[n][kq    ];
                bs[nt][1] = Bs_[n][kq + 4];
            }
            #pragma unroll
            for (int mt = 0; mt < 4; mt++)
                #pragma unroll
                for (int nt = 0; nt < 4; nt++) {
                    mma_bf16(c[mt][nt], as[mt], bb[nt]);
                    mma_bf16(c[mt][nt], ab[mt], bs[nt]);
                    mma_bf16(c[mt][nt], ab[mt], bb[nt]);
                }
        }
        __syncthreads();
    }

    #pragma unroll
    for (int mt = 0; mt < 4; mt++) {
        const int r0 = by * BM + wm * 64 + mt * 16 + (lane >> 2);
        #pragma unroll
        for (int nt = 0; nt < 4; nt++) {
            const int col = bx * BN + wn * 32 + nt * 8 + 2 * (lane & 3);
            const float b0 = bias[col], b1 = bias[col + 1];
            float2 o0, o1;
            o0.x = c[mt][nt][0] + b0; o0.y = c[mt][nt][1] + b1;
            o1.x = c[mt][nt][2] + b0; o1.y = c[mt][nt][3] + b1;
            if (relu) {
                o0.x = fmaxf(o0.x, 0.f); o0.y = fmaxf(o0.y, 0.f);
                o1.x = fmaxf(o1.x, 0.f); o1.y = fmaxf(o1.y, 0.f);
            }
            *(float2*)(C + (size_t)r0 * N + col)       = o0;
            *(float2*)(C + (size_t)(r0 + 8) * N + col) = o1;
        }
    }
}

// ---------------- warp-level attention, SparseKT top-k semantics ----------------
#define FULLM 0xFFFFFFFFu
#define QPB 8

__device__ __forceinline__ float warp_max(float v) {
    #pragma unroll
    for (int o = 16; o > 0; o >>= 1) v = fmaxf(v, __shfl_xor_sync(FULLM, v, o));
    return v;
}
__device__ __forceinline__ float warp_sum(float v) {
    #pragma unroll
    for (int o = 16; o > 0; o >>= 1) v += __shfl_xor_sync(FULLM, v, o);
    return v;
}
__device__ __forceinline__ int warp_min_i(int v) {
    #pragma unroll
    for (int o = 16; o > 0; o >>= 1) v = min(v, __shfl_xor_sync(FULLM, v, o));
    return v;
}

__global__ __launch_bounds__(256)
void attn_kernel(const float* __restrict__ Q, const float* __restrict__ V,
                 float* __restrict__ O)
{
    const int qt   = blockIdx.x;
    const int h    = blockIdx.y;
    const int b    = blockIdx.z;
    const int tid  = threadIdx.x;
    const int warp = tid >> 5;
    const int lane = tid & 31;
    const int i    = qt * QPB + warp;

    __shared__ float KT[64][65];
    __shared__ float qs[QPB][64];

    const size_t base = ((size_t)b * Sc) * Dc + (size_t)h * DHc;

    qs[warp][lane]      = Q[base + (size_t)i * Dc + lane];
    qs[warp][lane + 32] = Q[base + (size_t)i * Dc + lane + 32];

    float p[16];
    #pragma unroll
    for (int t = 0; t < 16; t++) p[t] = -FLT_MAX;

    const int nk = qt * QPB + QPB - 1;

    const int key = tid >> 2;
    const int d0  = (tid & 3) * 16;

    #pragma unroll
    for (int tt = 0; tt < 8; tt++) {
        if (tt * 64 < nk) {
            const int j0 = tt * 64;
            __syncthreads();
            {
                const float* src = Q + base + (size_t)(j0 + key) * Dc + d0;
                float4 f0 = *(const float4*)(src);
                float4 f1 = *(const float4*)(src + 4);
                float4 f2 = *(const float4*)(src + 8);
                float4 f3 = *(const float4*)(src + 12);
                KT[d0 + 0][key] = f0.x; KT[d0 + 1][key] = f0.y;
                KT[d0 + 2][key] = f0.z; KT[d0 + 3][key] = f0.w;
                KT[d0 + 4][key] = f1.x; KT[d0 + 5][key] = f1.y;
                KT[d0 + 6][key] = f1.z; KT[d0 + 7][key] = f1.w;
                KT[d0 + 8][key] = f2.x; KT[d0 + 9][key] = f2.y;
                KT[d0 +10][key] = f2.z; KT[d0 +11][key] = f2.w;
                KT[d0 +12][key] = f3.x; KT[d0 +13][key] = f3.y;
                KT[d0 +14][key] = f3.z; KT[d0 +15][key] = f3.w;
            }
            __syncthreads();

            float acc0 = 0.f, acc1 = 0.f;
            #pragma unroll
            for (int d = 0; d < 64; d++) {
                const float qd = qs[warp][d];
                acc0 = fmaf(qd, KT[d][lane],      acc0);
                acc1 = fmaf(qd, KT[d][lane + 32], acc1);
            }
            const int j1 = j0 + lane, j2 = j0 + lane + 32;
            if (j1 < i) p[2 * tt]     = acc0 * 0.125f;
            if (j2 < i) p[2 * tt + 1] = acc1 * 0.125f;
        }
    }

    float lm = -FLT_MAX;
    #pragma unroll
    for (int t = 0; t < 16; t++) lm = fmaxf(lm, p[t]);
    const float m = warp_max(lm);

    float ls = 0.f;
    #pragma unroll
    for (int t = 0; t < 16; t++) { p[t] = expf(p[t] - m); ls += p[t]; }
    const float invZ = 1.f / warp_sum(ls);
    #pragma unroll
    for (int t = 0; t < 16; t++) p[t] *= invZ;

    float w[16];
    float scale = 1.f;
    if (i > KIDX) {
        #pragma unroll
        for (int t = 0; t < 16; t++) w[t] = p[t];
        float pmax = 0.f, thresh = 0.f;
        #pragma unroll 1
        for (int pass = 0; pass < 5; pass++) {
            float lmx = -1.f;
            #pragma unroll
            for (int t = 0; t < 16; t++) lmx = fmaxf(lmx, w[t]);
            const float mt = warp_max(lmx);
            if (pass == 0) pmax = mt;
            thresh = mt;
            if (pass < 4) {
                int cand = INT_MAX;
                #pragma unroll
                for (int t = 0; t < 16; t++)
                    if (w[t] == mt) cand = min(cand, t * 32 + lane);
                const int jmin = warp_min_i(cand);
                #pragma unroll
                for (int t = 0; t < 16; t++)
                    if (jmin != INT_MAX && t == (jmin >> 5) && lane == (jmin & 31))
                        w[t] = -1.f;
            }
        }
        float lsum = 0.f;
        #pragma unroll
        for (int t = 0; t < 16; t++) {
            w[t] = (p[t] >= thresh) ? expf(p[t] - pmax) : 0.f;
            lsum += w[t];
        }
        scale = 1.f / warp_sum(lsum);
    } else {
        #pragma unroll
        for (int t = 0; t < 16; t++) w[t] = p[t];
    }

    float* out = O + base + (size_t)i * Dc;
    if (i == 0) {
        out[lane] = 0.f; out[lane + 32] = 0.f;
        return;
    }

    float o0 = 0.f, o1 = 0.f;
    #pragma unroll
    for (int t = 0; t < 16; t++) {
        unsigned mask = __ballot_sync(FULLM, w[t] > 0.f);
        while (mask) {
            const int bit = __ffs(mask) - 1;
            mask &= mask - 1;
            const float wj = __shfl_sync(FULLM, w[t], bit);
            const float* vr = V + base + (size_t)(t * 32 + bit) * Dc;
            o0 = fmaf(wj, vr[lane],      o0);
            o1 = fmaf(wj, vr[lane + 32], o1);
        }
    }
    out[lane]      = o0 * scale;
    out[lane + 32] = o1 * scale;
}

// ---------------- fused residual + LayerNorm: O = LN(X + R) * g + b ----------------
__global__ void ln_kernel(const float* __restrict__ X, const float* __restrict__ R,
                          const float* __restrict__ g, const float* __restrict__ bt,
                          float* __restrict__ O)
{
    const int row = blockIdx.x;
    const int tid = threadIdx.x;   // 128
    __shared__ float s_red[128];

    const float* xr = X + (size_t)row * Dc;
    const float* rr = R + (size_t)row * Dc;

    float v[4];
    float sum = 0.f, sq = 0.f;
    #pragma unroll
    for (int k = 0; k < 4; k++) {
        float t = xr[tid + k * 128] + rr[tid + k * 128];
        v[k] = t; sum += t; sq += t * t;
    }
    s_red[tid] = sum; __syncthreads();
    for (int s = 64; s > 0; s >>= 1) { if (tid < s) s_red[tid] += s_red[tid + s]; __syncthreads(); }
    float mean = s_red[0] * (1.f / Dc); __syncthreads();
    s_red[tid] = sq; __syncthreads();
    for (int s = 64; s > 0; s >>= 1) { if (tid < s) s_red[tid] += s_red[tid + s]; __syncthreads(); }
    float var = s_red[0] * (1.f / Dc) - mean * mean;
    float rs = rsqrtf(var + 1e-5f);

    #pragma unroll
    for (int k = 0; k < 4; k++) {
        int c = tid + k * 128;
        O[(size_t)row * Dc + c] = (v[k] - mean) * rs * g[c] + bt[c];
    }
}

// ---------------- launch ----------------
extern "C" void kernel_launch(void* const* d_in, const int* in_sizes, int n_in,
                              void* d_out, int out_size)
{
    const float* qe   = (const float*)d_in[0];
    const float* ie   = (const float*)d_in[1];
    const float* pe   = (const float*)d_in[2];
    const float* Wk   = (const float*)d_in[3];
    const float* bk   = (const float*)d_in[4];
    const float* Wv   = (const float*)d_in[5];
    const float* bv   = (const float*)d_in[6];
    const float* Wo   = (const float*)d_in[7];
    const float* bo   = (const float*)d_in[8];
    const float* ln1g = (const float*)d_in[9];
    const float* ln1b = (const float*)d_in[10];
    const float* W1   = (const float*)d_in[11];
    const float* b1   = (const float*)d_in[12];
    const float* W2   = (const float*)d_in[13];
    const float* b2   = (const float*)d_in[14];
    const float* ln2g = (const float*)d_in[15];
    const float* ln2b = (const float*)d_in[16];
    float* out = (float*)d_out;

    float *x, *y, *q, *v, *attn, *h1, *t2;
    cudaGetSymbolAddress((void**)&x,    g_x);
    cudaGetSymbolAddress((void**)&y,    g_y);
    cudaGetSymbolAddress((void**)&q,    g_q);
    cudaGetSymbolAddress((void**)&v,    g_v);
    cudaGetSymbolAddress((void**)&attn, g_attn);
    cudaGetSymbolAddress((void**)&h1,   g_h1);
    cudaGetSymbolAddress((void**)&t2,   g_t2);

    addpos_kernel<<<((size_t)BSc * Dc + 255) / 256, 256>>>(qe, ie, pe, x, y);

    for (int l = 0; l < Lc; l++) {
        const float* Wkl = Wk + (size_t)l * Dc * Dc;
        const float* Wvl = Wv + (size_t)l * Dc * Dc;
        const float* Wol = Wo + (size_t)l * Dc * Dc;
        const float* W1l = W1 + (size_t)l * Dc * DFFc;
        const float* W2l = W2 + (size_t)l * DFFc * Dc;

        // score/attention path: keep tf32x3 (top-k selection is precision-sensitive)
        tgemm_kernel<<<dim3(Dc / BN, BSc / BM), 256>>>(x, Wkl, bk + l * Dc, q, Dc, Dc, 0);
        tgemm_kernel<<<dim3(Dc / BN, BSc / BM), 256>>>(y, Wvl, bv + l * Dc, v, Dc, Dc, 0);
        attn_kernel<<<dim3(Sc / QPB, Hc, Bc), 256>>>(q, v, attn);
        tgemm_kernel<<<dim3(Dc / BN, BSc / BM), 256>>>(attn, Wol, bo + l * Dc, t2, Dc, Dc, 0);
        ln_kernel<<<BSc, 128>>>(x, t2, ln1g + l * Dc, ln1b + l * Dc, x);
        // FFN (73% of GEMM flops): bf16x3 at ~2x rate
        bgemm_kernel<<<dim3(DFFc / BN, BSc / BM), 256>>>(x, W1l, b1 + l * DFFc, h1, DFFc, Dc, 1);
        bgemm_kernel<<<dim3(Dc / BN, BSc / BM), 256>>>(h1, W2l, b2 + l * Dc, t2, Dc, DFFc, 0);
        float* dst = (l == Lc - 1) ? out : x;
        ln_kernel<<<BSc, 128>>>(x, t2, ln2g + l * Dc, ln2b + l * Dc, dst);
    }
}

// round 8
// speedup vs baseline: 2.5877x; 1.1102x over previous
#include <cuda_runtime.h>
#include <math.h>
#include <float.h>
#include <limits.h>
#include <stdint.h>

#define Lc   2
#define Bc   32
#define Sc   512
#define Dc   512
#define Hc   8
#define DFFc 2048
#define DHc  64
#define KIDX 5
#define BSc  (Bc*Sc)   // 16384

// ---------------- scratch (static device globals; no allocation) ----------------
__device__ float g_x[(size_t)BSc*Dc];
__device__ float g_y[(size_t)BSc*Dc];
__device__ float g_q[(size_t)BSc*Dc];      // q == k (kq_same)
__device__ float g_v[(size_t)BSc*Dc];
__device__ float g_attn[(size_t)BSc*Dc];
__device__ float g_h1[(size_t)BSc*DFFc];
__device__ float g_t2[(size_t)BSc*Dc];

// ---------------- elementwise: x = qemb + pos, y = iemb + pos ----------------
__global__ void addpos_kernel(const float* __restrict__ qe, const float* __restrict__ ie,
                              const float* __restrict__ pe,
                              float* __restrict__ x, float* __restrict__ y)
{
    size_t idx = (size_t)blockIdx.x * blockDim.x + threadIdx.x;
    if (idx >= (size_t)BSc * Dc) return;
    size_t p = idx % ((size_t)Sc * Dc);
    float pv = pe[p];
    x[idx] = qe[idx] + pv;
    y[idx] = ie[idx] + pv;
}

// ---------------- tf32x3 tensor-core GEMM (fp32-accurate; score path only) ----------------
__device__ __forceinline__ float f2tf32f(float x) {
    uint32_t r;
    asm("cvt.rna.tf32.f32 %0, %1;" : "=r"(r) : "f"(x));
    return __uint_as_float(r);
}

__device__ __forceinline__ void mma_tf32(float c[4], const uint32_t a[4], const uint32_t b[2]) {
    asm volatile(
        "mma.sync.aligned.m16n8k8.row.col.f32.tf32.tf32.f32 "
        "{%0,%1,%2,%3}, {%4,%5,%6,%7}, {%8,%9}, {%0,%1,%2,%3};"
        : "+f"(c[0]), "+f"(c[1]), "+f"(c[2]), "+f"(c[3])
        : "r"(a[0]), "r"(a[1]), "r"(a[2]), "r"(a[3]), "r"(b[0]), "r"(b[1]));
}

#define BM 128
#define BN 128
#define BKt 16

__global__ __launch_bounds__(256)
void tgemm_kernel(const float* __restrict__ A, const float* __restrict__ Bm,
                  const float* __restrict__ bias, float* __restrict__ C,
                  int N, int K, int relu)
{
    __shared__ float As_b[BM][20];
    __shared__ float As_s[BM][20];
    __shared__ float Bs_b[BKt][136];
    __shared__ float Bs_s[BKt][136];

    const int tid  = threadIdx.x;
    const int warp = tid >> 5;
    const int lane = tid & 31;
    const int wm   = warp >> 2;
    const int wn   = warp & 3;
    const int bx = blockIdx.x, by = blockIdx.y;

    const int ar0 = tid >> 2;
    const int ac  = (tid & 3) * 4;
    const int br0 = tid >> 5;
    const int bc  = (tid & 31) * 4;

    const float* Ag = A  + ((size_t)by * BM) * K;
    const float* Bg = Bm + (size_t)bx * BN;

    float c[4][4][4];
    #pragma unroll
    for (int mt = 0; mt < 4; mt++)
        #pragma unroll
        for (int nt = 0; nt < 4; nt++)
            #pragma unroll
            for (int e = 0; e < 4; e++) c[mt][nt][e] = 0.f;

    const int NT = K / BKt;
    float4 a_st[2], b_st[2];

    a_st[0] = *(const float4*)(Ag + (size_t)ar0 * K + ac);
    a_st[1] = *(const float4*)(Ag + (size_t)(ar0 + 64) * K + ac);
    b_st[0] = *(const float4*)(Bg + (size_t)br0 * N + bc);
    b_st[1] = *(const float4*)(Bg + (size_t)(br0 + 8) * N + bc);

    for (int kt = 0; kt < NT; kt++) {
        #pragma unroll
        for (int e = 0; e < 4; e++) {
            float v0 = ((const float*)&a_st[0])[e];
            float v1 = ((const float*)&a_st[1])[e];
            float b0 = f2tf32f(v0), b1 = f2tf32f(v1);
            As_b[ar0][ac + e]      = b0;
            As_s[ar0][ac + e]      = f2tf32f(v0 - b0);
            As_b[ar0 + 64][ac + e] = b1;
            As_s[ar0 + 64][ac + e] = f2tf32f(v1 - b1);

            float w0 = ((const float*)&b_st[0])[e];
            float w1 = ((const float*)&b_st[1])[e];
            float c0 = f2tf32f(w0), c1 = f2tf32f(w1);
            Bs_b[br0][bc + e]     = c0;
            Bs_s[br0][bc + e]     = f2tf32f(w0 - c0);
            Bs_b[br0 + 8][bc + e] = c1;
            Bs_s[br0 + 8][bc + e] = f2tf32f(w1 - c1);
        }
        __syncthreads();

        if (kt + 1 < NT) {
            const int k0 = (kt + 1) * BKt;
            a_st[0] = *(const float4*)(Ag + (size_t)ar0 * K + k0 + ac);
            a_st[1] = *(const float4*)(Ag + (size_t)(ar0 + 64) * K + k0 + ac);
            b_st[0] = *(const float4*)(Bg + (size_t)(k0 + br0) * N + bc);
            b_st[1] = *(const float4*)(Bg + (size_t)(k0 + br0 + 8) * N + bc);
        }

        #pragma unroll
        for (int ks = 0; ks < 2; ks++) {
            const int kk = ks * 8;
            const int kq = kk + (lane & 3);
            uint32_t ab[4][4], as[4][4], bb[4][2], bs[4][2];
            #pragma unroll
            for (int mt = 0; mt < 4; mt++) {
                const int r = wm * 64 + mt * 16 + (lane >> 2);
                ab[mt][0] = __float_as_uint(As_b[r    ][kq    ]);
                ab[mt][1] = __float_as_uint(As_b[r + 8][kq    ]);
                ab[mt][2] = __float_as_uint(As_b[r    ][kq + 4]);
                ab[mt][3] = __float_as_uint(As_b[r + 8][kq + 4]);
                as[mt][0] = __float_as_uint(As_s[r    ][kq    ]);
                as[mt][1] = __float_as_uint(As_s[r + 8][kq    ]);
                as[mt][2] = __float_as_uint(As_s[r    ][kq + 4]);
                as[mt][3] = __float_as_uint(As_s[r + 8][kq + 4]);
            }
            #pragma unroll
            for (int nt = 0; nt < 4; nt++) {
                const int cc = wn * 32 + nt * 8 + (lane >> 2);
                bb[nt][0] = __float_as_uint(Bs_b[kq    ][cc]);
                bb[nt][1] = __float_as_uint(Bs_b[kq + 4][cc]);
                bs[nt][0] = __float_as_uint(Bs_s[kq    ][cc]);
                bs[nt][1] = __float_as_uint(Bs_s[kq + 4][cc]);
            }
            #pragma unroll
            for (int mt = 0; mt < 4; mt++)
                #pragma unroll
                for (int nt = 0; nt < 4; nt++) {
                    mma_tf32(c[mt][nt], as[mt], bb[nt]);
                    mma_tf32(c[mt][nt], ab[mt], bs[nt]);
                    mma_tf32(c[mt][nt], ab[mt], bb[nt]);
                }
        }
        __syncthreads();
    }

    #pragma unroll
    for (int mt = 0; mt < 4; mt++) {
        const int r0 = by * BM + wm * 64 + mt * 16 + (lane >> 2);
        #pragma unroll
        for (int nt = 0; nt < 4; nt++) {
            const int col = bx * BN + wn * 32 + nt * 8 + 2 * (lane & 3);
            const float b0 = bias[col], b1 = bias[col + 1];
            float2 o0, o1;
            o0.x = c[mt][nt][0] + b0; o0.y = c[mt][nt][1] + b1;
            o1.x = c[mt][nt][2] + b0; o1.y = c[mt][nt][3] + b1;
            if (relu) {
                o0.x = fmaxf(o0.x, 0.f); o0.y = fmaxf(o0.y, 0.f);
                o1.x = fmaxf(o1.x, 0.f); o1.y = fmaxf(o1.y, 0.f);
            }
            *(float2*)(C + (size_t)r0 * N + col)       = o0;
            *(float2*)(C + (size_t)(r0 + 8) * N + col) = o1;
        }
    }
}

// ---------------- bf16x3 tensor-core GEMM (m16n8k16) ----------------
__device__ __forceinline__ uint32_t pack_bf16(float lo, float hi) {
    uint32_t r;
    asm("cvt.rn.bf16x2.f32 %0, %1, %2;" : "=r"(r) : "f"(hi), "f"(lo));
    return r;
}

__device__ __forceinline__ void mma_bf16(float c[4], const uint32_t a[4], const uint32_t b[2]) {
    asm volatile(
        "mma.sync.aligned.m16n8k16.row.col.f32.bf16.bf16.f32 "
        "{%0,%1,%2,%3}, {%4,%5,%6,%7}, {%8,%9}, {%0,%1,%2,%3};"
        : "+f"(c[0]), "+f"(c[1]), "+f"(c[2]), "+f"(c[3])
        : "r"(a[0]), "r"(a[1]), "r"(a[2]), "r"(a[3]), "r"(b[0]), "r"(b[1]));
}

__device__ __forceinline__ void split_pair(float x, float y, uint32_t& wb, uint32_t& ws) {
    wb = pack_bf16(x, y);
    float bx = __uint_as_float(wb << 16);
    float by = __uint_as_float(wb & 0xFFFF0000u);
    ws = pack_bf16(x - bx, y - by);
}

#define BKb 16

__global__ __launch_bounds__(256)
void bgemm_kernel(const float* __restrict__ A, const float* __restrict__ Bm,
                  const float* __restrict__ bias, float* __restrict__ C,
                  int N, int K, int relu)
{
    __shared__ uint32_t Ab_[BM][12];
    __shared__ uint32_t As_[BM][12];
    __shared__ uint32_t Bb_[BN][12];
    __shared__ uint32_t Bs_[BN][12];

    const int tid  = threadIdx.x;
    const int warp = tid >> 5;
    const int lane = tid & 31;
    const int wm   = warp >> 2;
    const int wn   = warp & 3;
    const int bx = blockIdx.x, by = blockIdx.y;

    const int arow = tid >> 1;
    const int acb  = (tid & 1) * 8;
    const int kp   = tid & 7;
    const int bn0  = (tid >> 3) * 4;

    const float* Ag = A  + ((size_t)by * BM) * K;
    const float* Bg = Bm + (size_t)bx * BN;

    float c[4][4][4];
    #pragma unroll
    for (int mt = 0; mt < 4; mt++)
        #pragma unroll
        for (int nt = 0; nt < 4; nt++)
            #pragma unroll
            for (int e = 0; e < 4; e++) c[mt][nt][e] = 0.f;

    const int NT = K / BKb;
    float4 a_st[2], b_st[2];

    a_st[0] = *(const float4*)(Ag + (size_t)arow * K + acb);
    a_st[1] = *(const float4*)(Ag + (size_t)arow * K + acb + 4);
    b_st[0] = *(const float4*)(Bg + (size_t)(2 * kp)     * N + bn0);
    b_st[1] = *(const float4*)(Bg + (size_t)(2 * kp + 1) * N + bn0);

    for (int kt = 0; kt < NT; kt++) {
        {
            const int wc = (tid & 1) * 4;
            uint32_t wb, ws;
            split_pair(a_st[0].x, a_st[0].y, wb, ws);
            Ab_[arow][wc + 0] = wb; As_[arow][wc + 0] = ws;
            split_pair(a_st[0].z, a_st[0].w, wb, ws);
            Ab_[arow][wc + 1] = wb; As_[arow][wc + 1] = ws;
            split_pair(a_st[1].x, a_st[1].y, wb, ws);
            Ab_[arow][wc + 2] = wb; As_[arow][wc + 2] = ws;
            split_pair(a_st[1].z, a_st[1].w, wb, ws);
            Ab_[arow][wc + 3] = wb; As_[arow][wc + 3] = ws;
        }
        {
            const float* r0 = (const float*)&b_st[0];
            const float* r1 = (const float*)&b_st[1];
            #pragma unroll
            for (int j = 0; j < 4; j++) {
                uint32_t wb, ws;
                split_pair(r0[j], r1[j], wb, ws);
                Bb_[bn0 + j][kp] = wb;
                Bs_[bn0 + j][kp] = ws;
            }
        }
        __syncthreads();

        if (kt + 1 < NT) {
            const int k0 = (kt + 1) * BKb;
            a_st[0] = *(const float4*)(Ag + (size_t)arow * K + k0 + acb);
            a_st[1] = *(const float4*)(Ag + (size_t)arow * K + k0 + acb + 4);
            b_st[0] = *(const float4*)(Bg + (size_t)(k0 + 2 * kp)     * N + bn0);
            b_st[1] = *(const float4*)(Bg + (size_t)(k0 + 2 * kp + 1) * N + bn0);
        }

        {
            const int kq = lane & 3;
            uint32_t ab[4][4], as[4][4], bb[4][2], bs[4][2];
            #pragma unroll
            for (int mt = 0; mt < 4; mt++) {
                const int r = wm * 64 + mt * 16 + (lane >> 2);
                ab[mt][0] = Ab_[r    ][kq    ];
                ab[mt][1] = Ab_[r + 8][kq    ];
                ab[mt][2] = Ab_[r    ][kq + 4];
                ab[mt][3] = Ab_[r + 8][kq + 4];
                as[mt][0] = As_[r    ][kq    ];
                as[mt][1] = As_[r + 8][kq    ];
                as[mt][2] = As_[r    ][kq + 4];
                as[mt][3] = As_[r + 8][kq + 4];
            }
            #pragma unroll
            for (int nt = 0; nt < 4; nt++) {
                const int n = wn * 32 + nt * 8 + (lane >> 2);
                bb[nt][0] = Bb_[n][kq    ];
                bb[nt][1] = Bb_[n][kq + 4];
                bs[nt][0] = Bs_[n][kq    ];
                bs[nt][1] = Bs_[n][kq + 4];
            }
            #pragma unroll
            for (int mt = 0; mt < 4; mt++)
                #pragma unroll
                for (int nt = 0; nt < 4; nt++) {
                    mma_bf16(c[mt][nt], as[mt], bb[nt]);
                    mma_bf16(c[mt][nt], ab[mt], bs[nt]);
                    mma_bf16(c[mt][nt], ab[mt], bb[nt]);
                }
        }
        __syncthreads();
    }

    #pragma unroll
    for (int mt = 0; mt < 4; mt++) {
        const int r0 = by * BM + wm * 64 + mt * 16 + (lane >> 2);
        #pragma unroll
        for (int nt = 0; nt < 4; nt++) {
            const int col = bx * BN + wn * 32 + nt * 8 + 2 * (lane & 3);
            const float b0 = bias[col], b1 = bias[col + 1];
            float2 o0, o1;
            o0.x = c[mt][nt][0] + b0; o0.y = c[mt][nt][1] + b1;
            o1.x = c[mt][nt][2] + b0; o1.y = c[mt][nt][3] + b1;
            if (relu) {
                o0.x = fmaxf(o0.x, 0.f); o0.y = fmaxf(o0.y, 0.f);
                o1.x = fmaxf(o1.x, 0.f); o1.y = fmaxf(o1.y, 0.f);
            }
            *(float2*)(C + (size_t)r0 * N + col)       = o0;
            *(float2*)(C + (size_t)(r0 + 8) * N + col) = o1;
        }
    }
}

// ---------------- warp-level attention, 2 queries/warp, SparseKT top-k ----------------
#define FULLM 0xFFFFFFFFu
#define QPB 16   // queries per block (8 warps x 2)

__device__ __forceinline__ float warp_max(float v) {
    #pragma unroll
    for (int o = 16; o > 0; o >>= 1) v = fmaxf(v, __shfl_xor_sync(FULLM, v, o));
    return v;
}
__device__ __forceinline__ float warp_sum(float v) {
    #pragma unroll
    for (int o = 16; o > 0; o >>= 1) v += __shfl_xor_sync(FULLM, v, o);
    return v;
}
__device__ __forceinline__ int warp_min_i(int v) {
    #pragma unroll
    for (int o = 16; o > 0; o >>= 1) v = min(v, __shfl_xor_sync(FULLM, v, o));
    return v;
}

__global__ __launch_bounds__(256)
void attn_kernel(const float* __restrict__ Q, const float* __restrict__ V,
                 float* __restrict__ O)
{
    const int qt   = blockIdx.x;
    const int h    = blockIdx.y;
    const int b    = blockIdx.z;
    const int tid  = threadIdx.x;
    const int warp = tid >> 5;
    const int lane = tid & 31;
    const int i0   = qt * QPB + warp * 2;      // this warp's queries: i0, i0+1

    // KT2[d][kl] = (K[j0+kl][d], K[j0+kl+32][d]); pad 33 -> conflict-free LDS.64
    __shared__ float2 KT2[64][33];
    __shared__ float2 qs2[QPB][32];            // (q[2d], q[2d+1])

    const size_t base = ((size_t)b * Sc) * Dc + (size_t)h * DHc;

    // load both queries for this warp (float2 from global)
    qs2[warp * 2    ][lane] = *(const float2*)(Q + base + (size_t)i0 * Dc + 2 * lane);
    qs2[warp * 2 + 1][lane] = *(const float2*)(Q + base + (size_t)(i0 + 1) * Dc + 2 * lane);

    // per-query scores in registers: slot t holds j = 32*t + lane
    float p0[16], p1[16];
    #pragma unroll
    for (int t = 0; t < 16; t++) { p0[t] = -FLT_MAX; p1[t] = -FLT_MAX; }

    const int nk = qt * QPB + QPB - 1;         // max query index in block

    // staging map: key = tid & 63, dgroup = tid >> 6 (16 d's each)
    const int skey = tid & 63;
    const int sd0  = (tid >> 6) * 16;
    const int skl  = skey & 31;
    const int shalf = skey >> 5;
    float* KTf = (float*)&KT2[0][0];           // flat view: idx = (d*33 + kl)*2 + half

    #pragma unroll
    for (int tt = 0; tt < 8; tt++) {
        if (tt * 64 < nk) {
            const int j0 = tt * 64;
            __syncthreads();                   // prev readers done (and qs2 ready on tt=0)
            {
                const float* src = Q + base + (size_t)(j0 + skey) * Dc + sd0;
                float4 f0 = *(const float4*)(src);
                float4 f1 = *(const float4*)(src + 4);
                float4 f2 = *(const float4*)(src + 8);
                float4 f3 = *(const float4*)(src + 12);
                const int bi = skl * 2 + shalf;
                KTf[(sd0 + 0) * 66 + bi] = f0.x;  KTf[(sd0 + 1) * 66 + bi] = f0.y;
                KTf[(sd0 + 2) * 66 + bi] = f0.z;  KTf[(sd0 + 3) * 66 + bi] = f0.w;
                KTf[(sd0 + 4) * 66 + bi] = f1.x;  KTf[(sd0 + 5) * 66 + bi] = f1.y;
                KTf[(sd0 + 6) * 66 + bi] = f1.z;  KTf[(sd0 + 7) * 66 + bi] = f1.w;
                KTf[(sd0 + 8) * 66 + bi] = f2.x;  KTf[(sd0 + 9) * 66 + bi] = f2.y;
                KTf[(sd0 +10) * 66 + bi] = f2.z;  KTf[(sd0 +11) * 66 + bi] = f2.w;
                KTf[(sd0 +12) * 66 + bi] = f3.x;  KTf[(sd0 +13) * 66 + bi] = f3.y;
                KTf[(sd0 +14) * 66 + bi] = f3.z;  KTf[(sd0 +15) * 66 + bi] = f3.w;
            }
            __syncthreads();

            float a00 = 0.f, a01 = 0.f, a10 = 0.f, a11 = 0.f; // [query][keyhalf]
            #pragma unroll
            for (int dd = 0; dd < 32; dd++) {
                const float2 ka = KT2[2 * dd    ][lane];
                const float2 kb = KT2[2 * dd + 1][lane];
                const float2 q0 = qs2[warp * 2    ][dd];
                const float2 q1 = qs2[warp * 2 + 1][dd];
                a00 = fmaf(q0.x, ka.x, a00); a00 = fmaf(q0.y, kb.x, a00);
                a01 = fmaf(q0.x, ka.y, a01); a01 = fmaf(q0.y, kb.y, a01);
                a10 = fmaf(q1.x, ka.x, a10); a10 = fmaf(q1.y, kb.x, a10);
                a11 = fmaf(q1.x, ka.y, a11); a11 = fmaf(q1.y, kb.y, a11);
            }
            const int j1 = j0 + lane, j2 = j0 + lane + 32;
            if (j1 < i0)     p0[2 * tt]     = a00 * 0.125f;
            if (j2 < i0)     p0[2 * tt + 1] = a01 * 0.125f;
            if (j1 < i0 + 1) p1[2 * tt]     = a10 * 0.125f;
            if (j2 < i0 + 1) p1[2 * tt + 1] = a11 * 0.125f;
        }
    }

    // ---- per-query epilogue (softmax, top-k, sparse PV); no block syncs below ----
    #pragma unroll
    for (int qq = 0; qq < 2; qq++) {
        const int i = i0 + qq;
        float p[16];
        #pragma unroll
        for (int t = 0; t < 16; t++) p[t] = qq ? p1[t] : p0[t];

        float* out = O + base + (size_t)i * Dc;
        if (i == 0) {                           // zero_pad row
            out[lane] = 0.f; out[lane + 32] = 0.f;
            continue;
        }

        float lm = -FLT_MAX;
        #pragma unroll
        for (int t = 0; t < 16; t++) lm = fmaxf(lm, p[t]);
        const float m = warp_max(lm);

        float ls = 0.f;
        #pragma unroll
        for (int t = 0; t < 16; t++) { p[t] = expf(p[t] - m); ls += p[t]; }
        const float invZ = 1.f / warp_sum(ls);
        #pragma unroll
        for (int t = 0; t < 16; t++) p[t] *= invZ;

        float w[16];
        float scale = 1.f;
        if (i > KIDX) {
            #pragma unroll
            for (int t = 0; t < 16; t++) w[t] = p[t];
            float pmax = 0.f, thresh = 0.f;
            #pragma unroll 1
            for (int pass = 0; pass < 5; pass++) {
                float lmx = -1.f;
                #pragma unroll
                for (int t = 0; t < 16; t++) lmx = fmaxf(lmx, w[t]);
                const float mt = warp_max(lmx);
                if (pass == 0) pmax = mt;
                thresh = mt;
                if (pass < 4) {
                    int cand = INT_MAX;
                    #pragma unroll
                    for (int t = 0; t < 16; t++)
                        if (w[t] == mt) cand = min(cand, t * 32 + lane);
                    const int jmin = warp_min_i(cand);
                    #pragma unroll
                    for (int t = 0; t < 16; t++)
                        if (jmin != INT_MAX && t == (jmin >> 5) && lane == (jmin & 31))
                            w[t] = -1.f;
                }
            }
            float lsum = 0.f;
            #pragma unroll
            for (int t = 0; t < 16; t++) {
                w[t] = (p[t] >= thresh) ? expf(p[t] - pmax) : 0.f;
                lsum += w[t];
            }
            scale = 1.f / warp_sum(lsum);
        } else {
            #pragma unroll
            for (int t = 0; t < 16; t++) w[t] = p[t];
        }

        float o0 = 0.f, o1 = 0.f;
        #pragma unroll
        for (int t = 0; t < 16; t++) {
            unsigned mask = __ballot_sync(FULLM, w[t] > 0.f);
            while (mask) {
                const int bit = __ffs(mask) - 1;
                mask &= mask - 1;
                const float wj = __shfl_sync(FULLM, w[t], bit);
                const float* vr = V + base + (size_t)(t * 32 + bit) * Dc;
                o0 = fmaf(wj, vr[lane],      o0);
                o1 = fmaf(wj, vr[lane + 32], o1);
            }
        }
        out[lane]      = o0 * scale;
        out[lane + 32] = o1 * scale;
    }
}

// ---------------- fused residual + LayerNorm: O = LN(X + R) * g + b ----------------
__global__ void ln_kernel(const float* __restrict__ X, const float* __restrict__ R,
                          const float* __restrict__ g, const float* __restrict__ bt,
                          float* __restrict__ O)
{
    const int row = blockIdx.x;
    const int tid = threadIdx.x;   // 128
    __shared__ float s_red[128];

    const float* xr = X + (size_t)row * Dc;
    const float* rr = R + (size_t)row * Dc;

    float v[4];
    float sum = 0.f, sq = 0.f;
    #pragma unroll
    for (int k = 0; k < 4; k++) {
        float t = xr[tid + k * 128] + rr[tid + k * 128];
        v[k] = t; sum += t; sq += t * t;
    }
    s_red[tid] = sum; __syncthreads();
    for (int s = 64; s > 0; s >>= 1) { if (tid < s) s_red[tid] += s_red[tid + s]; __syncthreads(); }
    float mean = s_red[0] * (1.f / Dc); __syncthreads();
    s_red[tid] = sq; __syncthreads();
    for (int s = 64; s > 0; s >>= 1) { if (tid < s) s_red[tid] += s_red[tid + s]; __syncthreads(); }
    float var = s_red[0] * (1.f / Dc) - mean * mean;
    float rs = rsqrtf(var + 1e-5f);

    #pragma unroll
    for (int k = 0; k < 4; k++) {
        int c = tid + k * 128;
        O[(size_t)row * Dc + c] = (v[k] - mean) * rs * g[c] + bt[c];
    }
}

// ---------------- launch ----------------
extern "C" void kernel_launch(void* const* d_in, const int* in_sizes, int n_in,
                              void* d_out, int out_size)
{
    const float* qe   = (const float*)d_in[0];
    const float* ie   = (const float*)d_in[1];
    const float* pe   = (const float*)d_in[2];
    const float* Wk   = (const float*)d_in[3];
    const float* bk   = (const float*)d_in[4];
    const float* Wv   = (const float*)d_in[5];
    const float* bv   = (const float*)d_in[6];
    const float* Wo   = (const float*)d_in[7];
    const float* bo   = (const float*)d_in[8];
    const float* ln1g = (const float*)d_in[9];
    const float* ln1b = (const float*)d_in[10];
    const float* W1   = (const float*)d_in[11];
    const float* b1   = (const float*)d_in[12];
    const float* W2   = (const float*)d_in[13];
    const float* b2   = (const float*)d_in[14];
    const float* ln2g = (const float*)d_in[15];
    const float* ln2b = (const float*)d_in[16];
    float* out = (float*)d_out;

    float *x, *y, *q, *v, *attn, *h1, *t2;
    cudaGetSymbolAddress((void**)&x,    g_x);
    cudaGetSymbolAddress((void**)&y,    g_y);
    cudaGetSymbolAddress((void**)&q,    g_q);
    cudaGetSymbolAddress((void**)&v,    g_v);
    cudaGetSymbolAddress((void**)&attn, g_attn);
    cudaGetSymbolAddress((void**)&h1,   g_h1);
    cudaGetSymbolAddress((void**)&t2,   g_t2);

    addpos_kernel<<<((size_t)BSc * Dc + 255) / 256, 256>>>(qe, ie, pe, x, y);

    for (int l = 0; l < Lc; l++) {
        const float* Wkl = Wk + (size_t)l * Dc * Dc;
        const float* Wvl = Wv + (size_t)l * Dc * Dc;
        const float* Wol = Wo + (size_t)l * Dc * Dc;
        const float* W1l = W1 + (size_t)l * Dc * DFFc;
        const float* W2l = W2 + (size_t)l * DFFc * Dc;

        // Wk stays tf32x3: feeds the precision-sensitive top-k score path
        tgemm_kernel<<<dim3(Dc / BN, BSc / BM), 256>>>(x, Wkl, bk + l * Dc, q, Dc, Dc, 0);
        // Wv, Wo: linear paths -> bf16x3
        bgemm_kernel<<<dim3(Dc / BN, BSc / BM), 256>>>(y, Wvl, bv + l * Dc, v, Dc, Dc, 0);
        attn_kernel<<<dim3(Sc / QPB, Hc, Bc), 256>>>(q, v, attn);
        bgemm_kernel<<<dim3(Dc / BN, BSc / BM), 256>>>(attn, Wol, bo + l * Dc, t2, Dc, Dc, 0);
        ln_kernel<<<BSc, 128>>>(x, t2, ln1g + l * Dc, ln1b + l * Dc, x);
        bgemm_kernel<<<dim3(DFFc / BN, BSc / BM), 256>>>(x, W1l, b1 + l * DFFc, h1, DFFc, Dc, 1);
        bgemm_kernel<<<dim3(Dc / BN, BSc / BM), 256>>>(h1, W2l, b2 + l * Dc, t2, Dc, DFFc, 0);
        float* dst = (l == Lc - 1) ? out : x;
        ln_kernel<<<BSc, 128>>>(x, t2, ln2g + l * Dc, ln2b + l * Dc, dst);
    }
}

// round 9
// speedup vs baseline: 2.7655x; 1.0687x over previous
#include <cuda_runtime.h>
#include <math.h>
#include <float.h>
#include <limits.h>
#include <stdint.h>

#define Lc   2
#define Bc   32
#define Sc   512
#define Dc   512
#define Hc   8
#define DFFc 2048
#define DHc  64
#define KIDX 5
#define BSc  (Bc*Sc)   // 16384

// ---------------- scratch (static device globals; no allocation) ----------------
__device__ float g_x[(size_t)BSc*Dc];
__device__ float g_y[(size_t)BSc*Dc];
__device__ float g_q[(size_t)BSc*Dc];      // q == k (kq_same)
__device__ float g_v[(size_t)BSc*Dc];
__device__ float g_attn[(size_t)BSc*Dc];
__device__ float g_h1[(size_t)BSc*DFFc];
__device__ float g_t2[(size_t)BSc*Dc];

// ---------------- elementwise: x = qemb + pos, y = iemb + pos ----------------
__global__ void addpos_kernel(const float* __restrict__ qe, const float* __restrict__ ie,
                              const float* __restrict__ pe,
                              float* __restrict__ x, float* __restrict__ y)
{
    size_t idx = (size_t)blockIdx.x * blockDim.x + threadIdx.x;
    if (idx >= (size_t)BSc * Dc) return;
    size_t p = idx % ((size_t)Sc * Dc);
    float pv = pe[p];
    x[idx] = qe[idx] + pv;
    y[idx] = ie[idx] + pv;
}

// ---------------- tf32x3 tensor-core GEMM (fp32-accurate; score path only) ----------------
__device__ __forceinline__ float f2tf32f(float x) {
    uint32_t r;
    asm("cvt.rna.tf32.f32 %0, %1;" : "=r"(r) : "f"(x));
    return __uint_as_float(r);
}

__device__ __forceinline__ void mma_tf32(float c[4], const uint32_t a[4], const uint32_t b[2]) {
    asm volatile(
        "mma.sync.aligned.m16n8k8.row.col.f32.tf32.tf32.f32 "
        "{%0,%1,%2,%3}, {%4,%5,%6,%7}, {%8,%9}, {%0,%1,%2,%3};"
        : "+f"(c[0]), "+f"(c[1]), "+f"(c[2]), "+f"(c[3])
        : "r"(a[0]), "r"(a[1]), "r"(a[2]), "r"(a[3]), "r"(b[0]), "r"(b[1]));
}

#define BM 128
#define BN 128
#define BKt 16

__global__ __launch_bounds__(256)
void tgemm_kernel(const float* __restrict__ A, const float* __restrict__ Bm,
                  const float* __restrict__ bias, float* __restrict__ C,
                  int N, int K, int relu)
{
    __shared__ float As_b[BM][20];
    __shared__ float As_s[BM][20];
    __shared__ float Bs_b[BKt][136];
    __shared__ float Bs_s[BKt][136];

    const int tid  = threadIdx.x;
    const int warp = tid >> 5;
    const int lane = tid & 31;
    const int wm   = warp >> 2;
    const int wn   = warp & 3;
    const int bx = blockIdx.x, by = blockIdx.y;

    const int ar0 = tid >> 2;
    const int ac  = (tid & 3) * 4;
    const int br0 = tid >> 5;
    const int bc  = (tid & 31) * 4;

    const float* Ag = A  + ((size_t)by * BM) * K;
    const float* Bg = Bm + (size_t)bx * BN;

    float c[4][4][4];
    #pragma unroll
    for (int mt = 0; mt < 4; mt++)
        #pragma unroll
        for (int nt = 0; nt < 4; nt++)
            #pragma unroll
            for (int e = 0; e < 4; e++) c[mt][nt][e] = 0.f;

    const int NT = K / BKt;
    float4 a_st[2], b_st[2];

    a_st[0] = *(const float4*)(Ag + (size_t)ar0 * K + ac);
    a_st[1] = *(const float4*)(Ag + (size_t)(ar0 + 64) * K + ac);
    b_st[0] = *(const float4*)(Bg + (size_t)br0 * N + bc);
    b_st[1] = *(const float4*)(Bg + (size_t)(br0 + 8) * N + bc);

    for (int kt = 0; kt < NT; kt++) {
        #pragma unroll
        for (int e = 0; e < 4; e++) {
            float v0 = ((const float*)&a_st[0])[e];
            float v1 = ((const float*)&a_st[1])[e];
            float b0 = f2tf32f(v0), b1 = f2tf32f(v1);
            As_b[ar0][ac + e]      = b0;
            As_s[ar0][ac + e]      = f2tf32f(v0 - b0);
            As_b[ar0 + 64][ac + e] = b1;
            As_s[ar0 + 64][ac + e] = f2tf32f(v1 - b1);

            float w0 = ((const float*)&b_st[0])[e];
            float w1 = ((const float*)&b_st[1])[e];
            float c0 = f2tf32f(w0), c1 = f2tf32f(w1);
            Bs_b[br0][bc + e]     = c0;
            Bs_s[br0][bc + e]     = f2tf32f(w0 - c0);
            Bs_b[br0 + 8][bc + e] = c1;
            Bs_s[br0 + 8][bc + e] = f2tf32f(w1 - c1);
        }
        __syncthreads();

        if (kt + 1 < NT) {
            const int k0 = (kt + 1) * BKt;
            a_st[0] = *(const float4*)(Ag + (size_t)ar0 * K + k0 + ac);
            a_st[1] = *(const float4*)(Ag + (size_t)(ar0 + 64) * K + k0 + ac);
            b_st[0] = *(const float4*)(Bg + (size_t)(k0 + br0) * N + bc);
            b_st[1] = *(const float4*)(Bg + (size_t)(k0 + br0 + 8) * N + bc);
        }

        #pragma unroll
        for (int ks = 0; ks < 2; ks++) {
            const int kk = ks * 8;
            const int kq = kk + (lane & 3);
            uint32_t ab[4][4], as[4][4], bb[4][2], bs[4][2];
            #pragma unroll
            for (int mt = 0; mt < 4; mt++) {
                const int r = wm * 64 + mt * 16 + (lane >> 2);
                ab[mt][0] = __float_as_uint(As_b[r    ][kq    ]);
                ab[mt][1] = __float_as_uint(As_b[r + 8][kq    ]);
                ab[mt][2] = __float_as_uint(As_b[r    ][kq + 4]);
                ab[mt][3] = __float_as_uint(As_b[r + 8][kq + 4]);
                as[mt][0] = __float_as_uint(As_s[r    ][kq    ]);
                as[mt][1] = __float_as_uint(As_s[r + 8][kq    ]);
                as[mt][2] = __float_as_uint(As_s[r    ][kq + 4]);
                as[mt][3] = __float_as_uint(As_s[r + 8][kq + 4]);
            }
            #pragma unroll
            for (int nt = 0; nt < 4; nt++) {
                const int cc = wn * 32 + nt * 8 + (lane >> 2);
                bb[nt][0] = __float_as_uint(Bs_b[kq    ][cc]);
                bb[nt][1] = __float_as_uint(Bs_b[kq + 4][cc]);
                bs[nt][0] = __float_as_uint(Bs_s[kq    ][cc]);
                bs[nt][1] = __float_as_uint(Bs_s[kq + 4][cc]);
            }
            #pragma unroll
            for (int mt = 0; mt < 4; mt++)
                #pragma unroll
                for (int nt = 0; nt < 4; nt++) {
                    mma_tf32(c[mt][nt], as[mt], bb[nt]);
                    mma_tf32(c[mt][nt], ab[mt], bs[nt]);
                    mma_tf32(c[mt][nt], ab[mt], bb[nt]);
                }
        }
        __syncthreads();
    }

    #pragma unroll
    for (int mt = 0; mt < 4; mt++) {
        const int r0 = by * BM + wm * 64 + mt * 16 + (lane >> 2);
        #pragma unroll
        for (int nt = 0; nt < 4; nt++) {
            const int col = bx * BN + wn * 32 + nt * 8 + 2 * (lane & 3);
            const float b0 = bias[col], b1 = bias[col + 1];
            float2 o0, o1;
            o0.x = c[mt][nt][0] + b0; o0.y = c[mt][nt][1] + b1;
            o1.x = c[mt][nt][2] + b0; o1.y = c[mt][nt][3] + b1;
            if (relu) {
                o0.x = fmaxf(o0.x, 0.f); o0.y = fmaxf(o0.y, 0.f);
                o1.x = fmaxf(o1.x, 0.f); o1.y = fmaxf(o1.y, 0.f);
            }
            *(float2*)(C + (size_t)r0 * N + col)       = o0;
            *(float2*)(C + (size_t)(r0 + 8) * N + col) = o1;
        }
    }
}

// ---------------- bf16x3 tensor-core GEMM (m16n8k16, double-buffered) ----------------
__device__ __forceinline__ uint32_t pack_bf16(float lo, float hi) {
    uint32_t r;
    asm("cvt.rn.bf16x2.f32 %0, %1, %2;" : "=r"(r) : "f"(hi), "f"(lo));
    return r;
}

__device__ __forceinline__ void mma_bf16(float c[4], const uint32_t a[4], const uint32_t b[2]) {
    asm volatile(
        "mma.sync.aligned.m16n8k16.row.col.f32.bf16.bf16.f32 "
        "{%0,%1,%2,%3}, {%4,%5,%6,%7}, {%8,%9}, {%0,%1,%2,%3};"
        : "+f"(c[0]), "+f"(c[1]), "+f"(c[2]), "+f"(c[3])
        : "r"(a[0]), "r"(a[1]), "r"(a[2]), "r"(a[3]), "r"(b[0]), "r"(b[1]));
}

__device__ __forceinline__ void split_pair(float x, float y, uint32_t& wb, uint32_t& ws) {
    wb = pack_bf16(x, y);
    float bx = __uint_as_float(wb << 16);
    float by = __uint_as_float(wb & 0xFFFF0000u);
    ws = pack_bf16(x - bx, y - by);
}

#define BKb 16

__global__ __launch_bounds__(256)
void bgemm_kernel(const float* __restrict__ A, const float* __restrict__ Bm,
                  const float* __restrict__ bias, float* __restrict__ C,
                  int N, int K, int relu)
{
    // double-buffered: 2 x 24 KB = 48 KB static (stride 12 -> conflict-free frags)
    __shared__ uint32_t Ab_[2][BM][12];
    __shared__ uint32_t As_[2][BM][12];
    __shared__ uint32_t Bb_[2][BN][12];
    __shared__ uint32_t Bs_[2][BN][12];

    const int tid  = threadIdx.x;
    const int warp = tid >> 5;
    const int lane = tid & 31;
    const int wm   = warp >> 2;
    const int wn   = warp & 3;
    const int bx = blockIdx.x, by = blockIdx.y;

    const int arow = tid >> 1;
    const int acb  = (tid & 1) * 8;
    const int wc   = (tid & 1) * 4;
    const int kp   = tid & 7;
    const int bn0  = (tid >> 3) * 4;

    const float* Ag = A  + ((size_t)by * BM) * K;
    const float* Bg = Bm + (size_t)bx * BN;

    float c[4][4][4];
    #pragma unroll
    for (int mt = 0; mt < 4; mt++)
        #pragma unroll
        for (int nt = 0; nt < 4; nt++)
            #pragma unroll
            for (int e = 0; e < 4; e++) c[mt][nt][e] = 0.f;

    const int NT = K / BKb;
    float4 a_st[2], b_st[2];

    // prologue: tile 0 -> buf 0
    a_st[0] = *(const float4*)(Ag + (size_t)arow * K + acb);
    a_st[1] = *(const float4*)(Ag + (size_t)arow * K + acb + 4);
    b_st[0] = *(const float4*)(Bg + (size_t)(2 * kp)     * N + bn0);
    b_st[1] = *(const float4*)(Bg + (size_t)(2 * kp + 1) * N + bn0);
    {
        uint32_t wb, ws;
        split_pair(a_st[0].x, a_st[0].y, wb, ws);
        Ab_[0][arow][wc + 0] = wb; As_[0][arow][wc + 0] = ws;
        split_pair(a_st[0].z, a_st[0].w, wb, ws);
        Ab_[0][arow][wc + 1] = wb; As_[0][arow][wc + 1] = ws;
        split_pair(a_st[1].x, a_st[1].y, wb, ws);
        Ab_[0][arow][wc + 2] = wb; As_[0][arow][wc + 2] = ws;
        split_pair(a_st[1].z, a_st[1].w, wb, ws);
        Ab_[0][arow][wc + 3] = wb; As_[0][arow][wc + 3] = ws;
        const float* r0 = (const float*)&b_st[0];
        const float* r1 = (const float*)&b_st[1];
        #pragma unroll
        for (int j = 0; j < 4; j++) {
            split_pair(r0[j], r1[j], wb, ws);
            Bb_[0][bn0 + j][kp] = wb;
            Bs_[0][bn0 + j][kp] = ws;
        }
    }
    __syncthreads();

    for (int kt = 0; kt < NT; kt++) {
        const int cur = kt & 1;

        // prefetch next tile from global (latency hidden behind mma)
        if (kt + 1 < NT) {
            const int k0 = (kt + 1) * BKb;
            a_st[0] = *(const float4*)(Ag + (size_t)arow * K + k0 + acb);
            a_st[1] = *(const float4*)(Ag + (size_t)arow * K + k0 + acb + 4);
            b_st[0] = *(const float4*)(Bg + (size_t)(k0 + 2 * kp)     * N + bn0);
            b_st[1] = *(const float4*)(Bg + (size_t)(k0 + 2 * kp + 1) * N + bn0);
        }

        // mma on current buffer
        {
            const int kq = lane & 3;
            uint32_t ab[4][4], as[4][4], bb[4][2], bs[4][2];
            #pragma unroll
            for (int mt = 0; mt < 4; mt++) {
                const int r = wm * 64 + mt * 16 + (lane >> 2);
                ab[mt][0] = Ab_[cur][r    ][kq    ];
                ab[mt][1] = Ab_[cur][r + 8][kq    ];
                ab[mt][2] = Ab_[cur][r    ][kq + 4];
                ab[mt][3] = Ab_[cur][r + 8][kq + 4];
                as[mt][0] = As_[cur][r    ][kq    ];
                as[mt][1] = As_[cur][r + 8][kq    ];
                as[mt][2] = As_[cur][r    ][kq + 4];
                as[mt][3] = As_[cur][r + 8][kq + 4];
            }
            #pragma unroll
            for (int nt = 0; nt < 4; nt++) {
                const int n = wn * 32 + nt * 8 + (lane >> 2);
                bb[nt][0] = Bb_[cur][n][kq    ];
                bb[nt][1] = Bb_[cur][n][kq + 4];
                bs[nt][0] = Bs_[cur][n][kq    ];
                bs[nt][1] = Bs_[cur][n][kq + 4];
            }
            #pragma unroll
            for (int mt = 0; mt < 4; mt++)
                #pragma unroll
                for (int nt = 0; nt < 4; nt++) {
                    mma_bf16(c[mt][nt], as[mt], bb[nt]);
                    mma_bf16(c[mt][nt], ab[mt], bs[nt]);
                    mma_bf16(c[mt][nt], ab[mt], bb[nt]);
                }
        }

        // deposit next tile into the other buffer (overlaps mma; WAR guarded by the
        // single barrier below: readers of buf cur^1 finished before last sync)
        if (kt + 1 < NT) {
            const int nxt = cur ^ 1;
            uint32_t wb, ws;
            split_pair(a_st[0].x, a_st[0].y, wb, ws);
            Ab_[nxt][arow][wc + 0] = wb; As_[nxt][arow][wc + 0] = ws;
            split_pair(a_st[0].z, a_st[0].w, wb, ws);
            Ab_[nxt][arow][wc + 1] = wb; As_[nxt][arow][wc + 1] = ws;
            split_pair(a_st[1].x, a_st[1].y, wb, ws);
            Ab_[nxt][arow][wc + 2] = wb; As_[nxt][arow][wc + 2] = ws;
            split_pair(a_st[1].z, a_st[1].w, wb, ws);
            Ab_[nxt][arow][wc + 3] = wb; As_[nxt][arow][wc + 3] = ws;
            const float* r0 = (const float*)&b_st[0];
            const float* r1 = (const float*)&b_st[1];
            #pragma unroll
            for (int j = 0; j < 4; j++) {
                split_pair(r0[j], r1[j], wb, ws);
                Bb_[nxt][bn0 + j][kp] = wb;
                Bs_[nxt][bn0 + j][kp] = ws;
            }
            __syncthreads();
        }
    }

    #pragma unroll
    for (int mt = 0; mt < 4; mt++) {
        const int r0 = by * BM + wm * 64 + mt * 16 + (lane >> 2);
        #pragma unroll
        for (int nt = 0; nt < 4; nt++) {
            const int col = bx * BN + wn * 32 + nt * 8 + 2 * (lane & 3);
            const float b0 = bias[col], b1 = bias[col + 1];
            float2 o0, o1;
            o0.x = c[mt][nt][0] + b0; o0.y = c[mt][nt][1] + b1;
            o1.x = c[mt][nt][2] + b0; o1.y = c[mt][nt][3] + b1;
            if (relu) {
                o0.x = fmaxf(o0.x, 0.f); o0.y = fmaxf(o0.y, 0.f);
                o1.x = fmaxf(o1.x, 0.f); o1.y = fmaxf(o1.y, 0.f);
            }
            *(float2*)(C + (size_t)r0 * N + col)       = o0;
            *(float2*)(C + (size_t)(r0 + 8) * N + col) = o1;
        }
    }
}

// ---------------- warp-level attention, 2 queries/warp, 128-key float4 tiles ----------------
#define FULLM 0xFFFFFFFFu
#define QPB 16   // queries per block (8 warps x 2)

__device__ __forceinline__ float warp_max(float v) {
    #pragma unroll
    for (int o = 16; o > 0; o >>= 1) v = fmaxf(v, __shfl_xor_sync(FULLM, v, o));
    return v;
}
__device__ __forceinline__ float warp_sum(float v) {
    #pragma unroll
    for (int o = 16; o > 0; o >>= 1) v += __shfl_xor_sync(FULLM, v, o);
    return v;
}
__device__ __forceinline__ int warp_min_i(int v) {
    #pragma unroll
    for (int o = 16; o > 0; o >>= 1) v = min(v, __shfl_xor_sync(FULLM, v, o));
    return v;
}

__global__ __launch_bounds__(256)
void attn_kernel(const float* __restrict__ Q, const float* __restrict__ V,
                 float* __restrict__ O)
{
    const int qt   = blockIdx.x;
    const int h    = blockIdx.y;
    const int b    = blockIdx.z;
    const int tid  = threadIdx.x;
    const int warp = tid >> 5;
    const int lane = tid & 31;
    const int i0   = qt * QPB + warp * 2;      // this warp's queries: i0, i0+1

    // KT4[d][kl] = (K[j0+kl][d], K[j0+kl+32][d], K[j0+kl+64][d], K[j0+kl+96][d])
    __shared__ float4 KT4[64][32];             // 32 KB; LDS.128 conflict-free
    __shared__ float2 qs2[QPB][32];            // (q[2d], q[2d+1]) broadcast

    const size_t base = ((size_t)b * Sc) * Dc + (size_t)h * DHc;

    qs2[warp * 2    ][lane] = *(const float2*)(Q + base + (size_t)i0 * Dc + 2 * lane);
    qs2[warp * 2 + 1][lane] = *(const float2*)(Q + base + (size_t)(i0 + 1) * Dc + 2 * lane);

    // per-query scores in registers: slot t holds j = 32*t + lane
    float p0[16], p1[16];
    #pragma unroll
    for (int t = 0; t < 16; t++) { p0[t] = -FLT_MAX; p1[t] = -FLT_MAX; }

    const int nk = qt * QPB + QPB - 1;         // max key index needed (exclusive-ish)

    // staging map: thread -> (key, 32 d's)
    const int skey = tid >> 1;                 // 0..127
    const int sd0  = (tid & 1) * 32;           // 0 or 32
    const int kcol = (skey & 31) * 4 + (skey >> 5);   // flat float column in KT4 row
    float* KTf = (float*)KT4;                  // flat: idx = d*128 + kcol

    #pragma unroll
    for (int tt = 0; tt < 4; tt++) {
        if (tt * 128 < nk) {
            const int j0 = tt * 128;
            __syncthreads();                   // prev readers done (qs2 ready on tt=0)
            {
                const float* src = Q + base + (size_t)(j0 + skey) * Dc + sd0;
                #pragma unroll
                for (int f = 0; f < 8; f++) {
                    float4 v = *(const float4*)(src + 4 * f);
                    const int d = sd0 + 4 * f;
                    KTf[(d + 0) * 128 + kcol] = v.x;
                    KTf[(d + 1) * 128 + kcol] = v.y;
                    KTf[(d + 2) * 128 + kcol] = v.z;
                    KTf[(d + 3) * 128 + kcol] = v.w;
                }
            }
            __syncthreads();

            float a0[4] = {0.f, 0.f, 0.f, 0.f};
            float a1[4] = {0.f, 0.f, 0.f, 0.f};
            #pragma unroll
            for (int dd = 0; dd < 32; dd++) {
                const float4 ka = KT4[2 * dd    ][lane];
                const float4 kb = KT4[2 * dd + 1][lane];
                const float2 q0 = qs2[warp * 2    ][dd];
                const float2 q1 = qs2[warp * 2 + 1][dd];
                a0[0] = fmaf(q0.x, ka.x, a0[0]); a0[0] = fmaf(q0.y, kb.x, a0[0]);
                a0[1] = fmaf(q0.x, ka.y, a0[1]); a0[1] = fmaf(q0.y, kb.y, a0[1]);
                a0[2] = fmaf(q0.x, ka.z, a0[2]); a0[2] = fmaf(q0.y, kb.z, a0[2]);
                a0[3] = fmaf(q0.x, ka.w, a0[3]); a0[3] = fmaf(q0.y, kb.w, a0[3]);
                a1[0] = fmaf(q1.x, ka.x, a1[0]); a1[0] = fmaf(q1.y, kb.x, a1[0]);
                a1[1] = fmaf(q1.x, ka.y, a1[1]); a1[1] = fmaf(q1.y, kb.y, a1[1]);
                a1[2] = fmaf(q1.x, ka.z, a1[2]); a1[2] = fmaf(q1.y, kb.z, a1[2]);
                a1[3] = fmaf(q1.x, ka.w, a1[3]); a1[3] = fmaf(q1.y, kb.w, a1[3]);
            }
            #pragma unroll
            for (int cc = 0; cc < 4; cc++) {
                const int j = j0 + 32 * cc + lane;
                if (j < i0)     p0[4 * tt + cc] = a0[cc] * 0.125f;
                if (j < i0 + 1) p1[4 * tt + cc] = a1[cc] * 0.125f;
            }
        }
    }

    // ---- per-query epilogue (softmax, top-k, sparse PV); no block syncs below ----
    #pragma unroll
    for (int qq = 0; qq < 2; qq++) {
        const int i = i0 + qq;
        float p[16];
        #pragma unroll
        for (int t = 0; t < 16; t++) p[t] = qq ? p1[t] : p0[t];

        float* out = O + base + (size_t)i * Dc;
        if (i == 0) {                           // zero_pad row
            out[lane] = 0.f; out[lane + 32] = 0.f;
            continue;
        }

        float lm = -FLT_MAX;
        #pragma unroll
        for (int t = 0; t < 16; t++) lm = fmaxf(lm, p[t]);
        const float m = warp_max(lm);

        float ls = 0.f;
        #pragma unroll
        for (int t = 0; t < 16; t++) { p[t] = expf(p[t] - m); ls += p[t]; }
        const float invZ = 1.f / warp_sum(ls);
        #pragma unroll
        for (int t = 0; t < 16; t++) p[t] *= invZ;

        float w[16];
        float scale = 1.f;
        if (i > KIDX) {
            #pragma unroll
            for (int t = 0; t < 16; t++) w[t] = p[t];
            float pmax = 0.f, thresh = 0.f;
            #pragma unroll 1
            for (int pass = 0; pass < 5; pass++) {
                float lmx = -1.f;
                #pragma unroll
                for (int t = 0; t < 16; t++) lmx = fmaxf(lmx, w[t]);
                const float mt = warp_max(lmx);
                if (pass == 0) pmax = mt;
                thresh = mt;
                if (pass < 4) {
                    int cand = INT_MAX;
                    #pragma unroll
                    for (int t = 0; t < 16; t++)
                        if (w[t] == mt) cand = min(cand, t * 32 + lane);
                    const int jmin = warp_min_i(cand);
                    #pragma unroll
                    for (int t = 0; t < 16; t++)
                        if (jmin != INT_MAX && t == (jmin >> 5) && lane == (jmin & 31))
                            w[t] = -1.f;
                }
            }
            float lsum = 0.f;
            #pragma unroll
            for (int t = 0; t < 16; t++) {
                w[t] = (p[t] >= thresh) ? expf(p[t] - pmax) : 0.f;
                lsum += w[t];
            }
            scale = 1.f / warp_sum(lsum);
        } else {
            #pragma unroll
            for (int t = 0; t < 16; t++) w[t] = p[t];
        }

        float o0 = 0.f, o1 = 0.f;
        #pragma unroll
        for (int t = 0; t < 16; t++) {
            unsigned mask = __ballot_sync(FULLM, w[t] > 0.f);
            while (mask) {
                const int bit = __ffs(mask) - 1;
                mask &= mask - 1;
                const float wj = __shfl_sync(FULLM, w[t], bit);
                const float* vr = V + base + (size_t)(t * 32 + bit) * Dc;
                o0 = fmaf(wj, vr[lane],      o0);
                o1 = fmaf(wj, vr[lane + 32], o1);
            }
        }
        out[lane]      = o0 * scale;
        out[lane + 32] = o1 * scale;
    }
}

// ---------------- fused residual + LayerNorm: O = LN(X + R) * g + b ----------------
__global__ void ln_kernel(const float* __restrict__ X, const float* __restrict__ R,
                          const float* __restrict__ g, const float* __restrict__ bt,
                          float* __restrict__ O)
{
    const int row = blockIdx.x;
    const int tid = threadIdx.x;   // 128
    __shared__ float s_red[128];

    const float* xr = X + (size_t)row * Dc;
    const float* rr = R + (size_t)row * Dc;

    float v[4];
    float sum = 0.f, sq = 0.f;
    #pragma unroll
    for (int k = 0; k < 4; k++) {
        float t = xr[tid + k * 128] + rr[tid + k * 128];
        v[k] = t; sum += t; sq += t * t;
    }
    s_red[tid] = sum; __syncthreads();
    for (int s = 64; s > 0; s >>= 1) { if (tid < s) s_red[tid] += s_red[tid + s]; __syncthreads(); }
    float mean = s_red[0] * (1.f / Dc); __syncthreads();
    s_red[tid] = sq; __syncthreads();
    for (int s = 64; s > 0; s >>= 1) { if (tid < s) s_red[tid] += s_red[tid + s]; __syncthreads(); }
    float var = s_red[0] * (1.f / Dc) - mean * mean;
    float rs = rsqrtf(var + 1e-5f);

    #pragma unroll
    for (int k = 0; k < 4; k++) {
        int c = tid + k * 128;
        O[(size_t)row * Dc + c] = (v[k] - mean) * rs * g[c] + bt[c];
    }
}

// ---------------- launch ----------------
extern "C" void kernel_launch(void* const* d_in, const int* in_sizes, int n_in,
                              void* d_out, int out_size)
{
    const float* qe   = (const float*)d_in[0];
    const float* ie   = (const float*)d_in[1];
    const float* pe   = (const float*)d_in[2];
    const float* Wk   = (const float*)d_in[3];
    const float* bk   = (const float*)d_in[4];
    const float* Wv   = (const float*)d_in[5];
    const float* bv   = (const float*)d_in[6];
    const float* Wo   = (const float*)d_in[7];
    const float* bo   = (const float*)d_in[8];
    const float* ln1g = (const float*)d_in[9];
    const float* ln1b = (const float*)d_in[10];
    const float* W1   = (const float*)d_in[11];
    const float* b1   = (const float*)d_in[12];
    const float* W2   = (const float*)d_in[13];
    const float* b2   = (const float*)d_in[14];
    const float* ln2g = (const float*)d_in[15];
    const float* ln2b = (const float*)d_in[16];
    float* out = (float*)d_out;

    float *x, *y, *q, *v, *attn, *h1, *t2;
    cudaGetSymbolAddress((void**)&x,    g_x);
    cudaGetSymbolAddress((void**)&y,    g_y);
    cudaGetSymbolAddress((void**)&q,    g_q);
    cudaGetSymbolAddress((void**)&v,    g_v);
    cudaGetSymbolAddress((void**)&attn, g_attn);
    cudaGetSymbolAddress((void**)&h1,   g_h1);
    cudaGetSymbolAddress((void**)&t2,   g_t2);

    addpos_kernel<<<((size_t)BSc * Dc + 255) / 256, 256>>>(qe, ie, pe, x, y);

    for (int l = 0; l < Lc; l++) {
        const float* Wkl = Wk + (size_t)l * Dc * Dc;
        const float* Wvl = Wv + (size_t)l * Dc * Dc;
        const float* Wol = Wo + (size_t)l * Dc * Dc;
        const float* W1l = W1 + (size_t)l * Dc * DFFc;
        const float* W2l = W2 + (size_t)l * DFFc * Dc;

        // Wk stays tf32x3: feeds the precision-sensitive top-k score path
        tgemm_kernel<<<dim3(Dc / BN, BSc / BM), 256>>>(x, Wkl, bk + l * Dc, q, Dc, Dc, 0);
        // Wv, Wo, FFN: linear paths -> bf16x3
        bgemm_kernel<<<dim3(Dc / BN, BSc / BM), 256>>>(y, Wvl, bv + l * Dc, v, Dc, Dc, 0);
        attn_kernel<<<dim3(Sc / QPB, Hc, Bc), 256>>>(q, v, attn);
        bgemm_kernel<<<dim3(Dc / BN, BSc / BM), 256>>>(attn, Wol, bo + l * Dc, t2, Dc, Dc, 0);
        ln_kernel<<<BSc, 128>>>(x, t2, ln1g + l * Dc, ln1b + l * Dc, x);
        bgemm_kernel<<<dim3(DFFc / BN, BSc / BM), 256>>>(x, W1l, b1 + l * DFFc, h1, DFFc, Dc, 1);
        bgemm_kernel<<<dim3(Dc / BN, BSc / BM), 256>>>(h1, W2l, b2 + l * Dc, t2, Dc, DFFc, 0);
        float* dst = (l == Lc - 1) ? out : x;
        ln_kernel<<<BSc, 128>>>(x, t2, ln2g + l * Dc, ln2b + l * Dc, dst);
    }
}

// round 10
// speedup vs baseline: 2.9465x; 1.0654x over previous
#include <cuda_runtime.h>
#include <math.h>
#include <float.h>
#include <limits.h>
#include <stdint.h>

#define Lc   2
#define Bc   32
#define Sc   512
#define Dc   512
#define Hc   8
#define DFFc 2048
#define DHc  64
#define KIDX 5
#define BSc  (Bc*Sc)   // 16384

// ---------------- scratch (static device globals; no allocation) ----------------
__device__ float g_x[(size_t)BSc*Dc];
__device__ float g_y[(size_t)BSc*Dc];
__device__ float g_q[(size_t)BSc*Dc];      // q == k (kq_same)
__device__ float g_v[(size_t)BSc*Dc];
__device__ float g_attn[(size_t)BSc*Dc];
__device__ float g_h1[(size_t)BSc*DFFc];
__device__ float g_t2[(size_t)BSc*Dc];

// ---------------- elementwise: x = qemb + pos, y = iemb + pos ----------------
__global__ void addpos_kernel(const float* __restrict__ qe, const float* __restrict__ ie,
                              const float* __restrict__ pe,
                              float* __restrict__ x, float* __restrict__ y)
{
    size_t idx = (size_t)blockIdx.x * blockDim.x + threadIdx.x;
    if (idx >= (size_t)BSc * Dc) return;
    size_t p = idx % ((size_t)Sc * Dc);
    float pv = pe[p];
    x[idx] = qe[idx] + pv;
    y[idx] = ie[idx] + pv;
}

// ---------------- tf32x3 tensor-core GEMM (fp32-accurate; score path only) ----------------
__device__ __forceinline__ float f2tf32f(float x) {
    uint32_t r;
    asm("cvt.rna.tf32.f32 %0, %1;" : "=r"(r) : "f"(x));
    return __uint_as_float(r);
}

__device__ __forceinline__ void mma_tf32(float c[4], const uint32_t a[4], const uint32_t b[2]) {
    asm volatile(
        "mma.sync.aligned.m16n8k8.row.col.f32.tf32.tf32.f32 "
        "{%0,%1,%2,%3}, {%4,%5,%6,%7}, {%8,%9}, {%0,%1,%2,%3};"
        : "+f"(c[0]), "+f"(c[1]), "+f"(c[2]), "+f"(c[3])
        : "r"(a[0]), "r"(a[1]), "r"(a[2]), "r"(a[3]), "r"(b[0]), "r"(b[1]));
}

#define BM 128
#define BN 128
#define BKt 16

__global__ __launch_bounds__(256)
void tgemm_kernel(const float* __restrict__ A, const float* __restrict__ Bm,
                  const float* __restrict__ bias, float* __restrict__ C,
                  int N, int K, int relu)
{
    __shared__ float As_b[BM][20];
    __shared__ float As_s[BM][20];
    __shared__ float Bs_b[BKt][136];
    __shared__ float Bs_s[BKt][136];

    const int tid  = threadIdx.x;
    const int warp = tid >> 5;
    const int lane = tid & 31;
    const int wm   = warp >> 2;
    const int wn   = warp & 3;
    const int bx = blockIdx.x, by = blockIdx.y;

    const int ar0 = tid >> 2;
    const int ac  = (tid & 3) * 4;
    const int br0 = tid >> 5;
    const int bc  = (tid & 31) * 4;

    const float* Ag = A  + ((size_t)by * BM) * K;
    const float* Bg = Bm + (size_t)bx * BN;

    float c[4][4][4];
    #pragma unroll
    for (int mt = 0; mt < 4; mt++)
        #pragma unroll
        for (int nt = 0; nt < 4; nt++)
            #pragma unroll
            for (int e = 0; e < 4; e++) c[mt][nt][e] = 0.f;

    const int NT = K / BKt;
    float4 a_st[2], b_st[2];

    a_st[0] = *(const float4*)(Ag + (size_t)ar0 * K + ac);
    a_st[1] = *(const float4*)(Ag + (size_t)(ar0 + 64) * K + ac);
    b_st[0] = *(const float4*)(Bg + (size_t)br0 * N + bc);
    b_st[1] = *(const float4*)(Bg + (size_t)(br0 + 8) * N + bc);

    for (int kt = 0; kt < NT; kt++) {
        #pragma unroll
        for (int e = 0; e < 4; e++) {
            float v0 = ((const float*)&a_st[0])[e];
            float v1 = ((const float*)&a_st[1])[e];
            float b0 = f2tf32f(v0), b1 = f2tf32f(v1);
            As_b[ar0][ac + e]      = b0;
            As_s[ar0][ac + e]      = f2tf32f(v0 - b0);
            As_b[ar0 + 64][ac + e] = b1;
            As_s[ar0 + 64][ac + e] = f2tf32f(v1 - b1);

            float w0 = ((const float*)&b_st[0])[e];
            float w1 = ((const float*)&b_st[1])[e];
            float c0 = f2tf32f(w0), c1 = f2tf32f(w1);
            Bs_b[br0][bc + e]     = c0;
            Bs_s[br0][bc + e]     = f2tf32f(w0 - c0);
            Bs_b[br0 + 8][bc + e] = c1;
            Bs_s[br0 + 8][bc + e] = f2tf32f(w1 - c1);
        }
        __syncthreads();

        if (kt + 1 < NT) {
            const int k0 = (kt + 1) * BKt;
            a_st[0] = *(const float4*)(Ag + (size_t)ar0 * K + k0 + ac);
            a_st[1] = *(const float4*)(Ag + (size_t)(ar0 + 64) * K + k0 + ac);
            b_st[0] = *(const float4*)(Bg + (size_t)(k0 + br0) * N + bc);
            b_st[1] = *(const float4*)(Bg + (size_t)(k0 + br0 + 8) * N + bc);
        }

        #pragma unroll
        for (int ks = 0; ks < 2; ks++) {
            const int kk = ks * 8;
            const int kq = kk + (lane & 3);
            uint32_t ab[4][4], as[4][4], bb[4][2], bs[4][2];
            #pragma unroll
            for (int mt = 0; mt < 4; mt++) {
                const int r = wm * 64 + mt * 16 + (lane >> 2);
                ab[mt][0] = __float_as_uint(As_b[r    ][kq    ]);
                ab[mt][1] = __float_as_uint(As_b[r + 8][kq    ]);
                ab[mt][2] = __float_as_uint(As_b[r    ][kq + 4]);
                ab[mt][3] = __float_as_uint(As_b[r + 8][kq + 4]);
                as[mt][0] = __float_as_uint(As_s[r    ][kq    ]);
                as[mt][1] = __float_as_uint(As_s[r + 8][kq    ]);
                as[mt][2] = __float_as_uint(As_s[r    ][kq + 4]);
                as[mt][3] = __float_as_uint(As_s[r + 8][kq + 4]);
            }
            #pragma unroll
            for (int nt = 0; nt < 4; nt++) {
                const int cc = wn * 32 + nt * 8 + (lane >> 2);
                bb[nt][0] = __float_as_uint(Bs_b[kq    ][cc]);
                bb[nt][1] = __float_as_uint(Bs_b[kq + 4][cc]);
                bs[nt][0] = __float_as_uint(Bs_s[kq    ][cc]);
                bs[nt][1] = __float_as_uint(Bs_s[kq + 4][cc]);
            }
            #pragma unroll
            for (int mt = 0; mt < 4; mt++)
                #pragma unroll
                for (int nt = 0; nt < 4; nt++) {
                    mma_tf32(c[mt][nt], as[mt], bb[nt]);
                    mma_tf32(c[mt][nt], ab[mt], bs[nt]);
                    mma_tf32(c[mt][nt], ab[mt], bb[nt]);
                }
        }
        __syncthreads();
    }

    #pragma unroll
    for (int mt = 0; mt < 4; mt++) {
        const int r0 = by * BM + wm * 64 + mt * 16 + (lane >> 2);
        #pragma unroll
        for (int nt = 0; nt < 4; nt++) {
            const int col = bx * BN + wn * 32 + nt * 8 + 2 * (lane & 3);
            const float b0 = bias[col], b1 = bias[col + 1];
            float2 o0, o1;
            o0.x = c[mt][nt][0] + b0; o0.y = c[mt][nt][1] + b1;
            o1.x = c[mt][nt][2] + b0; o1.y = c[mt][nt][3] + b1;
            if (relu) {
                o0.x = fmaxf(o0.x, 0.f); o0.y = fmaxf(o0.y, 0.f);
                o1.x = fmaxf(o1.x, 0.f); o1.y = fmaxf(o1.y, 0.f);
            }
            *(float2*)(C + (size_t)r0 * N + col)       = o0;
            *(float2*)(C + (size_t)(r0 + 8) * N + col) = o1;
        }
    }
}

// ---------------- bf16x3 tensor-core GEMM (m16n8k16, double-buffered) ----------------
__device__ __forceinline__ uint32_t pack_bf16(float lo, float hi) {
    uint32_t r;
    asm("cvt.rn.bf16x2.f32 %0, %1, %2;" : "=r"(r) : "f"(hi), "f"(lo));
    return r;
}

__device__ __forceinline__ void mma_bf16(float c[4], const uint32_t a[4], const uint32_t b[2]) {
    asm volatile(
        "mma.sync.aligned.m16n8k16.row.col.f32.bf16.bf16.f32 "
        "{%0,%1,%2,%3}, {%4,%5,%6,%7}, {%8,%9}, {%0,%1,%2,%3};"
        : "+f"(c[0]), "+f"(c[1]), "+f"(c[2]), "+f"(c[3])
        : "r"(a[0]), "r"(a[1]), "r"(a[2]), "r"(a[3]), "r"(b[0]), "r"(b[1]));
}

__device__ __forceinline__ void split_pair(float x, float y, uint32_t& wb, uint32_t& ws) {
    wb = pack_bf16(x, y);
    float bx = __uint_as_float(wb << 16);
    float by = __uint_as_float(wb & 0xFFFF0000u);
    ws = pack_bf16(x - bx, y - by);
}

#define BKb 16

__global__ __launch_bounds__(256)
void bgemm_kernel(const float* __restrict__ A, const float* __restrict__ Bm,
                  const float* __restrict__ bias, float* __restrict__ C,
                  int N, int K, int relu)
{
    __shared__ uint32_t Ab_[2][BM][12];
    __shared__ uint32_t As_[2][BM][12];
    __shared__ uint32_t Bb_[2][BN][12];
    __shared__ uint32_t Bs_[2][BN][12];

    const int tid  = threadIdx.x;
    const int warp = tid >> 5;
    const int lane = tid & 31;
    const int wm   = warp >> 2;
    const int wn   = warp & 3;
    const int bx = blockIdx.x, by = blockIdx.y;

    const int arow = tid >> 1;
    const int acb  = (tid & 1) * 8;
    const int wc   = (tid & 1) * 4;
    const int kp   = tid & 7;
    const int bn0  = (tid >> 3) * 4;

    const float* Ag = A  + ((size_t)by * BM) * K;
    const float* Bg = Bm + (size_t)bx * BN;

    float c[4][4][4];
    #pragma unroll
    for (int mt = 0; mt < 4; mt++)
        #pragma unroll
        for (int nt = 0; nt < 4; nt++)
            #pragma unroll
            for (int e = 0; e < 4; e++) c[mt][nt][e] = 0.f;

    const int NT = K / BKb;
    float4 a_st[2], b_st[2];

    a_st[0] = *(const float4*)(Ag + (size_t)arow * K + acb);
    a_st[1] = *(const float4*)(Ag + (size_t)arow * K + acb + 4);
    b_st[0] = *(const float4*)(Bg + (size_t)(2 * kp)     * N + bn0);
    b_st[1] = *(const float4*)(Bg + (size_t)(2 * kp + 1) * N + bn0);
    {
        uint32_t wb, ws;
        split_pair(a_st[0].x, a_st[0].y, wb, ws);
        Ab_[0][arow][wc + 0] = wb; As_[0][arow][wc + 0] = ws;
        split_pair(a_st[0].z, a_st[0].w, wb, ws);
        Ab_[0][arow][wc + 1] = wb; As_[0][arow][wc + 1] = ws;
        split_pair(a_st[1].x, a_st[1].y, wb, ws);
        Ab_[0][arow][wc + 2] = wb; As_[0][arow][wc + 2] = ws;
        split_pair(a_st[1].z, a_st[1].w, wb, ws);
        Ab_[0][arow][wc + 3] = wb; As_[0][arow][wc + 3] = ws;
        const float* r0 = (const float*)&b_st[0];
        const float* r1 = (const float*)&b_st[1];
        #pragma unroll
        for (int j = 0; j < 4; j++) {
            split_pair(r0[j], r1[j], wb, ws);
            Bb_[0][bn0 + j][kp] = wb;
            Bs_[0][bn0 + j][kp] = ws;
        }
    }
    __syncthreads();

    for (int kt = 0; kt < NT; kt++) {
        const int cur = kt & 1;

        if (kt + 1 < NT) {
            const int k0 = (kt + 1) * BKb;
            a_st[0] = *(const float4*)(Ag + (size_t)arow * K + k0 + acb);
            a_st[1] = *(const float4*)(Ag + (size_t)arow * K + k0 + acb + 4);
            b_st[0] = *(const float4*)(Bg + (size_t)(k0 + 2 * kp)     * N + bn0);
            b_st[1] = *(const float4*)(Bg + (size_t)(k0 + 2 * kp + 1) * N + bn0);
        }

        {
            const int kq = lane & 3;
            uint32_t ab[4][4], as[4][4], bb[4][2], bs[4][2];
            #pragma unroll
            for (int mt = 0; mt < 4; mt++) {
                const int r = wm * 64 + mt * 16 + (lane >> 2);
                ab[mt][0] = Ab_[cur][r    ][kq    ];
                ab[mt][1] = Ab_[cur][r + 8][kq    ];
                ab[mt][2] = Ab_[cur][r    ][kq + 4];
                ab[mt][3] = Ab_[cur][r + 8][kq + 4];
                as[mt][0] = As_[cur][r    ][kq    ];
                as[mt][1] = As_[cur][r + 8][kq    ];
                as[mt][2] = As_[cur][r    ][kq + 4];
                as[mt][3] = As_[cur][r + 8][kq + 4];
            }
            #pragma unroll
            for (int nt = 0; nt < 4; nt++) {
                const int n = wn * 32 + nt * 8 + (lane >> 2);
                bb[nt][0] = Bb_[cur][n][kq    ];
                bb[nt][1] = Bb_[cur][n][kq + 4];
                bs[nt][0] = Bs_[cur][n][kq    ];
                bs[nt][1] = Bs_[cur][n][kq + 4];
            }
            #pragma unroll
            for (int mt = 0; mt < 4; mt++)
                #pragma unroll
                for (int nt = 0; nt < 4; nt++) {
                    mma_bf16(c[mt][nt], as[mt], bb[nt]);
                    mma_bf16(c[mt][nt], ab[mt], bs[nt]);
                    mma_bf16(c[mt][nt], ab[mt], bb[nt]);
                }
        }

        if (kt + 1 < NT) {
            const int nxt = cur ^ 1;
            uint32_t wb, ws;
            split_pair(a_st[0].x, a_st[0].y, wb, ws);
            Ab_[nxt][arow][wc + 0] = wb; As_[nxt][arow][wc + 0] = ws;
            split_pair(a_st[0].z, a_st[0].w, wb, ws);
            Ab_[nxt][arow][wc + 1] = wb; As_[nxt][arow][wc + 1] = ws;
            split_pair(a_st[1].x, a_st[1].y, wb, ws);
            Ab_[nxt][arow][wc + 2] = wb; As_[nxt][arow][wc + 2] = ws;
            split_pair(a_st[1].z, a_st[1].w, wb, ws);
            Ab_[nxt][arow][wc + 3] = wb; As_[nxt][arow][wc + 3] = ws;
            const float* r0 = (const float*)&b_st[0];
            const float* r1 = (const float*)&b_st[1];
            #pragma unroll
            for (int j = 0; j < 4; j++) {
                split_pair(r0[j], r1[j], wb, ws);
                Bb_[nxt][bn0 + j][kp] = wb;
                Bs_[nxt][bn0 + j][kp] = ws;
            }
            __syncthreads();
        }
    }

    #pragma unroll
    for (int mt = 0; mt < 4; mt++) {
        const int r0 = by * BM + wm * 64 + mt * 16 + (lane >> 2);
        #pragma unroll
        for (int nt = 0; nt < 4; nt++) {
            const int col = bx * BN + wn * 32 + nt * 8 + 2 * (lane & 3);
            const float b0 = bias[col], b1 = bias[col + 1];
            float2 o0, o1;
            o0.x = c[mt][nt][0] + b0; o0.y = c[mt][nt][1] + b1;
            o1.x = c[mt][nt][2] + b0; o1.y = c[mt][nt][3] + b1;
            if (relu) {
                o0.x = fmaxf(o0.x, 0.f); o0.y = fmaxf(o0.y, 0.f);
                o1.x = fmaxf(o1.x, 0.f); o1.y = fmaxf(o1.y, 0.f);
            }
            *(float2*)(C + (size_t)r0 * N + col)       = o0;
            *(float2*)(C + (size_t)(r0 + 8) * N + col) = o1;
        }
    }
}

// ---------------- warp-level attention, 2 queries/warp, fast top-k ----------------
#define FULLM 0xFFFFFFFFu
#define QPB 16   // queries per block (8 warps x 2)

__device__ __forceinline__ float warp_max(float v) {
    #pragma unroll
    for (int o = 16; o > 0; o >>= 1) v = fmaxf(v, __shfl_xor_sync(FULLM, v, o));
    return v;
}
__device__ __forceinline__ float warp_sum(float v) {
    #pragma unroll
    for (int o = 16; o > 0; o >>= 1) v += __shfl_xor_sync(FULLM, v, o);
    return v;
}

__global__ __launch_bounds__(256)
void attn_kernel(const float* __restrict__ Q, const float* __restrict__ V,
                 float* __restrict__ O)
{
    const int qt   = blockIdx.x;
    const int h    = blockIdx.y;
    const int b    = blockIdx.z;
    const int tid  = threadIdx.x;
    const int warp = tid >> 5;
    const int lane = tid & 31;
    const int i0   = qt * QPB + warp * 2;      // this warp's queries: i0, i0+1

    // KT2[d][kl] = (K[j0+kl][d], K[j0+kl+32][d]); pad 33 -> conflict-free LDS.64
    __shared__ float2 KT2[64][33];
    __shared__ float2 qs2[QPB][32];            // (q[2d], q[2d+1])

    const size_t base = ((size_t)b * Sc) * Dc + (size_t)h * DHc;

    qs2[warp * 2    ][lane] = *(const float2*)(Q + base + (size_t)i0 * Dc + 2 * lane);
    qs2[warp * 2 + 1][lane] = *(const float2*)(Q + base + (size_t)(i0 + 1) * Dc + 2 * lane);

    // per-query scores in registers: slot t holds j = 32*t + lane
    float p0[16], p1[16];
    #pragma unroll
    for (int t = 0; t < 16; t++) { p0[t] = -FLT_MAX; p1[t] = -FLT_MAX; }

    const int nk = qt * QPB + QPB - 1;         // max query index in block

    // staging map: key = tid & 63, dgroup = tid >> 6 (16 d's each)
    const int skey = tid & 63;
    const int sd0  = (tid >> 6) * 16;
    const int skl  = skey & 31;
    const int shalf = skey >> 5;
    float* KTf = (float*)&KT2[0][0];           // flat view: idx = (d*33 + kl)*2 + half

    #pragma unroll
    for (int tt = 0; tt < 8; tt++) {
        if (tt * 64 < nk) {
            const int j0 = tt * 64;
            __syncthreads();                   // prev readers done (and qs2 ready on tt=0)
            {
                const float* src = Q + base + (size_t)(j0 + skey) * Dc + sd0;
                float4 f0 = *(const float4*)(src);
                float4 f1 = *(const float4*)(src + 4);
                float4 f2 = *(const float4*)(src + 8);
                float4 f3 = *(const float4*)(src + 12);
                const int bi = skl * 2 + shalf;
                KTf[(sd0 + 0) * 66 + bi] = f0.x;  KTf[(sd0 + 1) * 66 + bi] = f0.y;
                KTf[(sd0 + 2) * 66 + bi] = f0.z;  KTf[(sd0 + 3) * 66 + bi] = f0.w;
                KTf[(sd0 + 4) * 66 + bi] = f1.x;  KTf[(sd0 + 5) * 66 + bi] = f1.y;
                KTf[(sd0 + 6) * 66 + bi] = f1.z;  KTf[(sd0 + 7) * 66 + bi] = f1.w;
                KTf[(sd0 + 8) * 66 + bi] = f2.x;  KTf[(sd0 + 9) * 66 + bi] = f2.y;
                KTf[(sd0 +10) * 66 + bi] = f2.z;  KTf[(sd0 +11) * 66 + bi] = f2.w;
                KTf[(sd0 +12) * 66 + bi] = f3.x;  KTf[(sd0 +13) * 66 + bi] = f3.y;
                KTf[(sd0 +14) * 66 + bi] = f3.z;  KTf[(sd0 +15) * 66 + bi] = f3.w;
            }
            __syncthreads();

            float a00 = 0.f, a01 = 0.f, a10 = 0.f, a11 = 0.f; // [query][keyhalf]
            #pragma unroll
            for (int dd = 0; dd < 32; dd++) {
                const float2 ka = KT2[2 * dd    ][lane];
                const float2 kb = KT2[2 * dd + 1][lane];
                const float2 q0 = qs2[warp * 2    ][dd];
                const float2 q1 = qs2[warp * 2 + 1][dd];
                a00 = fmaf(q0.x, ka.x, a00); a00 = fmaf(q0.y, kb.x, a00);
                a01 = fmaf(q0.x, ka.y, a01); a01 = fmaf(q0.y, kb.y, a01);
                a10 = fmaf(q1.x, ka.x, a10); a10 = fmaf(q1.y, kb.x, a10);
                a11 = fmaf(q1.x, ka.y, a11); a11 = fmaf(q1.y, kb.y, a11);
            }
            const int j1 = j0 + lane, j2 = j0 + lane + 32;
            if (j1 < i0)     p0[2 * tt]     = a00 * 0.125f;
            if (j2 < i0)     p0[2 * tt + 1] = a01 * 0.125f;
            if (j1 < i0 + 1) p1[2 * tt]     = a10 * 0.125f;
            if (j2 < i0 + 1) p1[2 * tt + 1] = a11 * 0.125f;
        }
    }

    // ---- per-query epilogue (softmax, fast top-k, sparse PV); no block syncs below ----
    #pragma unroll
    for (int qq = 0; qq < 2; qq++) {
        const int i = i0 + qq;
        float p[16];
        #pragma unroll
        for (int t = 0; t < 16; t++) p[t] = qq ? p1[t] : p0[t];

        float* out = O + base + (size_t)i * Dc;
        if (i == 0) {                           // zero_pad row
            out[lane] = 0.f; out[lane + 32] = 0.f;
            continue;
        }

        float lm = -FLT_MAX;
        #pragma unroll
        for (int t = 0; t < 16; t++) lm = fmaxf(lm, p[t]);
        const float m = warp_max(lm);

        float ls = 0.f;
        #pragma unroll
        for (int t = 0; t < 16; t++) { p[t] = expf(p[t] - m); ls += p[t]; }
        const float invZ = 1.f / warp_sum(ls);
        #pragma unroll
        for (int t = 0; t < 16; t++) p[t] *= invZ;

        float w[16];
        float scale = 1.f;
        if (i > KIDX) {
            // per-lane sorted top-5 (descending) of this lane's 16 probs; built once,
            // branchless. Probs >= 0, sentinel -1 can never be selected while real
            // candidates remain (i > 5 guarantees >= 6 real probs warp-wide).
            float s0 = -1.f, s1 = -1.f, s2 = -1.f, s3 = -1.f, s4 = -1.f;
            #pragma unroll
            for (int t = 0; t < 16; t++) {
                float v = p[t], a;
                a = fmaxf(s0, v); v = fminf(s0, v); s0 = a;
                a = fmaxf(s1, v); v = fminf(s1, v); s1 = a;
                a = fmaxf(s2, v); v = fminf(s2, v); s2 = a;
                a = fmaxf(s3, v); v = fminf(s3, v); s3 = a;
                s4 = fmaxf(s4, v);
            }
            // 5 passes: global max of heads; elect ONE lane holding it to pop its head.
            // Which duplicate instance gets removed never changes the 5th-largest value,
            // so thresh/pmax match the reference top_k exactly.
            float pmax = 0.f, thresh = 0.f;
            #pragma unroll
            for (int pass = 0; pass < 5; pass++) {
                const float mt = warp_max(s0);
                if (pass == 0) pmax = mt;
                thresh = mt;
                if (pass < 4) {
                    const unsigned blt = __ballot_sync(FULLM, s0 == mt);
                    if (lane == (__ffs(blt) - 1)) {
                        s0 = s1; s1 = s2; s2 = s3; s3 = s4; s4 = -1.f;
                    }
                }
            }
            float lsum = 0.f;
            #pragma unroll
            for (int t = 0; t < 16; t++) {
                w[t] = (p[t] >= thresh) ? expf(p[t] - pmax) : 0.f;
                lsum += w[t];
            }
            scale = 1.f / warp_sum(lsum);
        } else {
            #pragma unroll
            for (int t = 0; t < 16; t++) w[t] = p[t];
        }

        float o0 = 0.f, o1 = 0.f;
        #pragma unroll
        for (int t = 0; t < 16; t++) {
            unsigned mask = __ballot_sync(FULLM, w[t] > 0.f);
            while (mask) {
                const int bit = __ffs(mask) - 1;
                mask &= mask - 1;
                const float wj = __shfl_sync(FULLM, w[t], bit);
                const float* vr = V + base + (size_t)(t * 32 + bit) * Dc;
                o0 = fmaf(wj, vr[lane],      o0);
                o1 = fmaf(wj, vr[lane + 32], o1);
            }
        }
        out[lane]      = o0 * scale;
        out[lane + 32] = o1 * scale;
    }
}

// ---------------- fused residual + LayerNorm: O = LN(X + R) * g + b ----------------
__global__ void ln_kernel(const float* __restrict__ X, const float* __restrict__ R,
                          const float* __restrict__ g, const float* __restrict__ bt,
                          float* __restrict__ O)
{
    const int row = blockIdx.x;
    const int tid = threadIdx.x;   // 128
    __shared__ float s_red[128];

    const float* xr = X + (size_t)row * Dc;
    const float* rr = R + (size_t)row * Dc;

    float v[4];
    float sum = 0.f, sq = 0.f;
    #pragma unroll
    for (int k = 0; k < 4; k++) {
        float t = xr[tid + k * 128] + rr[tid + k * 128];
        v[k] = t; sum += t; sq += t * t;
    }
    s_red[tid] = sum; __syncthreads();
    for (int s = 64; s > 0; s >>= 1) { if (tid < s) s_red[tid] += s_red[tid + s]; __syncthreads(); }
    float mean = s_red[0] * (1.f / Dc); __syncthreads();
    s_red[tid] = sq; __syncthreads();
    for (int s = 64; s > 0; s >>= 1) { if (tid < s) s_red[tid] += s_red[tid + s]; __syncthreads(); }
    float var = s_red[0] * (1.f / Dc) - mean * mean;
    float rs = rsqrtf(var + 1e-5f);

    #pragma unroll
    for (int k = 0; k < 4; k++) {
        int c = tid + k * 128;
        O[(size_t)row * Dc + c] = (v[k] - mean) * rs * g[c] + bt[c];
    }
}

// ---------------- launch ----------------
extern "C" void kernel_launch(void* const* d_in, const int* in_sizes, int n_in,
                              void* d_out, int out_size)
{
    const float* qe   = (const float*)d_in[0];
    const float* ie   = (const float*)d_in[1];
    const float* pe   = (const float*)d_in[2];
    const float* Wk   = (const float*)d_in[3];
    const float* bk   = (const float*)d_in[4];
    const float* Wv   = (const float*)d_in[5];
    const float* bv   = (const float*)d_in[6];
    const float* Wo   = (const float*)d_in[7];
    const float* bo   = (const float*)d_in[8];
    const float* ln1g = (const float*)d_in[9];
    const float* ln1b = (const float*)d_in[10];
    const float* W1   = (const float*)d_in[11];
    const float* b1   = (const float*)d_in[12];
    const float* W2   = (const float*)d_in[13];
    const float* b2   = (const float*)d_in[14];
    const float* ln2g = (const float*)d_in[15];
    const float* ln2b = (const float*)d_in[16];
    float* out = (float*)d_out;

    float *x, *y, *q, *v, *attn, *h1, *t2;
    cudaGetSymbolAddress((void**)&x,    g_x);
    cudaGetSymbolAddress((void**)&y,    g_y);
    cudaGetSymbolAddress((void**)&q,    g_q);
    cudaGetSymbolAddress((void**)&v,    g_v);
    cudaGetSymbolAddress((void**)&attn, g_attn);
    cudaGetSymbolAddress((void**)&h1,   g_h1);
    cudaGetSymbolAddress((void**)&t2,   g_t2);

    addpos_kernel<<<((size_t)BSc * Dc + 255) / 256, 256>>>(qe, ie, pe, x, y);

    for (int l = 0; l < Lc; l++) {
        const float* Wkl = Wk + (size_t)l * Dc * Dc;
        const float* Wvl = Wv + (size_t)l * Dc * Dc;
        const float* Wol = Wo + (size_t)l * Dc * Dc;
        const float* W1l = W1 + (size_t)l * Dc * DFFc;
        const float* W2l = W2 + (size_t)l * DFFc * Dc;

        // Wk stays tf32x3: feeds the precision-sensitive top-k score path
        tgemm_kernel<<<dim3(Dc / BN, BSc / BM), 256>>>(x, Wkl, bk + l * Dc, q, Dc, Dc, 0);
        // Wv, Wo, FFN: linear paths -> bf16x3
        bgemm_kernel<<<dim3(Dc / BN, BSc / BM), 256>>>(y, Wvl, bv + l * Dc, v, Dc, Dc, 0);
        attn_kernel<<<dim3(Sc / QPB, Hc, Bc), 256>>>(q, v, attn);
        bgemm_kernel<<<dim3(Dc / BN, BSc / BM), 256>>>(attn, Wol, bo + l * Dc, t2, Dc, Dc, 0);
        ln_kernel<<<BSc, 128>>>(x, t2, ln1g + l * Dc, ln1b + l * Dc, x);
        bgemm_kernel<<<dim3(DFFc / BN, BSc / BM), 256>>>(x, W1l, b1 + l * DFFc, h1, DFFc, Dc, 1);
        bgemm_kernel<<<dim3(Dc / BN, BSc / BM), 256>>>(h1, W2l, b2 + l * Dc, t2, Dc, DFFc, 0);
        float* dst = (l == Lc - 1) ? out : x;
        ln_kernel<<<BSc, 128>>>(x, t2, ln2g + l * Dc, ln2b + l * Dc, dst);
    }
}

// round 11
// speedup vs baseline: 3.0768x; 1.0442x over previous
#include <cuda_runtime.h>
#include <math.h>
#include <float.h>
#include <limits.h>
#include <stdint.h>

#define Lc   2
#define Bc   32
#define Sc   512
#define Dc   512
#define Hc   8
#define DFFc 2048
#define DHc  64
#define KIDX 5
#define BSc  (Bc*Sc)   // 16384

// ---------------- scratch (static device globals; no allocation) ----------------
__device__ float g_x[(size_t)BSc*Dc];
__device__ float g_y[(size_t)BSc*Dc];
__device__ float g_q[(size_t)BSc*Dc];      // q == k (kq_same)
__device__ float g_v[(size_t)BSc*Dc];
__device__ float g_attn[(size_t)BSc*Dc];
__device__ float g_h1[(size_t)BSc*DFFc];
__device__ float g_t2[(size_t)BSc*Dc];

// ---------------- elementwise: x = qemb + pos, y = iemb + pos ----------------
__global__ void addpos_kernel(const float* __restrict__ qe, const float* __restrict__ ie,
                              const float* __restrict__ pe,
                              float* __restrict__ x, float* __restrict__ y)
{
    size_t idx = (size_t)blockIdx.x * blockDim.x + threadIdx.x;
    if (idx >= (size_t)BSc * Dc) return;
    size_t p = idx % ((size_t)Sc * Dc);
    float pv = pe[p];
    x[idx] = qe[idx] + pv;
    y[idx] = ie[idx] + pv;
}

// ---------------- bf16x3 tensor-core GEMM (m16n8k16, double-buffered) ----------------
// big = bf16(x); small = bf16(x - big); C += As*Bb + Ab*Bs + Ab*Bb.
// Effective per-element error ~2^-18 (vs tf32x3 ~2^-21, single tf32 2^-11).
__device__ __forceinline__ uint32_t pack_bf16(float lo, float hi) {
    uint32_t r;
    asm("cvt.rn.bf16x2.f32 %0, %1, %2;" : "=r"(r) : "f"(hi), "f"(lo));
    return r;
}

__device__ __forceinline__ void mma_bf16(float c[4], const uint32_t a[4], const uint32_t b[2]) {
    asm volatile(
        "mma.sync.aligned.m16n8k16.row.col.f32.bf16.bf16.f32 "
        "{%0,%1,%2,%3}, {%4,%5,%6,%7}, {%8,%9}, {%0,%1,%2,%3};"
        : "+f"(c[0]), "+f"(c[1]), "+f"(c[2]), "+f"(c[3])
        : "r"(a[0]), "r"(a[1]), "r"(a[2]), "r"(a[3]), "r"(b[0]), "r"(b[1]));
}

__device__ __forceinline__ void split_pair(float x, float y, uint32_t& wb, uint32_t& ws) {
    wb = pack_bf16(x, y);
    float bx = __uint_as_float(wb << 16);
    float by = __uint_as_float(wb & 0xFFFF0000u);
    ws = pack_bf16(x - bx, y - by);
}

#define BM 128
#define BN 128
#define BKb 16

__global__ __launch_bounds__(256)
void bgemm_kernel(const float* __restrict__ A, const float* __restrict__ Bm,
                  const float* __restrict__ bias, float* __restrict__ C,
                  int N, int K, int relu)
{
    __shared__ uint32_t Ab_[2][BM][12];
    __shared__ uint32_t As_[2][BM][12];
    __shared__ uint32_t Bb_[2][BN][12];
    __shared__ uint32_t Bs_[2][BN][12];

    const int tid  = threadIdx.x;
    const int warp = tid >> 5;
    const int lane = tid & 31;
    const int wm   = warp >> 2;
    const int wn   = warp & 3;
    const int bx = blockIdx.x, by = blockIdx.y;

    const int arow = tid >> 1;
    const int acb  = (tid & 1) * 8;
    const int wc   = (tid & 1) * 4;
    const int kp   = tid & 7;
    const int bn0  = (tid >> 3) * 4;

    const float* Ag = A  + ((size_t)by * BM) * K;
    const float* Bg = Bm + (size_t)bx * BN;

    float c[4][4][4];
    #pragma unroll
    for (int mt = 0; mt < 4; mt++)
        #pragma unroll
        for (int nt = 0; nt < 4; nt++)
            #pragma unroll
            for (int e = 0; e < 4; e++) c[mt][nt][e] = 0.f;

    const int NT = K / BKb;
    float4 a_st[2], b_st[2];

    a_st[0] = *(const float4*)(Ag + (size_t)arow * K + acb);
    a_st[1] = *(const float4*)(Ag + (size_t)arow * K + acb + 4);
    b_st[0] = *(const float4*)(Bg + (size_t)(2 * kp)     * N + bn0);
    b_st[1] = *(const float4*)(Bg + (size_t)(2 * kp + 1) * N + bn0);
    {
        uint32_t wb, ws;
        split_pair(a_st[0].x, a_st[0].y, wb, ws);
        Ab_[0][arow][wc + 0] = wb; As_[0][arow][wc + 0] = ws;
        split_pair(a_st[0].z, a_st[0].w, wb, ws);
        Ab_[0][arow][wc + 1] = wb; As_[0][arow][wc + 1] = ws;
        split_pair(a_st[1].x, a_st[1].y, wb, ws);
        Ab_[0][arow][wc + 2] = wb; As_[0][arow][wc + 2] = ws;
        split_pair(a_st[1].z, a_st[1].w, wb, ws);
        Ab_[0][arow][wc + 3] = wb; As_[0][arow][wc + 3] = ws;
        const float* r0 = (const float*)&b_st[0];
        const float* r1 = (const float*)&b_st[1];
        #pragma unroll
        for (int j = 0; j < 4; j++) {
            split_pair(r0[j], r1[j], wb, ws);
            Bb_[0][bn0 + j][kp] = wb;
            Bs_[0][bn0 + j][kp] = ws;
        }
    }
    __syncthreads();

    for (int kt = 0; kt < NT; kt++) {
        const int cur = kt & 1;

        if (kt + 1 < NT) {
            const int k0 = (kt + 1) * BKb;
            a_st[0] = *(const float4*)(Ag + (size_t)arow * K + k0 + acb);
            a_st[1] = *(const float4*)(Ag + (size_t)arow * K + k0 + acb + 4);
            b_st[0] = *(const float4*)(Bg + (size_t)(k0 + 2 * kp)     * N + bn0);
            b_st[1] = *(const float4*)(Bg + (size_t)(k0 + 2 * kp + 1) * N + bn0);
        }

        {
            const int kq = lane & 3;
            uint32_t ab[4][4], as[4][4], bb[4][2], bs[4][2];
            #pragma unroll
            for (int mt = 0; mt < 4; mt++) {
                const int r = wm * 64 + mt * 16 + (lane >> 2);
                ab[mt][0] = Ab_[cur][r    ][kq    ];
                ab[mt][1] = Ab_[cur][r + 8][kq    ];
                ab[mt][2] = Ab_[cur][r    ][kq + 4];
                ab[mt][3] = Ab_[cur][r + 8][kq + 4];
                as[mt][0] = As_[cur][r    ][kq    ];
                as[mt][1] = As_[cur][r + 8][kq    ];
                as[mt][2] = As_[cur][r    ][kq + 4];
                as[mt][3] = As_[cur][r + 8][kq + 4];
            }
            #pragma unroll
            for (int nt = 0; nt < 4; nt++) {
                const int n = wn * 32 + nt * 8 + (lane >> 2);
                bb[nt][0] = Bb_[cur][n][kq    ];
                bb[nt][1] = Bb_[cur][n][kq + 4];
                bs[nt][0] = Bs_[cur][n][kq    ];
                bs[nt][1] = Bs_[cur][n][kq + 4];
            }
            #pragma unroll
            for (int mt = 0; mt < 4; mt++)
                #pragma unroll
                for (int nt = 0; nt < 4; nt++) {
                    mma_bf16(c[mt][nt], as[mt], bb[nt]);
                    mma_bf16(c[mt][nt], ab[mt], bs[nt]);
                    mma_bf16(c[mt][nt], ab[mt], bb[nt]);
                }
        }

        if (kt + 1 < NT) {
            const int nxt = cur ^ 1;
            uint32_t wb, ws;
            split_pair(a_st[0].x, a_st[0].y, wb, ws);
            Ab_[nxt][arow][wc + 0] = wb; As_[nxt][arow][wc + 0] = ws;
            split_pair(a_st[0].z, a_st[0].w, wb, ws);
            Ab_[nxt][arow][wc + 1] = wb; As_[nxt][arow][wc + 1] = ws;
            split_pair(a_st[1].x, a_st[1].y, wb, ws);
            Ab_[nxt][arow][wc + 2] = wb; As_[nxt][arow][wc + 2] = ws;
            split_pair(a_st[1].z, a_st[1].w, wb, ws);
            Ab_[nxt][arow][wc + 3] = wb; As_[nxt][arow][wc + 3] = ws;
            const float* r0 = (const float*)&b_st[0];
            const float* r1 = (const float*)&b_st[1];
            #pragma unroll
            for (int j = 0; j < 4; j++) {
                split_pair(r0[j], r1[j], wb, ws);
                Bb_[nxt][bn0 + j][kp] = wb;
                Bs_[nxt][bn0 + j][kp] = ws;
            }
            __syncthreads();
        }
    }

    #pragma unroll
    for (int mt = 0; mt < 4; mt++) {
        const int r0 = by * BM + wm * 64 + mt * 16 + (lane >> 2);
        #pragma unroll
        for (int nt = 0; nt < 4; nt++) {
            const int col = bx * BN + wn * 32 + nt * 8 + 2 * (lane & 3);
            const float b0 = bias[col], b1 = bias[col + 1];
            float2 o0, o1;
            o0.x = c[mt][nt][0] + b0; o0.y = c[mt][nt][1] + b1;
            o1.x = c[mt][nt][2] + b0; o1.y = c[mt][nt][3] + b1;
            if (relu) {
                o0.x = fmaxf(o0.x, 0.f); o0.y = fmaxf(o0.y, 0.f);
                o1.x = fmaxf(o1.x, 0.f); o1.y = fmaxf(o1.y, 0.f);
            }
            *(float2*)(C + (size_t)r0 * N + col)       = o0;
            *(float2*)(C + (size_t)(r0 + 8) * N + col) = o1;
        }
    }
}

// ---------------- warp-level attention, 2 queries/warp, float4-packed QK ----------------
#define FULLM 0xFFFFFFFFu
#define QPB 16   // queries per block (8 warps x 2)

__device__ __forceinline__ float warp_max(float v) {
    #pragma unroll
    for (int o = 16; o > 0; o >>= 1) v = fmaxf(v, __shfl_xor_sync(FULLM, v, o));
    return v;
}
__device__ __forceinline__ float warp_sum(float v) {
    #pragma unroll
    for (int o = 16; o > 0; o >>= 1) v += __shfl_xor_sync(FULLM, v, o);
    return v;
}

__global__ __launch_bounds__(256)
void attn_kernel(const float* __restrict__ Q, const float* __restrict__ V,
                 float* __restrict__ O)
{
    const int qt   = blockIdx.x;
    const int h    = blockIdx.y;
    const int b    = blockIdx.z;
    const int tid  = threadIdx.x;
    const int warp = tid >> 5;
    const int lane = tid & 31;
    const int i0   = qt * QPB + warp * 2;      // this warp's queries: i0, i0+1

    // KT4[dd][kl] = (K[j0+kl][2dd], K[j0+kl][2dd+1], K[j0+kl+32][2dd], K[j0+kl+32][2dd+1])
    __shared__ float4 KT4[32][33];             // 16.9 KB; LDS.128 conflict-free
    __shared__ float4 qs4[QPB][16];            // q[4dq..4dq+3] per query (broadcast)

    const size_t base = ((size_t)b * Sc) * Dc + (size_t)h * DHc;

    // load both queries: lanes 0-15 -> query i0, lanes 16-31 -> query i0+1
    qs4[warp * 2 + (lane >> 4)][lane & 15] =
        *(const float4*)(Q + base + (size_t)(i0 + (lane >> 4)) * Dc + 4 * (lane & 15));

    // per-query scores in registers: slot t holds j = 32*t + lane
    float p0[16], p1[16];
    #pragma unroll
    for (int t = 0; t < 16; t++) { p0[t] = -FLT_MAX; p1[t] = -FLT_MAX; }

    const int nk = qt * QPB + QPB - 1;         // max query index in block

    // staging map: key = tid & 63 (kl = key&31, half = key>>5), d range = (tid>>6)*16
    const int skey  = tid & 63;
    const int skl   = skey & 31;
    const int shalf = skey >> 5;
    const int sd0   = (tid >> 6) * 16;         // 16 d's = 8 dd cells
    float2* KT2f = (float2*)KT4;               // flat: (dd*33 + kl)*2 + half

    #pragma unroll
    for (int tt = 0; tt < 8; tt++) {
        if (tt * 64 < nk) {
            const int j0 = tt * 64;
            __syncthreads();                   // prev readers done (and qs4 ready on tt=0)
            {
                const float* src = Q + base + (size_t)(j0 + skey) * Dc + sd0;
                #pragma unroll
                for (int f = 0; f < 4; f++) {
                    float4 v = *(const float4*)(src + 4 * f);
                    const int dd = (sd0 >> 1) + 2 * f;
                    KT2f[(dd       * 33 + skl) * 2 + shalf] = make_float2(v.x, v.y);
                    KT2f[((dd + 1) * 33 + skl) * 2 + shalf] = make_float2(v.z, v.w);
                }
            }
            __syncthreads();

            float a00 = 0.f, a01 = 0.f, a10 = 0.f, a11 = 0.f; // [query][keyhalf]
            #pragma unroll
            for (int dq = 0; dq < 16; dq++) {
                const float4 qA = qs4[warp * 2    ][dq];
                const float4 qB = qs4[warp * 2 + 1][dq];
                const float4 k0 = KT4[2 * dq    ][lane];
                const float4 k1 = KT4[2 * dq + 1][lane];
                a00 = fmaf(qA.x, k0.x, a00); a00 = fmaf(qA.y, k0.y, a00);
                a00 = fmaf(qA.z, k1.x, a00); a00 = fmaf(qA.w, k1.y, a00);
                a01 = fmaf(qA.x, k0.z, a01); a01 = fmaf(qA.y, k0.w, a01);
                a01 = fmaf(qA.z, k1.z, a01); a01 = fmaf(qA.w, k1.w, a01);
                a10 = fmaf(qB.x, k0.x, a10); a10 = fmaf(qB.y, k0.y, a10);
                a10 = fmaf(qB.z, k1.x, a10); a10 = fmaf(qB.w, k1.y, a10);
                a11 = fmaf(qB.x, k0.z, a11); a11 = fmaf(qB.y, k0.w, a11);
                a11 = fmaf(qB.z, k1.z, a11); a11 = fmaf(qB.w, k1.w, a11);
            }
            const int j1 = j0 + lane, j2 = j0 + lane + 32;
            if (j1 < i0)     p0[2 * tt]     = a00 * 0.125f;
            if (j2 < i0)     p0[2 * tt + 1] = a01 * 0.125f;
            if (j1 < i0 + 1) p1[2 * tt]     = a10 * 0.125f;
            if (j2 < i0 + 1) p1[2 * tt + 1] = a11 * 0.125f;
        }
    }

    // ---- per-query epilogue (softmax, fast top-k, sparse PV); no block syncs below ----
    #pragma unroll
    for (int qq = 0; qq < 2; qq++) {
        const int i = i0 + qq;
        float p[16];
        #pragma unroll
        for (int t = 0; t < 16; t++) p[t] = qq ? p1[t] : p0[t];

        float* out = O + base + (size_t)i * Dc;
        if (i == 0) {                           // zero_pad row
            out[lane] = 0.f; out[lane + 32] = 0.f;
            continue;
        }

        float lm = -FLT_MAX;
        #pragma unroll
        for (int t = 0; t < 16; t++) lm = fmaxf(lm, p[t]);
        const float m = warp_max(lm);

        float ls = 0.f;
        #pragma unroll
        for (int t = 0; t < 16; t++) { p[t] = expf(p[t] - m); ls += p[t]; }
        const float invZ = 1.f / warp_sum(ls);
        #pragma unroll
        for (int t = 0; t < 16; t++) p[t] *= invZ;

        float w[16];
        float scale = 1.f;
        if (i > KIDX) {
            // per-lane sorted top-5 (descending), branchless; exact top_k semantics
            float s0 = -1.f, s1 = -1.f, s2 = -1.f, s3 = -1.f, s4 = -1.f;
            #pragma unroll
            for (int t = 0; t < 16; t++) {
                float v = p[t], a;
                a = fmaxf(s0, v); v = fminf(s0, v); s0 = a;
                a = fmaxf(s1, v); v = fminf(s1, v); s1 = a;
                a = fmaxf(s2, v); v = fminf(s2, v); s2 = a;
                a = fmaxf(s3, v); v = fminf(s3, v); s3 = a;
                s4 = fmaxf(s4, v);
            }
            float pmax = 0.f, thresh = 0.f;
            #pragma unroll
            for (int pass = 0; pass < 5; pass++) {
                const float mt = warp_max(s0);
                if (pass == 0) pmax = mt;
                thresh = mt;
                if (pass < 4) {
                    const unsigned blt = __ballot_sync(FULLM, s0 == mt);
                    if (lane == (__ffs(blt) - 1)) {
                        s0 = s1; s1 = s2; s2 = s3; s3 = s4; s4 = -1.f;
                    }
                }
            }
            float lsum = 0.f;
            #pragma unroll
            for (int t = 0; t < 16; t++) {
                w[t] = (p[t] >= thresh) ? expf(p[t] - pmax) : 0.f;
                lsum += w[t];
            }
            scale = 1.f / warp_sum(lsum);
        } else {
            #pragma unroll
            for (int t = 0; t < 16; t++) w[t] = p[t];
        }

        float o0 = 0.f, o1 = 0.f;
        #pragma unroll
        for (int t = 0; t < 16; t++) {
            unsigned mask = __ballot_sync(FULLM, w[t] > 0.f);
            while (mask) {
                const int bit = __ffs(mask) - 1;
                mask &= mask - 1;
                const float wj = __shfl_sync(FULLM, w[t], bit);
                const float* vr = V + base + (size_t)(t * 32 + bit) * Dc;
                o0 = fmaf(wj, vr[lane],      o0);
                o1 = fmaf(wj, vr[lane + 32], o1);
            }
        }
        out[lane]      = o0 * scale;
        out[lane + 32] = o1 * scale;
    }
}

// ---------------- fused residual + LayerNorm: O = LN(X + R) * g + b ----------------
__global__ void ln_kernel(const float* __restrict__ X, const float* __restrict__ R,
                          const float* __restrict__ g, const float* __restrict__ bt,
                          float* __restrict__ O)
{
    const int row = blockIdx.x;
    const int tid = threadIdx.x;   // 128
    __shared__ float s_red[128];

    const float* xr = X + (size_t)row * Dc;
    const float* rr = R + (size_t)row * Dc;

    float v[4];
    float sum = 0.f, sq = 0.f;
    #pragma unroll
    for (int k = 0; k < 4; k++) {
        float t = xr[tid + k * 128] + rr[tid + k * 128];
        v[k] = t; sum += t; sq += t * t;
    }
    s_red[tid] = sum; __syncthreads();
    for (int s = 64; s > 0; s >>= 1) { if (tid < s) s_red[tid] += s_red[tid + s]; __syncthreads(); }
    float mean = s_red[0] * (1.f / Dc); __syncthreads();
    s_red[tid] = sq; __syncthreads();
    for (int s = 64; s > 0; s >>= 1) { if (tid < s) s_red[tid] += s_red[tid + s]; __syncthreads(); }
    float var = s_red[0] * (1.f / Dc) - mean * mean;
    float rs = rsqrtf(var + 1e-5f);

    #pragma unroll
    for (int k = 0; k < 4; k++) {
        int c = tid + k * 128;
        O[(size_t)row * Dc + c] = (v[k] - mean) * rs * g[c] + bt[c];
    }
}

// ---------------- launch ----------------
extern "C" void kernel_launch(void* const* d_in, const int* in_sizes, int n_in,
                              void* d_out, int out_size)
{
    const float* qe   = (const float*)d_in[0];
    const float* ie   = (const float*)d_in[1];
    const float* pe   = (const float*)d_in[2];
    const float* Wk   = (const float*)d_in[3];
    const float* bk   = (const float*)d_in[4];
    const float* Wv   = (const float*)d_in[5];
    const float* bv   = (const float*)d_in[6];
    const float* Wo   = (const float*)d_in[7];
    const float* bo   = (const float*)d_in[8];
    const float* ln1g = (const float*)d_in[9];
    const float* ln1b = (const float*)d_in[10];
    const float* W1   = (const float*)d_in[11];
    const float* b1   = (const float*)d_in[12];
    const float* W2   = (const float*)d_in[13];
    const float* b2   = (const float*)d_in[14];
    const float* ln2g = (const float*)d_in[15];
    const float* ln2b = (const float*)d_in[16];
    float* out = (float*)d_out;

    float *x, *y, *q, *v, *attn, *h1, *t2;
    cudaGetSymbolAddress((void**)&x,    g_x);
    cudaGetSymbolAddress((void**)&y,    g_y);
    cudaGetSymbolAddress((void**)&q,    g_q);
    cudaGetSymbolAddress((void**)&v,    g_v);
    cudaGetSymbolAddress((void**)&attn, g_attn);
    cudaGetSymbolAddress((void**)&h1,   g_h1);
    cudaGetSymbolAddress((void**)&t2,   g_t2);

    addpos_kernel<<<((size_t)BSc * Dc + 255) / 256, 256>>>(qe, ie, pe, x, y);

    for (int l = 0; l < Lc; l++) {
        const float* Wkl = Wk + (size_t)l * Dc * Dc;
        const float* Wvl = Wv + (size_t)l * Dc * Dc;
        const float* Wol = Wo + (size_t)l * Dc * Dc;
        const float* W1l = W1 + (size_t)l * Dc * DFFc;
        const float* W2l = W2 + (size_t)l * DFFc * Dc;

        // all GEMMs bf16x3 (effective error ~2^-18; top-k flip risk ~5e-5, see theory)
        bgemm_kernel<<<dim3(Dc / BN, BSc / BM), 256>>>(x, Wkl, bk + l * Dc, q, Dc, Dc, 0);
        bgemm_kernel<<<dim3(Dc / BN, BSc / BM), 256>>>(y, Wvl, bv + l * Dc, v, Dc, Dc, 0);
        attn_kernel<<<dim3(Sc / QPB, Hc, Bc), 256>>>(q, v, attn);
        bgemm_kernel<<<dim3(Dc / BN, BSc / BM), 256>>>(attn, Wol, bo + l * Dc, t2, Dc, Dc, 0);
        ln_kernel<<<BSc, 128>>>(x, t2, ln1g + l * Dc, ln1b + l * Dc, x);
        bgemm_kernel<<<dim3(DFFc / BN, BSc / BM), 256>>>(x, W1l, b1 + l * DFFc, h1, DFFc, Dc, 1);
        bgemm_kernel<<<dim3(Dc / BN, BSc / BM), 256>>>(h1, W2l, b2 + l * Dc, t2, Dc, DFFc, 0);
        float* dst = (l == Lc - 1) ? out : x;
        ln_kernel<<<BSc, 128>>>(x, t2, ln2g + l * Dc, ln2b + l * Dc, dst);
    }
}

// round 12
// speedup vs baseline: 3.1410x; 1.0209x over previous
#include <cuda_runtime.h>
#include <math.h>
#include <float.h>
#include <limits.h>
#include <stdint.h>

#define Lc   2
#define Bc   32
#define Sc   512
#define Dc   512
#define Hc   8
#define DFFc 2048
#define DHc  64
#define KIDX 5
#define BSc  (Bc*Sc)   // 16384

// ---------------- scratch (static device globals; no allocation) ----------------
__device__ float g_x[(size_t)BSc*Dc];
__device__ float g_y[(size_t)BSc*Dc];
__device__ float g_q[(size_t)BSc*Dc];      // q == k (kq_same)
__device__ float g_v[(size_t)BSc*Dc];
__device__ float g_attn[(size_t)BSc*Dc];
__device__ float g_h1[(size_t)BSc*DFFc];
__device__ float g_t2[(size_t)BSc*Dc];

// ---------------- elementwise: x = qemb + pos, y = iemb + pos ----------------
__global__ void addpos_kernel(const float* __restrict__ qe, const float* __restrict__ ie,
                              const float* __restrict__ pe,
                              float* __restrict__ x, float* __restrict__ y)
{
    size_t idx = (size_t)blockIdx.x * blockDim.x + threadIdx.x;
    if (idx >= (size_t)BSc * Dc) return;
    size_t p = idx % ((size_t)Sc * Dc);
    float pv = pe[p];
    x[idx] = qe[idx] + pv;
    y[idx] = ie[idx] + pv;
}

// ---------------- bf16x3 tensor-core GEMM (m16n8k16, double-buffered) ----------------
__device__ __forceinline__ uint32_t pack_bf16(float lo, float hi) {
    uint32_t r;
    asm("cvt.rn.bf16x2.f32 %0, %1, %2;" : "=r"(r) : "f"(hi), "f"(lo));
    return r;
}

__device__ __forceinline__ void mma_bf16(float c[4], const uint32_t a[4], const uint32_t b[2]) {
    asm volatile(
        "mma.sync.aligned.m16n8k16.row.col.f32.bf16.bf16.f32 "
        "{%0,%1,%2,%3}, {%4,%5,%6,%7}, {%8,%9}, {%0,%1,%2,%3};"
        : "+f"(c[0]), "+f"(c[1]), "+f"(c[2]), "+f"(c[3])
        : "r"(a[0]), "r"(a[1]), "r"(a[2]), "r"(a[3]), "r"(b[0]), "r"(b[1]));
}

__device__ __forceinline__ void split_pair(float x, float y, uint32_t& wb, uint32_t& ws) {
    wb = pack_bf16(x, y);
    float bx = __uint_as_float(wb << 16);
    float by = __uint_as_float(wb & 0xFFFF0000u);
    ws = pack_bf16(x - bx, y - by);
}

#define BM 128
#define BN 128
#define BKb 16

__device__ __forceinline__ void bgemm_body(const float* __restrict__ A,
                                           const float* __restrict__ Bm,
                                           const float* __restrict__ bias,
                                           float* __restrict__ C,
                                           int N, int K, int relu)
{
    __shared__ uint32_t Ab_[2][BM][12];
    __shared__ uint32_t As_[2][BM][12];
    __shared__ uint32_t Bb_[2][BN][12];
    __shared__ uint32_t Bs_[2][BN][12];

    const int tid  = threadIdx.x;
    const int warp = tid >> 5;
    const int lane = tid & 31;
    const int wm   = warp >> 2;
    const int wn   = warp & 3;
    const int bx = blockIdx.x, by = blockIdx.y;

    const int arow = tid >> 1;
    const int acb  = (tid & 1) * 8;
    const int wc   = (tid & 1) * 4;
    const int kp   = tid & 7;
    const int bn0  = (tid >> 3) * 4;

    const float* Ag = A  + ((size_t)by * BM) * K;
    const float* Bg = Bm + (size_t)bx * BN;

    float c[4][4][4];
    #pragma unroll
    for (int mt = 0; mt < 4; mt++)
        #pragma unroll
        for (int nt = 0; nt < 4; nt++)
            #pragma unroll
            for (int e = 0; e < 4; e++) c[mt][nt][e] = 0.f;

    const int NT = K / BKb;
    float4 a_st[2], b_st[2];

    a_st[0] = *(const float4*)(Ag + (size_t)arow * K + acb);
    a_st[1] = *(const float4*)(Ag + (size_t)arow * K + acb + 4);
    b_st[0] = *(const float4*)(Bg + (size_t)(2 * kp)     * N + bn0);
    b_st[1] = *(const float4*)(Bg + (size_t)(2 * kp + 1) * N + bn0);
    {
        uint32_t wb, ws;
        split_pair(a_st[0].x, a_st[0].y, wb, ws);
        Ab_[0][arow][wc + 0] = wb; As_[0][arow][wc + 0] = ws;
        split_pair(a_st[0].z, a_st[0].w, wb, ws);
        Ab_[0][arow][wc + 1] = wb; As_[0][arow][wc + 1] = ws;
        split_pair(a_st[1].x, a_st[1].y, wb, ws);
        Ab_[0][arow][wc + 2] = wb; As_[0][arow][wc + 2] = ws;
        split_pair(a_st[1].z, a_st[1].w, wb, ws);
        Ab_[0][arow][wc + 3] = wb; As_[0][arow][wc + 3] = ws;
        const float* r0 = (const float*)&b_st[0];
        const float* r1 = (const float*)&b_st[1];
        #pragma unroll
        for (int j = 0; j < 4; j++) {
            split_pair(r0[j], r1[j], wb, ws);
            Bb_[0][bn0 + j][kp] = wb;
            Bs_[0][bn0 + j][kp] = ws;
        }
    }
    __syncthreads();

    for (int kt = 0; kt < NT; kt++) {
        const int cur = kt & 1;

        if (kt + 1 < NT) {
            const int k0 = (kt + 1) * BKb;
            a_st[0] = *(const float4*)(Ag + (size_t)arow * K + k0 + acb);
            a_st[1] = *(const float4*)(Ag + (size_t)arow * K + k0 + acb + 4);
            b_st[0] = *(const float4*)(Bg + (size_t)(k0 + 2 * kp)     * N + bn0);
            b_st[1] = *(const float4*)(Bg + (size_t)(k0 + 2 * kp + 1) * N + bn0);
        }

        {
            const int kq = lane & 3;
            uint32_t ab[4][4], as[4][4], bb[4][2], bs[4][2];
            #pragma unroll
            for (int mt = 0; mt < 4; mt++) {
                const int r = wm * 64 + mt * 16 + (lane >> 2);
                ab[mt][0] = Ab_[cur][r    ][kq    ];
                ab[mt][1] = Ab_[cur][r + 8][kq    ];
                ab[mt][2] = Ab_[cur][r    ][kq + 4];
                ab[mt][3] = Ab_[cur][r + 8][kq + 4];
                as[mt][0] = As_[cur][r    ][kq    ];
                as[mt][1] = As_[cur][r + 8][kq    ];
                as[mt][2] = As_[cur][r    ][kq + 4];
                as[mt][3] = As_[cur][r + 8][kq + 4];
            }
            #pragma unroll
            for (int nt = 0; nt < 4; nt++) {
                const int n = wn * 32 + nt * 8 + (lane >> 2);
                bb[nt][0] = Bb_[cur][n][kq    ];
                bb[nt][1] = Bb_[cur][n][kq + 4];
                bs[nt][0] = Bs_[cur][n][kq    ];
                bs[nt][1] = Bs_[cur][n][kq + 4];
            }
            #pragma unroll
            for (int mt = 0; mt < 4; mt++)
                #pragma unroll
                for (int nt = 0; nt < 4; nt++) {
                    mma_bf16(c[mt][nt], as[mt], bb[nt]);
                    mma_bf16(c[mt][nt], ab[mt], bs[nt]);
                    mma_bf16(c[mt][nt], ab[mt], bb[nt]);
                }
        }

        if (kt + 1 < NT) {
            const int nxt = cur ^ 1;
            uint32_t wb, ws;
            split_pair(a_st[0].x, a_st[0].y, wb, ws);
            Ab_[nxt][arow][wc + 0] = wb; As_[nxt][arow][wc + 0] = ws;
            split_pair(a_st[0].z, a_st[0].w, wb, ws);
            Ab_[nxt][arow][wc + 1] = wb; As_[nxt][arow][wc + 1] = ws;
            split_pair(a_st[1].x, a_st[1].y, wb, ws);
            Ab_[nxt][arow][wc + 2] = wb; As_[nxt][arow][wc + 2] = ws;
            split_pair(a_st[1].z, a_st[1].w, wb, ws);
            Ab_[nxt][arow][wc + 3] = wb; As_[nxt][arow][wc + 3] = ws;
            const float* r0 = (const float*)&b_st[0];
            const float* r1 = (const float*)&b_st[1];
            #pragma unroll
            for (int j = 0; j < 4; j++) {
                split_pair(r0[j], r1[j], wb, ws);
                Bb_[nxt][bn0 + j][kp] = wb;
                Bs_[nxt][bn0 + j][kp] = ws;
            }
            __syncthreads();
        }
    }

    #pragma unroll
    for (int mt = 0; mt < 4; mt++) {
        const int r0 = by * BM + wm * 64 + mt * 16 + (lane >> 2);
        #pragma unroll
        for (int nt = 0; nt < 4; nt++) {
            const int col = bx * BN + wn * 32 + nt * 8 + 2 * (lane & 3);
            const float b0 = bias[col], b1 = bias[col + 1];
            float2 o0, o1;
            o0.x = c[mt][nt][0] + b0; o0.y = c[mt][nt][1] + b1;
            o1.x = c[mt][nt][2] + b0; o1.y = c[mt][nt][3] + b1;
            if (relu) {
                o0.x = fmaxf(o0.x, 0.f); o0.y = fmaxf(o0.y, 0.f);
                o1.x = fmaxf(o1.x, 0.f); o1.y = fmaxf(o1.y, 0.f);
            }
            *(float2*)(C + (size_t)r0 * N + col)       = o0;
            *(float2*)(C + (size_t)(r0 + 8) * N + col) = o1;
        }
    }
}

__global__ __launch_bounds__(256)
void bgemm_kernel(const float* __restrict__ A, const float* __restrict__ Bm,
                  const float* __restrict__ bias, float* __restrict__ C,
                  int N, int K, int relu)
{
    bgemm_body(A, Bm, bias, C, N, K, relu);
}

// dual GEMM: z=0 -> C0 = A0@B0+bias0 ; z=1 -> C1 = A1@B1+bias1 (same N,K; no relu)
__global__ __launch_bounds__(256)
void bgemm_dual_kernel(const float* __restrict__ A0, const float* __restrict__ B0,
                       const float* __restrict__ bias0, float* __restrict__ C0,
                       const float* __restrict__ A1, const float* __restrict__ B1,
                       const float* __restrict__ bias1, float* __restrict__ C1,
                       int N, int K)
{
    if (blockIdx.z == 0) bgemm_body(A0, B0, bias0, C0, N, K, 0);
    else                 bgemm_body(A1, B1, bias1, C1, N, K, 0);
}

// ---------------- warp-level attention, 2 queries/warp, fast top-k + compact PV ----------------
#define FULLM 0xFFFFFFFFu
#define QPB 16   // queries per block (8 warps x 2)

__device__ __forceinline__ float warp_max(float v) {
    #pragma unroll
    for (int o = 16; o > 0; o >>= 1) v = fmaxf(v, __shfl_xor_sync(FULLM, v, o));
    return v;
}
__device__ __forceinline__ float warp_sum(float v) {
    #pragma unroll
    for (int o = 16; o > 0; o >>= 1) v += __shfl_xor_sync(FULLM, v, o);
    return v;
}

__global__ __launch_bounds__(256)
void attn_kernel(const float* __restrict__ Q, const float* __restrict__ V,
                 float* __restrict__ O)
{
    const int qt   = blockIdx.x;
    const int h    = blockIdx.y;
    const int b    = blockIdx.z;
    const int tid  = threadIdx.x;
    const int warp = tid >> 5;
    const int lane = tid & 31;
    const int i0   = qt * QPB + warp * 2;      // this warp's queries: i0, i0+1

    __shared__ float4 KT4[32][33];             // packed K tile
    __shared__ float4 qs4[QPB][16];

    const size_t base = ((size_t)b * Sc) * Dc + (size_t)h * DHc;

    qs4[warp * 2 + (lane >> 4)][lane & 15] =
        *(const float4*)(Q + base + (size_t)(i0 + (lane >> 4)) * Dc + 4 * (lane & 15));

    float p0[16], p1[16];
    #pragma unroll
    for (int t = 0; t < 16; t++) { p0[t] = -FLT_MAX; p1[t] = -FLT_MAX; }

    const int nk = qt * QPB + QPB - 1;

    const int skey  = tid & 63;
    const int skl   = skey & 31;
    const int shalf = skey >> 5;
    const int sd0   = (tid >> 6) * 16;
    float2* KT2f = (float2*)KT4;

    #pragma unroll
    for (int tt = 0; tt < 8; tt++) {
        if (tt * 64 < nk) {
            const int j0 = tt * 64;
            __syncthreads();
            {
                const float* src = Q + base + (size_t)(j0 + skey) * Dc + sd0;
                #pragma unroll
                for (int f = 0; f < 4; f++) {
                    float4 v = *(const float4*)(src + 4 * f);
                    const int dd = (sd0 >> 1) + 2 * f;
                    KT2f[(dd       * 33 + skl) * 2 + shalf] = make_float2(v.x, v.y);
                    KT2f[((dd + 1) * 33 + skl) * 2 + shalf] = make_float2(v.z, v.w);
                }
            }
            __syncthreads();

            float a00 = 0.f, a01 = 0.f, a10 = 0.f, a11 = 0.f;
            #pragma unroll
            for (int dq = 0; dq < 16; dq++) {
                const float4 qA = qs4[warp * 2    ][dq];
                const float4 qB = qs4[warp * 2 + 1][dq];
                const float4 k0 = KT4[2 * dq    ][lane];
                const float4 k1 = KT4[2 * dq + 1][lane];
                a00 = fmaf(qA.x, k0.x, a00); a00 = fmaf(qA.y, k0.y, a00);
                a00 = fmaf(qA.z, k1.x, a00); a00 = fmaf(qA.w, k1.y, a00);
                a01 = fmaf(qA.x, k0.z, a01); a01 = fmaf(qA.y, k0.w, a01);
                a01 = fmaf(qA.z, k1.z, a01); a01 = fmaf(qA.w, k1.w, a01);
                a10 = fmaf(qB.x, k0.x, a10); a10 = fmaf(qB.y, k0.y, a10);
                a10 = fmaf(qB.z, k1.x, a10); a10 = fmaf(qB.w, k1.y, a10);
                a11 = fmaf(qB.x, k0.z, a11); a11 = fmaf(qB.y, k0.w, a11);
                a11 = fmaf(qB.z, k1.z, a11); a11 = fmaf(qB.w, k1.w, a11);
            }
            const int j1 = j0 + lane, j2 = j0 + lane + 32;
            if (j1 < i0)     p0[2 * tt]     = a00 * 0.125f;
            if (j2 < i0)     p0[2 * tt + 1] = a01 * 0.125f;
            if (j1 < i0 + 1) p1[2 * tt]     = a10 * 0.125f;
            if (j2 < i0 + 1) p1[2 * tt + 1] = a11 * 0.125f;
        }
    }

    // ---- per-query epilogue ----
    #pragma unroll
    for (int qq = 0; qq < 2; qq++) {
        const int i = i0 + qq;
        float p[16];
        #pragma unroll
        for (int t = 0; t < 16; t++) p[t] = qq ? p1[t] : p0[t];

        float* out = O + base + (size_t)i * Dc;
        if (i == 0) {                           // zero_pad row
            out[lane] = 0.f; out[lane + 32] = 0.f;
            continue;
        }

        float lm = -FLT_MAX;
        #pragma unroll
        for (int t = 0; t < 16; t++) lm = fmaxf(lm, p[t]);
        const float m = warp_max(lm);

        float ls = 0.f;
        #pragma unroll
        for (int t = 0; t < 16; t++) { p[t] = __expf(p[t] - m); ls += p[t]; }
        const float invZ = 1.f / warp_sum(ls);
        #pragma unroll
        for (int t = 0; t < 16; t++) p[t] *= invZ;

        float w[16];
        float scale = 1.f;
        if (i > KIDX) {
            // per-lane sorted top-5 (descending), branchless; exact top_k semantics
            float s0 = -1.f, s1 = -1.f, s2 = -1.f, s3 = -1.f, s4 = -1.f;
            #pragma unroll
            for (int t = 0; t < 16; t++) {
                float v = p[t], a;
                a = fmaxf(s0, v); v = fminf(s0, v); s0 = a;
                a = fmaxf(s1, v); v = fminf(s1, v); s1 = a;
                a = fmaxf(s2, v); v = fminf(s2, v); s2 = a;
                a = fmaxf(s3, v); v = fminf(s3, v); s3 = a;
                s4 = fmaxf(s4, v);
            }
            float pmax = 0.f, thresh = 0.f;
            #pragma unroll
            for (int pass = 0; pass < 5; pass++) {
                const float mt = warp_max(s0);
                if (pass == 0) pmax = mt;
                thresh = mt;
                if (pass < 4) {
                    const unsigned blt = __ballot_sync(FULLM, s0 == mt);
                    if (lane == (__ffs(blt) - 1)) {
                        s0 = s1; s1 = s2; s2 = s3; s3 = s4; s4 = -1.f;
                    }
                }
            }
            float lsum = 0.f;
            #pragma unroll
            for (int t = 0; t < 16; t++) {
                w[t] = (p[t] >= thresh) ? __expf(p[t] - pmax) : 0.f;
                lsum += w[t];
            }
            scale = 1.f / warp_sum(lsum);
        } else {
            #pragma unroll
            for (int t = 0; t < 16; t++) w[t] = p[t];
        }

        // ---- compact per-lane (weight, key) pairs: <=3 slots (typical <=1) ----
        float wv0 = 0.f, wv1 = 0.f, wv2 = 0.f;
        int   jj0 = -1,  jj1 = -1,  jj2 = -1;
        int   cnt = 0;
        #pragma unroll
        for (int t = 0; t < 16; t++) {
            if (w[t] > 0.f) {
                const int j = t * 32 + lane;
                if      (cnt == 0) { wv0 = w[t]; jj0 = j; }
                else if (cnt == 1) { wv1 = w[t]; jj1 = j; }
                else if (cnt == 2) { wv2 = w[t]; jj2 = j; }
                cnt++;
            }
        }

        float o0 = 0.f, o1 = 0.f;
        if (__ballot_sync(FULLM, cnt > 3)) {
            // slow fallback (rare): original per-slot ballot loop
            #pragma unroll
            for (int t = 0; t < 16; t++) {
                unsigned mask = __ballot_sync(FULLM, w[t] > 0.f);
                while (mask) {
                    const int bit = __ffs(mask) - 1;
                    mask &= mask - 1;
                    const float wj = __shfl_sync(FULLM, w[t], bit);
                    const float* vr = V + base + (size_t)(t * 32 + bit) * Dc;
                    o0 = fmaf(wj, vr[lane],      o0);
                    o1 = fmaf(wj, vr[lane + 32], o1);
                }
            }
        } else {
            unsigned m0 = __ballot_sync(FULLM, jj0 >= 0);
            unsigned m1 = __ballot_sync(FULLM, jj1 >= 0);
            unsigned m2 = __ballot_sync(FULLM, jj2 >= 0);
            while (m0) {
                const int bit = __ffs(m0) - 1; m0 &= m0 - 1;
                const float wj = __shfl_sync(FULLM, wv0, bit);
                const int   j  = __shfl_sync(FULLM, jj0, bit);
                const float* vr = V + base + (size_t)j * Dc;
                o0 = fmaf(wj, vr[lane],      o0);
                o1 = fmaf(wj, vr[lane + 32], o1);
            }
            while (m1) {
                const int bit = __ffs(m1) - 1; m1 &= m1 - 1;
                const float wj = __shfl_sync(FULLM, wv1, bit);
                const int   j  = __shfl_sync(FULLM, jj1, bit);
                const float* vr = V + base + (size_t)j * Dc;
                o0 = fmaf(wj, vr[lane],      o0);
                o1 = fmaf(wj, vr[lane + 32], o1);
            }
            while (m2) {
                const int bit = __ffs(m2) - 1; m2 &= m2 - 1;
                const float wj = __shfl_sync(FULLM, wv2, bit);
                const int   j  = __shfl_sync(FULLM, jj2, bit);
                const float* vr = V + base + (size_t)j * Dc;
                o0 = fmaf(wj, vr[lane],      o0);
                o1 = fmaf(wj, vr[lane + 32], o1);
            }
        }
        out[lane]      = o0 * scale;
        out[lane + 32] = o1 * scale;
    }
}

// ---------------- fused residual + LayerNorm: O = LN(X + R) * g + b ----------------
__global__ void ln_kernel(const float* __restrict__ X, const float* __restrict__ R,
                          const float* __restrict__ g, const float* __restrict__ bt,
                          float* __restrict__ O)
{
    const int row = blockIdx.x;
    const int tid = threadIdx.x;   // 128
    __shared__ float s_red[128];

    const float* xr = X + (size_t)row * Dc;
    const float* rr = R + (size_t)row * Dc;

    float v[4];
    float sum = 0.f, sq = 0.f;
    #pragma unroll
    for (int k = 0; k < 4; k++) {
        float t = xr[tid + k * 128] + rr[tid + k * 128];
        v[k] = t; sum += t; sq += t * t;
    }
    s_red[tid] = sum; __syncthreads();
    for (int s = 64; s > 0; s >>= 1) { if (tid < s) s_red[tid] += s_red[tid + s]; __syncthreads(); }
    float mean = s_red[0] * (1.f / Dc); __syncthreads();
    s_red[tid] = sq; __syncthreads();
    for (int s = 64; s > 0; s >>= 1) { if (tid < s) s_red[tid] += s_red[tid + s]; __syncthreads(); }
    float var = s_red[0] * (1.f / Dc) - mean * mean;
    float rs = rsqrtf(var + 1e-5f);

    #pragma unroll
    for (int k = 0; k < 4; k++) {
        int c = tid + k * 128;
        O[(size_t)row * Dc + c] = (v[k] - mean) * rs * g[c] + bt[c];
    }
}

// ---------------- launch ----------------
extern "C" void kernel_launch(void* const* d_in, const int* in_sizes, int n_in,
                              void* d_out, int out_size)
{
    const float* qe   = (const float*)d_in[0];
    const float* ie   = (const float*)d_in[1];
    const float* pe   = (const float*)d_in[2];
    const float* Wk   = (const float*)d_in[3];
    const float* bk   = (const float*)d_in[4];
    const float* Wv   = (const float*)d_in[5];
    const float* bv   = (const float*)d_in[6];
    const float* Wo   = (const float*)d_in[7];
    const float* bo   = (const float*)d_in[8];
    const float* ln1g = (const float*)d_in[9];
    const float* ln1b = (const float*)d_in[10];
    const float* W1   = (const float*)d_in[11];
    const float* b1   = (const float*)d_in[12];
    const float* W2   = (const float*)d_in[13];
    const float* b2   = (const float*)d_in[14];
    const float* ln2g = (const float*)d_in[15];
    const float* ln2b = (const float*)d_in[16];
    float* out = (float*)d_out;

    float *x, *y, *q, *v, *attn, *h1, *t2;
    cudaGetSymbolAddress((void**)&x,    g_x);
    cudaGetSymbolAddress((void**)&y,    g_y);
    cudaGetSymbolAddress((void**)&q,    g_q);
    cudaGetSymbolAddress((void**)&v,    g_v);
    cudaGetSymbolAddress((void**)&attn, g_attn);
    cudaGetSymbolAddress((void**)&h1,   g_h1);
    cudaGetSymbolAddress((void**)&t2,   g_t2);

    addpos_kernel<<<((size_t)BSc * Dc + 255) / 256, 256>>>(qe, ie, pe, x, y);

    for (int l = 0; l < Lc; l++) {
        const float* Wkl = Wk + (size_t)l * Dc * Dc;
        const float* Wvl = Wv + (size_t)l * Dc * Dc;
        const float* Wol = Wo + (size_t)l * Dc * Dc;
        const float* W1l = W1 + (size_t)l * Dc * DFFc;
        const float* W2l = W2 + (size_t)l * DFFc * Dc;

        // fused Wk || Wv (independent) in one launch for better wave packing
        bgemm_dual_kernel<<<dim3(Dc / BN, BSc / BM, 2), 256>>>(
            x, Wkl, bk + l * Dc, q,
            y, Wvl, bv + l * Dc, v, Dc, Dc);
        attn_kernel<<<dim3(Sc / QPB, Hc, Bc), 256>>>(q, v, attn);
        bgemm_kernel<<<dim3(Dc / BN, BSc / BM), 256>>>(attn, Wol, bo + l * Dc, t2, Dc, Dc, 0);
        ln_kernel<<<BSc, 128>>>(x, t2, ln1g + l * Dc, ln1b + l * Dc, x);
        bgemm_kernel<<<dim3(DFFc / BN, BSc / BM), 256>>>(x, W1l, b1 + l * DFFc, h1, DFFc, Dc, 1);
        bgemm_kernel<<<dim3(Dc / BN, BSc / BM), 256>>>(h1, W2l, b2 + l * Dc, t2, Dc, DFFc, 0);
        float* dst = (l == Lc - 1) ? out : x;
        ln_kernel<<<BSc, 128>>>(x, t2, ln2g + l * Dc, ln2b + l * Dc, dst);
    }
}